// round 3
// baseline (speedup 1.0000x reference)
#include <cuda_runtime.h>
#include <cstdint>

#define NN 100000
#define EE 600000
#define DD 128
#define BN_EPS 1e-5f

// ---------------- scratch (static device globals; no runtime alloc) ----------------
__device__ __align__(16) float    g_hl  [(size_t)NN * DD];   // 51.2 MB
__device__ __align__(16) float    g_agg [(size_t)NN * DD];   // 51.2 MB
__device__ __align__(16) float    g_norm[EE];
__device__ __align__(16) unsigned g_pk  [(size_t)EE * 8];    // 2-bit packed edge_attr
__device__ __align__(16) int      g_row [EE];
__device__ __align__(16) int      g_col [EE];
__device__ __align__(16) float    g_deg [NN];
__device__ __align__(16) float    g_dinv[NN];
__device__ __align__(16) float    g_rdeg[NN];

// ---------------- f32x2 packed-FMA helpers (sm_100+) ----------------
__device__ __forceinline__ unsigned long long pack2(float x, float y) {
    unsigned long long r;
    asm("mov.b64 %0, {%1, %2};" : "=l"(r) : "f"(x), "f"(y));
    return r;
}
__device__ __forceinline__ unsigned long long fma2(unsigned long long a,
                                                   unsigned long long b,
                                                   unsigned long long c) {
    unsigned long long d;
    asm("fma.rn.f32x2 %0, %1, %2, %3;" : "=l"(d) : "l"(a), "l"(b), "l"(c));
    return d;
}
__device__ __forceinline__ float2 unpack2(unsigned long long v) {
    float2 f;
    asm("mov.b64 {%0, %1}, %2;" : "=f"(f.x), "=f"(f.y) : "l"(v));
    return f;
}

// ---------------- prep kernels ----------------
__global__ void k_zero_deg() {
    int i = blockIdx.x * blockDim.x + threadIdx.x;
    if (i < NN) g_deg[i] = 0.0f;
}

// edge_index is int32 (JAX default config downcasts int64). Clamp defensively.
__global__ void k_deg(const int* __restrict__ ei) {
    int e = blockIdx.x * blockDim.x + threadIdx.x;
    if (e < EE) {
        int r = ei[e];
        int c = ei[EE + e];
        r = (r < 0) ? 0 : ((r >= NN) ? NN - 1 : r);
        c = (c < 0) ? 0 : ((c >= NN) ? NN - 1 : c);
        g_row[e] = r;
        g_col[e] = c;
        atomicAdd(&g_deg[r], 1.0f);
    }
}

__global__ void k_fin() {
    int i = blockIdx.x * blockDim.x + threadIdx.x;
    if (i < NN) {
        float d = g_deg[i] + 1.0f;
        g_dinv[i] = rsqrtf(d);
        g_rdeg[i] = 1.0f / d;
    }
}

__global__ void k_norm() {
    int e = blockIdx.x * blockDim.x + threadIdx.x;
    if (e < EE) {
        g_norm[e] = g_dinv[g_row[e]] * g_dinv[g_col[e]];
    }
}

// pack 16 consecutive int32 attr values (each 0..3) into one uint32
__global__ void k_pack(const int* __restrict__ ea) {
    int idx = blockIdx.x * blockDim.x + threadIdx.x;   // word index over EE*8
    if (idx < EE * 8) {
        const int4* p4 = reinterpret_cast<const int4*>(ea + (size_t)idx * 16);
        unsigned w = 0;
        int4 a = p4[0], b = p4[1], c = p4[2], d = p4[3];
        w |= ((unsigned)a.x & 3u) << 0;  w |= ((unsigned)a.y & 3u) << 2;
        w |= ((unsigned)a.z & 3u) << 4;  w |= ((unsigned)a.w & 3u) << 6;
        w |= ((unsigned)b.x & 3u) << 8;  w |= ((unsigned)b.y & 3u) << 10;
        w |= ((unsigned)b.z & 3u) << 12; w |= ((unsigned)b.w & 3u) << 14;
        w |= ((unsigned)c.x & 3u) << 16; w |= ((unsigned)c.y & 3u) << 18;
        w |= ((unsigned)c.z & 3u) << 20; w |= ((unsigned)c.w & 3u) << 22;
        w |= ((unsigned)d.x & 3u) << 24; w |= ((unsigned)d.y & 3u) << 26;
        w |= ((unsigned)d.z & 3u) << 28; w |= ((unsigned)d.w & 3u) << 30;
        g_pk[idx] = w;
    }
}

// ---------------- GEMM: g_hl = A @ W^T + bias  (A [n,128], W [128,128]) ----------------
// block: 256 threads, BM=128 rows, full 128 cols, K chunked by 32.
// smem: sA [128][36] (A tile), sW [128][36] (W rows as-is; dot over k).
// Each thread: 8 rows x 8 cols micro-tile. 36-float pitch -> conflict-free float4.
__global__ __launch_bounds__(256) void k_gemm(const float* __restrict__ A,
                                              const float* __restrict__ W,
                                              const float* __restrict__ bias,
                                              int n) {
    __shared__ __align__(16) float sA[128 * 36];
    __shared__ __align__(16) float sW[128 * 36];

    const int tid = threadIdx.x;
    const int tx = tid & 15;          // col group (8 cols each)
    const int ty = tid >> 4;          // row group (8 rows each)
    const int row0 = blockIdx.x * 128;

    unsigned long long acc2[8][4];
#pragma unroll
    for (int i = 0; i < 8; i++)
#pragma unroll
        for (int j = 0; j < 4; j++) acc2[i][j] = 0ULL;

    for (int kb = 0; kb < 128; kb += 32) {
        // load A tile: 128 rows x 32 floats = 1024 float4, 256 threads x 4
#pragma unroll
        for (int r = 0; r < 4; r++) {
            int idx = r * 256 + tid;
            int arow = idx >> 3;            // 0..127
            int k4 = idx & 7;               // 0..7
            int grow = row0 + arow;
            float4 v = make_float4(0.f, 0.f, 0.f, 0.f);
            if (grow < n)
                v = *reinterpret_cast<const float4*>(&A[(size_t)grow * 128 + kb + k4 * 4]);
            *reinterpret_cast<float4*>(&sA[arow * 36 + k4 * 4]) = v;
        }
        // load W tile: sW[j][k] = W[j][kb+k], j=0..127, k=0..31
#pragma unroll
        for (int r = 0; r < 4; r++) {
            int idx = r * 256 + tid;
            int j = idx >> 3;               // 0..127
            int k4 = idx & 7;               // 0..7
            float4 v = *reinterpret_cast<const float4*>(&W[(size_t)j * 128 + kb + k4 * 4]);
            *reinterpret_cast<float4*>(&sW[j * 36 + k4 * 4]) = v;
        }
        __syncthreads();

#pragma unroll 8
        for (int kk = 0; kk < 32; kk++) {
            float w0 = sW[(tx * 8 + 0) * 36 + kk];
            float w1 = sW[(tx * 8 + 1) * 36 + kk];
            float w2 = sW[(tx * 8 + 2) * 36 + kk];
            float w3 = sW[(tx * 8 + 3) * 36 + kk];
            float w4 = sW[(tx * 8 + 4) * 36 + kk];
            float w5 = sW[(tx * 8 + 5) * 36 + kk];
            float w6 = sW[(tx * 8 + 6) * 36 + kk];
            float w7 = sW[(tx * 8 + 7) * 36 + kk];
            unsigned long long wp[4];
            wp[0] = pack2(w0, w1);
            wp[1] = pack2(w2, w3);
            wp[2] = pack2(w4, w5);
            wp[3] = pack2(w6, w7);
#pragma unroll
            for (int i = 0; i < 8; i++) {
                float a = sA[(ty * 8 + i) * 36 + kk];
                unsigned long long a2 = pack2(a, a);
#pragma unroll
                for (int j = 0; j < 4; j++) acc2[i][j] = fma2(a2, wp[j], acc2[i][j]);
            }
        }
        __syncthreads();
    }

    // epilogue: + bias, store
    float bb[8];
#pragma unroll
    for (int q = 0; q < 8; q++) bb[q] = bias[tx * 8 + q];
#pragma unroll
    for (int i = 0; i < 8; i++) {
        int grow = row0 + ty * 8 + i;
        if (grow < n) {
            float2 f0 = unpack2(acc2[i][0]);
            float2 f1 = unpack2(acc2[i][1]);
            float2 f2 = unpack2(acc2[i][2]);
            float2 f3 = unpack2(acc2[i][3]);
            float4 o0 = make_float4(f0.x + bb[0], f0.y + bb[1], f1.x + bb[2], f1.y + bb[3]);
            float4 o1 = make_float4(f2.x + bb[4], f2.y + bb[5], f3.x + bb[6], f3.y + bb[7]);
            *reinterpret_cast<float4*>(&g_hl[(size_t)grow * 128 + tx * 8])     = o0;
            *reinterpret_cast<float4*>(&g_hl[(size_t)grow * 128 + tx * 8 + 4]) = o1;
        }
    }
}

// ---------------- pre: agg = relu(hl + root) / deg  (replaces memset of agg) ----------------
__global__ void k_pre(const float* __restrict__ rootl) {
    int idx = blockIdx.x * blockDim.x + threadIdx.x;   // over NN*32
    if (idx >= NN * 32) return;
    int i = idx >> 5;
    int c4 = (idx & 31) * 4;
    float rd = g_rdeg[i];
    float4 h4 = *reinterpret_cast<const float4*>(&g_hl[(size_t)i * 128 + c4]);
    float4 r4 = *reinterpret_cast<const float4*>(&rootl[c4]);
    float4 o;
    o.x = fmaxf(h4.x + r4.x, 0.f) * rd;
    o.y = fmaxf(h4.y + r4.y, 0.f) * rd;
    o.z = fmaxf(h4.z + r4.z, 0.f) * rd;
    o.w = fmaxf(h4.w + r4.w, 0.f) * rd;
    *reinterpret_cast<float4*>(&g_agg[(size_t)i * 128 + c4]) = o;
}

// ---------------- edge: one warp per edge, v4 reduction into agg ----------------
__global__ void k_edge() {
    int lane = threadIdx.x & 31;
    int e = (blockIdx.x * blockDim.x + threadIdx.x) >> 5;
    if (e >= EE) return;
    int r = g_row[e];
    int c = g_col[e];
    float nm = g_norm[e];
    unsigned w = g_pk[(size_t)e * 8 + (lane >> 2)];
    unsigned byte = (w >> ((lane & 3) * 8)) & 0xFFu;
    float4 h4 = *reinterpret_cast<const float4*>(&g_hl[(size_t)r * 128 + lane * 4]);
    float mx = fmaxf(h4.x + (float)(byte & 3u), 0.f) * nm;
    float my = fmaxf(h4.y + (float)((byte >> 2) & 3u), 0.f) * nm;
    float mz = fmaxf(h4.z + (float)((byte >> 4) & 3u), 0.f) * nm;
    float mw = fmaxf(h4.w + (float)((byte >> 6) & 3u), 0.f) * nm;
    float* p = &g_agg[(size_t)c * 128 + lane * 4];
    asm volatile("red.global.add.v4.f32 [%0], {%1, %2, %3, %4};"
                 :: "l"(p), "f"(mx), "f"(my), "f"(mz), "f"(mw)
                 : "memory");
}

// ---------------- post: BN (eval) + optional relu ----------------
__global__ void k_post(const float* __restrict__ gammal, const float* __restrict__ betal,
                       const float* __restrict__ meanl, const float* __restrict__ varl,
                       float* __restrict__ out, int do_relu) {
    int idx = blockIdx.x * blockDim.x + threadIdx.x;   // over NN*32
    if (idx >= NN * 32) return;
    int i = idx >> 5;
    int c4 = (idx & 31) * 4;
    float4 a4 = *reinterpret_cast<const float4*>(&g_agg[(size_t)i * 128 + c4]);
    float4 g4 = *reinterpret_cast<const float4*>(&gammal[c4]);
    float4 b4 = *reinterpret_cast<const float4*>(&betal[c4]);
    float4 m4 = *reinterpret_cast<const float4*>(&meanl[c4]);
    float4 v4 = *reinterpret_cast<const float4*>(&varl[c4]);
    float sx = g4.x * rsqrtf(v4.x + BN_EPS);
    float sy = g4.y * rsqrtf(v4.y + BN_EPS);
    float sz = g4.z * rsqrtf(v4.z + BN_EPS);
    float sw = g4.w * rsqrtf(v4.w + BN_EPS);
    float4 o;
    o.x = a4.x * sx + (b4.x - m4.x * sx);
    o.y = a4.y * sy + (b4.y - m4.y * sy);
    o.z = a4.z * sz + (b4.z - m4.z * sz);
    o.w = a4.w * sw + (b4.w - m4.w * sw);
    if (do_relu) {
        o.x = fmaxf(o.x, 0.f);
        o.y = fmaxf(o.y, 0.f);
        o.z = fmaxf(o.z, 0.f);
        o.w = fmaxf(o.w, 0.f);
    }
    *reinterpret_cast<float4*>(&out[(size_t)i * 128 + c4]) = o;
}

// ---------------- launcher ----------------
extern "C" void kernel_launch(void* const* d_in, const int* in_sizes, int n_in,
                              void* d_out, int out_size) {
    (void)in_sizes; (void)n_in; (void)out_size;
    const float* x    = (const float*)d_in[0];
    const int*   ei   = (const int*)d_in[1];     // int32 (JAX default, not x64)
    const int*   ea   = (const int*)d_in[2];
    const float* W    = (const float*)d_in[3];
    const float* b    = (const float*)d_in[4];
    const float* root = (const float*)d_in[5];
    const float* gam  = (const float*)d_in[6];
    const float* bet  = (const float*)d_in[7];
    const float* mean = (const float*)d_in[8];
    const float* var  = (const float*)d_in[9];
    float* out = (float*)d_out;

    // ---- prep (every replay; deterministic) ----
    k_zero_deg<<<(NN + 255) / 256, 256>>>();
    k_deg<<<(EE + 255) / 256, 256>>>(ei);
    k_fin<<<(NN + 255) / 256, 256>>>();
    k_norm<<<(EE + 255) / 256, 256>>>();
    k_pack<<<(EE * 8 + 255) / 256, 256>>>(ea);

    const int gemm_blocks = (NN + 127) / 128;
    const int node_blocks = (NN * 32 + 255) / 256;
    const int edge_blocks = (EE * 32 + 255) / 256;

    const float* hin = x;
    for (int l = 0; l < 5; l++) {
        k_gemm<<<gemm_blocks, 256>>>(
            hin, W + (size_t)l * 128 * 128, b + (size_t)l * 128, NN);
        k_pre<<<node_blocks, 256>>>(root + (size_t)l * 128);
        k_edge<<<edge_blocks, 256>>>();
        k_post<<<node_blocks, 256>>>(gam + (size_t)l * 128, bet + (size_t)l * 128,
                                     mean + (size_t)l * 128, var + (size_t)l * 128,
                                     out, (l < 4) ? 1 : 0);
        hin = out;
    }
}

// round 4
// speedup vs baseline: 1.0853x; 1.0853x over previous
#include <cuda_runtime.h>
#include <cstdint>

#define NN 100000
#define EE 600000
#define DD 128
#define BN_EPS 1e-5f

// ---------------- scratch (static device globals; no runtime alloc) ----------------
__device__ __align__(16) float    g_hl  [(size_t)NN * DD];   // 51.2 MB
__device__ __align__(16) unsigned g_pk  [(size_t)EE * 8];    // 2-bit packed edge_attr
__device__ __align__(16) int      g_row [EE];
__device__ __align__(16) int      g_col [EE];
__device__ __align__(16) float    g_deg [NN];
__device__ __align__(16) float    g_dinv[NN];
__device__ __align__(16) float    g_rdeg[NN];
// CSR by target (col)
__device__ __align__(16) int      g_cnt   [NN];
__device__ __align__(16) int      g_cursor[NN];
__device__ __align__(16) int      g_start [NN + 1];
__device__ __align__(16) int      g_csr_row [EE];
__device__ __align__(16) int      g_csr_eid [EE];
__device__ __align__(16) float    g_csr_norm[EE];

// ---------------- f32x2 packed-FMA helpers (sm_100+) ----------------
__device__ __forceinline__ unsigned long long pack2(float x, float y) {
    unsigned long long r;
    asm("mov.b64 %0, {%1, %2};" : "=l"(r) : "f"(x), "f"(y));
    return r;
}
__device__ __forceinline__ unsigned long long fma2(unsigned long long a,
                                                   unsigned long long b,
                                                   unsigned long long c) {
    unsigned long long d;
    asm("fma.rn.f32x2 %0, %1, %2, %3;" : "=l"(d) : "l"(a), "l"(b), "l"(c));
    return d;
}
__device__ __forceinline__ float2 unpack2(unsigned long long v) {
    float2 f;
    asm("mov.b64 {%0, %1}, %2;" : "=f"(f.x), "=f"(f.y) : "l"(v));
    return f;
}

// ---------------- prep kernels ----------------
__global__ void k_zero() {
    int i = blockIdx.x * blockDim.x + threadIdx.x;
    if (i < NN) {
        g_deg[i] = 0.0f;
        g_cnt[i] = 0;
        g_cursor[i] = 0;
    }
}

// edge_index is int32 (JAX default config). Clamp defensively.
__global__ void k_deg(const int* __restrict__ ei) {
    int e = blockIdx.x * blockDim.x + threadIdx.x;
    if (e < EE) {
        int r = ei[e];
        int c = ei[EE + e];
        r = (r < 0) ? 0 : ((r >= NN) ? NN - 1 : r);
        c = (c < 0) ? 0 : ((c >= NN) ? NN - 1 : c);
        g_row[e] = r;
        g_col[e] = c;
        atomicAdd(&g_deg[r], 1.0f);        // out-degree (reference's deg)
        atomicAdd(&g_cnt[c], 1);           // in-degree for CSR
    }
}

__global__ void k_fin() {
    int i = blockIdx.x * blockDim.x + threadIdx.x;
    if (i < NN) {
        float d = g_deg[i] + 1.0f;
        g_dinv[i] = rsqrtf(d);
        g_rdeg[i] = 1.0f / d;
    }
}

// single-block exclusive scan of g_cnt -> g_start (NN+1 entries)
__global__ __launch_bounds__(1024) void k_scan() {
    __shared__ int s[1024];
    const int t = threadIdx.x;
    const int CH = (NN + 1023) / 1024;      // 98
    const int base = t * CH;
    const int lim = (base + CH < NN) ? base + CH : NN;
    int local = 0;
    for (int i = base; i < lim; i++) local += g_cnt[i];
    s[t] = local;
    __syncthreads();
    // Hillis-Steele inclusive scan
    for (int d = 1; d < 1024; d <<= 1) {
        int v = (t >= d) ? s[t - d] : 0;
        __syncthreads();
        s[t] += v;
        __syncthreads();
    }
    int off = s[t] - local;                 // exclusive prefix for this chunk
    for (int i = base; i < lim; i++) {
        g_start[i] = off;
        off += g_cnt[i];
    }
    if (t == 1023) g_start[NN] = s[1023];
}

// scatter edges into CSR-by-col; precompute per-edge norm
__global__ void k_scatter() {
    int e = blockIdx.x * blockDim.x + threadIdx.x;
    if (e < EE) {
        int r = g_row[e];
        int c = g_col[e];
        int pos = atomicAdd(&g_cursor[c], 1);
        int idx = g_start[c] + pos;
        g_csr_row[idx] = r;
        g_csr_eid[idx] = e;
        g_csr_norm[idx] = g_dinv[r] * g_dinv[c];
    }
}

// pack 16 consecutive int32 attr values (each 0..3) into one uint32
__global__ void k_pack(const int* __restrict__ ea) {
    int idx = blockIdx.x * blockDim.x + threadIdx.x;   // word index over EE*8
    if (idx < EE * 8) {
        const int4* p4 = reinterpret_cast<const int4*>(ea + (size_t)idx * 16);
        unsigned w = 0;
        int4 a = p4[0], b = p4[1], c = p4[2], d = p4[3];
        w |= ((unsigned)a.x & 3u) << 0;  w |= ((unsigned)a.y & 3u) << 2;
        w |= ((unsigned)a.z & 3u) << 4;  w |= ((unsigned)a.w & 3u) << 6;
        w |= ((unsigned)b.x & 3u) << 8;  w |= ((unsigned)b.y & 3u) << 10;
        w |= ((unsigned)b.z & 3u) << 12; w |= ((unsigned)b.w & 3u) << 14;
        w |= ((unsigned)c.x & 3u) << 16; w |= ((unsigned)c.y & 3u) << 18;
        w |= ((unsigned)c.z & 3u) << 20; w |= ((unsigned)c.w & 3u) << 22;
        w |= ((unsigned)d.x & 3u) << 24; w |= ((unsigned)d.y & 3u) << 26;
        w |= ((unsigned)d.z & 3u) << 28; w |= ((unsigned)d.w & 3u) << 30;
        g_pk[idx] = w;
    }
}

// ---------------- GEMM: g_hl = A @ W^T + bias  (A [n,128], W [128,128]) ----------------
__global__ __launch_bounds__(256) void k_gemm(const float* __restrict__ A,
                                              const float* __restrict__ W,
                                              const float* __restrict__ bias,
                                              int n) {
    __shared__ __align__(16) float sA[128 * 36];
    __shared__ __align__(16) float sW[128 * 36];

    const int tid = threadIdx.x;
    const int tx = tid & 15;          // col group (8 cols each)
    const int ty = tid >> 4;          // row group (8 rows each)
    const int row0 = blockIdx.x * 128;

    unsigned long long acc2[8][4];
#pragma unroll
    for (int i = 0; i < 8; i++)
#pragma unroll
        for (int j = 0; j < 4; j++) acc2[i][j] = 0ULL;

    for (int kb = 0; kb < 128; kb += 32) {
#pragma unroll
        for (int r = 0; r < 4; r++) {
            int idx = r * 256 + tid;
            int arow = idx >> 3;
            int k4 = idx & 7;
            int grow = row0 + arow;
            float4 v = make_float4(0.f, 0.f, 0.f, 0.f);
            if (grow < n)
                v = *reinterpret_cast<const float4*>(&A[(size_t)grow * 128 + kb + k4 * 4]);
            *reinterpret_cast<float4*>(&sA[arow * 36 + k4 * 4]) = v;
        }
#pragma unroll
        for (int r = 0; r < 4; r++) {
            int idx = r * 256 + tid;
            int j = idx >> 3;
            int k4 = idx & 7;
            float4 v = *reinterpret_cast<const float4*>(&W[(size_t)j * 128 + kb + k4 * 4]);
            *reinterpret_cast<float4*>(&sW[j * 36 + k4 * 4]) = v;
        }
        __syncthreads();

#pragma unroll 8
        for (int kk = 0; kk < 32; kk++) {
            float w0 = sW[(tx * 8 + 0) * 36 + kk];
            float w1 = sW[(tx * 8 + 1) * 36 + kk];
            float w2 = sW[(tx * 8 + 2) * 36 + kk];
            float w3 = sW[(tx * 8 + 3) * 36 + kk];
            float w4 = sW[(tx * 8 + 4) * 36 + kk];
            float w5 = sW[(tx * 8 + 5) * 36 + kk];
            float w6 = sW[(tx * 8 + 6) * 36 + kk];
            float w7 = sW[(tx * 8 + 7) * 36 + kk];
            unsigned long long wp[4];
            wp[0] = pack2(w0, w1);
            wp[1] = pack2(w2, w3);
            wp[2] = pack2(w4, w5);
            wp[3] = pack2(w6, w7);
#pragma unroll
            for (int i = 0; i < 8; i++) {
                float a = sA[(ty * 8 + i) * 36 + kk];
                unsigned long long a2 = pack2(a, a);
#pragma unroll
                for (int j = 0; j < 4; j++) acc2[i][j] = fma2(a2, wp[j], acc2[i][j]);
            }
        }
        __syncthreads();
    }

    float bb[8];
#pragma unroll
    for (int q = 0; q < 8; q++) bb[q] = bias[tx * 8 + q];
#pragma unroll
    for (int i = 0; i < 8; i++) {
        int grow = row0 + ty * 8 + i;
        if (grow < n) {
            float2 f0 = unpack2(acc2[i][0]);
            float2 f1 = unpack2(acc2[i][1]);
            float2 f2 = unpack2(acc2[i][2]);
            float2 f3 = unpack2(acc2[i][3]);
            float4 o0 = make_float4(f0.x + bb[0], f0.y + bb[1], f1.x + bb[2], f1.y + bb[3]);
            float4 o1 = make_float4(f2.x + bb[4], f2.y + bb[5], f3.x + bb[6], f3.y + bb[7]);
            *reinterpret_cast<float4*>(&g_hl[(size_t)grow * 128 + tx * 8])     = o0;
            *reinterpret_cast<float4*>(&g_hl[(size_t)grow * 128 + tx * 8 + 4]) = o1;
        }
    }
}

// ---------------- fused per-node layer kernel ----------------
// warp-per-node: acc = relu(hl[i]+root)/deg  +  sum_{incoming e} norm_e * relu(hl[row_e]+attr_e)
// then BN (+optional relu), write out. No atomics, no agg buffer.
__global__ __launch_bounds__(256) void k_layer(const float* __restrict__ rootl,
                                               const float* __restrict__ gammal,
                                               const float* __restrict__ betal,
                                               const float* __restrict__ meanl,
                                               const float* __restrict__ varl,
                                               float* __restrict__ out, int do_relu) {
    const int warp = (blockIdx.x * blockDim.x + threadIdx.x) >> 5;
    const int lane = threadIdx.x & 31;
    if (warp >= NN) return;
    const int i = warp;
    const int c4 = lane * 4;

    float4 h4 = *reinterpret_cast<const float4*>(&g_hl[(size_t)i * 128 + c4]);
    float4 r4 = *reinterpret_cast<const float4*>(&rootl[c4]);
    const float rd = g_rdeg[i];
    float ax = fmaxf(h4.x + r4.x, 0.f) * rd;
    float ay = fmaxf(h4.y + r4.y, 0.f) * rd;
    float az = fmaxf(h4.z + r4.z, 0.f) * rd;
    float aw = fmaxf(h4.w + r4.w, 0.f) * rd;

    const int s = g_start[i];
    const int e_end = g_start[i + 1];
    const unsigned sh = (lane & 3) * 8;
    for (int p = s; p < e_end; p++) {
        int r = g_csr_row[p];
        float nm = g_csr_norm[p];
        int eid = g_csr_eid[p];
        unsigned w = g_pk[(size_t)eid * 8 + (lane >> 2)];
        unsigned byte = (w >> sh) & 0xFFu;
        float4 hv = *reinterpret_cast<const float4*>(&g_hl[(size_t)r * 128 + c4]);
        ax += fmaxf(hv.x + (float)(byte & 3u), 0.f) * nm;
        ay += fmaxf(hv.y + (float)((byte >> 2) & 3u), 0.f) * nm;
        az += fmaxf(hv.z + (float)((byte >> 4) & 3u), 0.f) * nm;
        aw += fmaxf(hv.w + (float)((byte >> 6) & 3u), 0.f) * nm;
    }

    // BN (eval) + optional relu
    float4 g4 = *reinterpret_cast<const float4*>(&gammal[c4]);
    float4 b4 = *reinterpret_cast<const float4*>(&betal[c4]);
    float4 m4 = *reinterpret_cast<const float4*>(&meanl[c4]);
    float4 v4 = *reinterpret_cast<const float4*>(&varl[c4]);
    float sx = g4.x * rsqrtf(v4.x + BN_EPS);
    float sy = g4.y * rsqrtf(v4.y + BN_EPS);
    float sz = g4.z * rsqrtf(v4.z + BN_EPS);
    float sw = g4.w * rsqrtf(v4.w + BN_EPS);
    float4 o;
    o.x = ax * sx + (b4.x - m4.x * sx);
    o.y = ay * sy + (b4.y - m4.y * sy);
    o.z = az * sz + (b4.z - m4.z * sz);
    o.w = aw * sw + (b4.w - m4.w * sw);
    if (do_relu) {
        o.x = fmaxf(o.x, 0.f);
        o.y = fmaxf(o.y, 0.f);
        o.z = fmaxf(o.z, 0.f);
        o.w = fmaxf(o.w, 0.f);
    }
    *reinterpret_cast<float4*>(&out[(size_t)i * 128 + c4]) = o;
}

// ---------------- launcher ----------------
extern "C" void kernel_launch(void* const* d_in, const int* in_sizes, int n_in,
                              void* d_out, int out_size) {
    (void)in_sizes; (void)n_in; (void)out_size;
    const float* x    = (const float*)d_in[0];
    const int*   ei   = (const int*)d_in[1];     // int32 (JAX default, not x64)
    const int*   ea   = (const int*)d_in[2];
    const float* W    = (const float*)d_in[3];
    const float* b    = (const float*)d_in[4];
    const float* root = (const float*)d_in[5];
    const float* gam  = (const float*)d_in[6];
    const float* bet  = (const float*)d_in[7];
    const float* mean = (const float*)d_in[8];
    const float* var  = (const float*)d_in[9];
    float* out = (float*)d_out;

    // ---- prep (every replay; deterministic work) ----
    k_zero<<<(NN + 255) / 256, 256>>>();
    k_deg<<<(EE + 255) / 256, 256>>>(ei);
    k_fin<<<(NN + 255) / 256, 256>>>();
    k_scan<<<1, 1024>>>();
    k_scatter<<<(EE + 255) / 256, 256>>>();
    k_pack<<<(EE * 8 + 255) / 256, 256>>>(ea);

    const int gemm_blocks = (NN + 127) / 128;
    const int layer_blocks = (NN * 32 + 255) / 256;

    const float* hin = x;
    for (int l = 0; l < 5; l++) {
        k_gemm<<<gemm_blocks, 256>>>(
            hin, W + (size_t)l * 128 * 128, b + (size_t)l * 128, NN);
        k_layer<<<layer_blocks, 256>>>(root + (size_t)l * 128,
                                       gam + (size_t)l * 128, bet + (size_t)l * 128,
                                       mean + (size_t)l * 128, var + (size_t)l * 128,
                                       out, (l < 4) ? 1 : 0);
        hin = out;
    }
}

// round 6
// speedup vs baseline: 2.4446x; 2.2525x over previous
#include <cuda_runtime.h>
#include <cstdint>

#define NN 100000
#define EE 600000
#define DD 128
#define BN_EPS 1e-5f
#define NB_SCAN 100          // scan blocks, 1000 elems each

// ---------------- scratch (static device globals; no runtime alloc) ----------------
__device__ __align__(16) float    g_hl  [(size_t)NN * DD];   // 51.2 MB
__device__ __align__(16) unsigned g_pk  [(size_t)EE * 8];    // edge-order packed attrs
__device__ __align__(16) unsigned g_pk_csr[(size_t)EE * 8];  // CSR-order packed attrs
__device__ __align__(16) int      g_row [EE];
__device__ __align__(16) int      g_col [EE];
__device__ __align__(16) float    g_deg [NN];
__device__ __align__(16) float    g_dinv[NN];
__device__ __align__(16) float    g_rdeg[NN];
// CSR by target (col)
__device__ __align__(16) int      g_cnt   [NN];
__device__ __align__(16) int      g_cursor[NN];
__device__ __align__(16) int      g_start [NN + 1];
__device__ __align__(16) int2     g_csr_rn[EE];              // {row, norm bits}
__device__ __align__(16) int      g_bsum[NB_SCAN];
__device__ __align__(16) int      g_boff[NB_SCAN];

// ---------------- tf32 helpers ----------------
__device__ __forceinline__ unsigned f2tf32(float a) {
    unsigned r;
    asm("cvt.rna.tf32.f32 %0, %1;" : "=r"(r) : "f"(a));
    return r;
}
__device__ __forceinline__ void mma_tf32(float* c, const unsigned* a, const unsigned* b) {
    asm volatile(
        "mma.sync.aligned.m16n8k8.row.col.f32.tf32.tf32.f32 "
        "{%0,%1,%2,%3}, {%4,%5,%6,%7}, {%8,%9}, {%0,%1,%2,%3};"
        : "+f"(c[0]), "+f"(c[1]), "+f"(c[2]), "+f"(c[3])
        : "r"(a[0]), "r"(a[1]), "r"(a[2]), "r"(a[3]), "r"(b[0]), "r"(b[1]));
}

// ---------------- prep kernels ----------------
__global__ void k_zero() {
    int i = blockIdx.x * blockDim.x + threadIdx.x;
    if (i < NN) {
        g_deg[i] = 0.0f;
        g_cnt[i] = 0;
        g_cursor[i] = 0;
    }
}

// edge_index is int32 (JAX default config). Clamp defensively.
__global__ void k_deg(const int* __restrict__ ei) {
    int e = blockIdx.x * blockDim.x + threadIdx.x;
    if (e < EE) {
        int r = ei[e];
        int c = ei[EE + e];
        r = (r < 0) ? 0 : ((r >= NN) ? NN - 1 : r);
        c = (c < 0) ? 0 : ((c >= NN) ? NN - 1 : c);
        g_row[e] = r;
        g_col[e] = c;
        atomicAdd(&g_deg[r], 1.0f);        // out-degree (reference's deg)
        atomicAdd(&g_cnt[c], 1);           // in-degree for CSR
    }
}

// scan pass A: per-chunk block sums of g_cnt; also finish deg -> dinv/rdeg
__global__ __launch_bounds__(1024) void k_scanA() {
    __shared__ int red[1024];
    const int b = blockIdx.x, t = threadIdx.x;
    const int i = b * 1000 + t;
    int v = 0;
    if (t < 1000 && i < NN) {
        v = g_cnt[i];
        float d = g_deg[i] + 1.0f;
        g_dinv[i] = rsqrtf(d);
        g_rdeg[i] = 1.0f / d;
    }
    red[t] = v;
    __syncthreads();
    for (int s = 512; s > 0; s >>= 1) {
        if (t < s) red[t] += red[t + s];
        __syncthreads();
    }
    if (t == 0) g_bsum[b] = red[0];
}

// scan pass B: exclusive scan of the 100 block sums
__global__ void k_scanB() {
    __shared__ int s[128];
    const int t = threadIdx.x;
    int v = (t < NB_SCAN) ? g_bsum[t] : 0;
    s[t] = v;
    __syncthreads();
    for (int d = 1; d < 128; d <<= 1) {
        int add = (t >= d) ? s[t - d] : 0;
        __syncthreads();
        s[t] += add;
        __syncthreads();
    }
    if (t < NB_SCAN) g_boff[t] = s[t] - v;
    if (t == 0) g_start[NN] = EE;
}

// scan pass C: per-chunk exclusive scan + block offset -> g_start
__global__ __launch_bounds__(1024) void k_scanC() {
    __shared__ int s[2][1024];
    const int b = blockIdx.x, t = threadIdx.x;
    const int i = b * 1000 + t;
    const int v = (t < 1000 && i < NN) ? g_cnt[i] : 0;
    int cur = 0;
    s[0][t] = v;
    __syncthreads();
    for (int d = 1; d < 1024; d <<= 1) {
        int nxt = cur ^ 1;
        s[nxt][t] = s[cur][t] + ((t >= d) ? s[cur][t - d] : 0);
        __syncthreads();
        cur = nxt;
    }
    if (t < 1000 && i < NN) g_start[i] = g_boff[b] + s[cur][t] - v;
}

// pack 16 consecutive int32 attr values (each 0..3) into one uint32
__global__ void k_pack(const int* __restrict__ ea) {
    int idx = blockIdx.x * blockDim.x + threadIdx.x;   // word index over EE*8
    if (idx < EE * 8) {
        const int4* p4 = reinterpret_cast<const int4*>(ea + (size_t)idx * 16);
        unsigned w = 0;
        int4 a = p4[0], b = p4[1], c = p4[2], d = p4[3];
        w |= ((unsigned)a.x & 3u) << 0;  w |= ((unsigned)a.y & 3u) << 2;
        w |= ((unsigned)a.z & 3u) << 4;  w |= ((unsigned)a.w & 3u) << 6;
        w |= ((unsigned)b.x & 3u) << 8;  w |= ((unsigned)b.y & 3u) << 10;
        w |= ((unsigned)b.z & 3u) << 12; w |= ((unsigned)b.w & 3u) << 14;
        w |= ((unsigned)c.x & 3u) << 16; w |= ((unsigned)c.y & 3u) << 18;
        w |= ((unsigned)c.z & 3u) << 20; w |= ((unsigned)c.w & 3u) << 22;
        w |= ((unsigned)d.x & 3u) << 24; w |= ((unsigned)d.y & 3u) << 26;
        w |= ((unsigned)d.z & 3u) << 28; w |= ((unsigned)d.w & 3u) << 30;
        g_pk[idx] = w;
    }
}

// scatter edges into CSR-by-col: packed (row, norm) + pk words in CSR order
__global__ void k_scatter() {
    int e = blockIdx.x * blockDim.x + threadIdx.x;
    if (e < EE) {
        int r = g_row[e];
        int c = g_col[e];
        int pos = atomicAdd(&g_cursor[c], 1);
        int idx = g_start[c] + pos;
        int2 rn;
        rn.x = r;
        rn.y = __float_as_int(g_dinv[r] * g_dinv[c]);
        g_csr_rn[idx] = rn;
        const uint4* src = reinterpret_cast<const uint4*>(&g_pk[(size_t)e * 8]);
        uint4* dst = reinterpret_cast<uint4*>(&g_pk_csr[(size_t)idx * 8]);
        dst[0] = src[0];
        dst[1] = src[1];
    }
}

// ---------------- GEMM (tf32 tensor core, 3-term split): g_hl = A @ W^T + bias ----------
// block 256 thr (8 warps), tile 128x128, K-chunk 32. warp tile 32x64.
// smem fp32: sA[128][36] (rows), sW[128][36] (sW[j][k] = W[j][kb+k], j = output col).
// y = Ahi*Whi + Ahi*Wlo + Alo*Whi  (error ~2^-22 rel)
__global__ __launch_bounds__(256) void k_gemm(const float* __restrict__ A,
                                              const float* __restrict__ W,
                                              const float* __restrict__ bias,
                                              int n) {
    __shared__ __align__(16) float sA[128 * 36];
    __shared__ __align__(16) float sW[128 * 36];

    const int tid = threadIdx.x;
    const int lane = tid & 31;
    const int warp = tid >> 5;
    const int group = lane >> 2;     // 0..7
    const int tg = lane & 3;         // 0..3
    const int m0 = (warp & 3) * 32;  // warp row offset in tile
    const int n0 = (warp >> 2) * 64; // warp col offset in tile
    const int row0 = blockIdx.x * 128;

    float acc[2][8][4];
#pragma unroll
    for (int i = 0; i < 2; i++)
#pragma unroll
        for (int j = 0; j < 8; j++)
#pragma unroll
            for (int q = 0; q < 4; q++) acc[i][j][q] = 0.0f;

    for (int kb = 0; kb < 128; kb += 32) {
        // load A tile: 128 rows x 32 floats
#pragma unroll
        for (int r = 0; r < 4; r++) {
            int idx = r * 256 + tid;
            int arow = idx >> 3;
            int k4 = idx & 7;
            int grow = row0 + arow;
            float4 v = make_float4(0.f, 0.f, 0.f, 0.f);
            if (grow < n)
                v = *reinterpret_cast<const float4*>(&A[(size_t)grow * 128 + kb + k4 * 4]);
            *reinterpret_cast<float4*>(&sA[arow * 36 + k4 * 4]) = v;
        }
        // load W tile: sW[j][k] = W[j][kb+k]
#pragma unroll
        for (int r = 0; r < 4; r++) {
            int idx = r * 256 + tid;
            int j = idx >> 3;
            int k4 = idx & 7;
            float4 v = *reinterpret_cast<const float4*>(&W[(size_t)j * 128 + kb + k4 * 4]);
            *reinterpret_cast<float4*>(&sW[j * 36 + k4 * 4]) = v;
        }
        __syncthreads();

#pragma unroll
        for (int ks = 0; ks < 32; ks += 8) {
            // A fragments (2 m-tiles), hi+lo split
            unsigned ah[2][4], al[2][4];
#pragma unroll
            for (int i = 0; i < 2; i++) {
                int rb = m0 + 16 * i;
                float a0 = sA[(rb + group) * 36 + ks + tg];
                float a1 = sA[(rb + group + 8) * 36 + ks + tg];
                float a2 = sA[(rb + group) * 36 + ks + tg + 4];
                float a3 = sA[(rb + group + 8) * 36 + ks + tg + 4];
                ah[i][0] = f2tf32(a0); al[i][0] = f2tf32(a0 - __uint_as_float(ah[i][0]));
                ah[i][1] = f2tf32(a1); al[i][1] = f2tf32(a1 - __uint_as_float(ah[i][1]));
                ah[i][2] = f2tf32(a2); al[i][2] = f2tf32(a2 - __uint_as_float(ah[i][2]));
                ah[i][3] = f2tf32(a3); al[i][3] = f2tf32(a3 - __uint_as_float(ah[i][3]));
            }
            // B fragments per n-tile, 3 mma products each
#pragma unroll
            for (int j = 0; j < 8; j++) {
                float b0 = sW[(n0 + 8 * j + group) * 36 + ks + tg];
                float b1 = sW[(n0 + 8 * j + group) * 36 + ks + tg + 4];
                unsigned bh[2], bl[2];
                bh[0] = f2tf32(b0); bl[0] = f2tf32(b0 - __uint_as_float(bh[0]));
                bh[1] = f2tf32(b1); bl[1] = f2tf32(b1 - __uint_as_float(bh[1]));
#pragma unroll
                for (int i = 0; i < 2; i++) {
                    mma_tf32(acc[i][j], ah[i], bh);   // hi*hi
                    mma_tf32(acc[i][j], ah[i], bl);   // hi*lo
                    mma_tf32(acc[i][j], al[i], bh);   // lo*hi
                }
            }
        }
        __syncthreads();
    }

    // epilogue: + bias, store (thread owns rows m0+16i+group{,+8}, cols n0+8j+2tg{,+1})
#pragma unroll
    for (int j = 0; j < 8; j++) {
        int col = n0 + 8 * j + 2 * tg;
        float b0 = bias[col];
        float b1 = bias[col + 1];
#pragma unroll
        for (int i = 0; i < 2; i++) {
            int r_lo = row0 + m0 + 16 * i + group;
            int r_hi = r_lo + 8;
            if (r_lo < n) {
                float2 v = make_float2(acc[i][j][0] + b0, acc[i][j][1] + b1);
                *reinterpret_cast<float2*>(&g_hl[(size_t)r_lo * 128 + col]) = v;
            }
            if (r_hi < n) {
                float2 v = make_float2(acc[i][j][2] + b0, acc[i][j][3] + b1);
                *reinterpret_cast<float2*>(&g_hl[(size_t)r_hi * 128 + col]) = v;
            }
        }
    }
}

// ---------------- fused per-node layer kernel ----------------
__global__ __launch_bounds__(256) void k_layer(const float* __restrict__ rootl,
                                               const float* __restrict__ gammal,
                                               const float* __restrict__ betal,
                                               const float* __restrict__ meanl,
                                               const float* __restrict__ varl,
                                               float* __restrict__ out, int do_relu) {
    const int warp = (blockIdx.x * blockDim.x + threadIdx.x) >> 5;
    const int lane = threadIdx.x & 31;
    if (warp >= NN) return;
    const int i = warp;
    const int c4 = lane * 4;

    float4 h4 = *reinterpret_cast<const float4*>(&g_hl[(size_t)i * 128 + c4]);
    float4 r4 = *reinterpret_cast<const float4*>(&rootl[c4]);
    const float rd = g_rdeg[i];
    float ax = fmaxf(h4.x + r4.x, 0.f) * rd;
    float ay = fmaxf(h4.y + r4.y, 0.f) * rd;
    float az = fmaxf(h4.z + r4.z, 0.f) * rd;
    float aw = fmaxf(h4.w + r4.w, 0.f) * rd;

    const int s = g_start[i];
    const int e_end = g_start[i + 1];
    const unsigned sh = (lane & 3) * 8;
    const int wsel = lane >> 2;
    for (int p = s; p < e_end; p++) {
        int2 rn = g_csr_rn[p];
        float nm = __int_as_float(rn.y);
        unsigned w = g_pk_csr[(size_t)p * 8 + wsel];
        unsigned byte = (w >> sh) & 0xFFu;
        float4 hv = *reinterpret_cast<const float4*>(&g_hl[(size_t)rn.x * 128 + c4]);
        ax += fmaxf(hv.x + (float)(byte & 3u), 0.f) * nm;
        ay += fmaxf(hv.y + (float)((byte >> 2) & 3u), 0.f) * nm;
        az += fmaxf(hv.z + (float)((byte >> 4) & 3u), 0.f) * nm;
        aw += fmaxf(hv.w + (float)((byte >> 6) & 3u), 0.f) * nm;
    }

    float4 g4 = *reinterpret_cast<const float4*>(&gammal[c4]);
    float4 b4 = *reinterpret_cast<const float4*>(&betal[c4]);
    float4 m4 = *reinterpret_cast<const float4*>(&meanl[c4]);
    float4 v4 = *reinterpret_cast<const float4*>(&varl[c4]);
    float sx = g4.x * rsqrtf(v4.x + BN_EPS);
    float sy = g4.y * rsqrtf(v4.y + BN_EPS);
    float sz = g4.z * rsqrtf(v4.z + BN_EPS);
    float sw = g4.w * rsqrtf(v4.w + BN_EPS);
    float4 o;
    o.x = ax * sx + (b4.x - m4.x * sx);
    o.y = ay * sy + (b4.y - m4.y * sy);
    o.z = az * sz + (b4.z - m4.z * sz);
    o.w = aw * sw + (b4.w - m4.w * sw);
    if (do_relu) {
        o.x = fmaxf(o.x, 0.f);
        o.y = fmaxf(o.y, 0.f);
        o.z = fmaxf(o.z, 0.f);
        o.w = fmaxf(o.w, 0.f);
    }
    *reinterpret_cast<float4*>(&out[(size_t)i * 128 + c4]) = o;
}

// ---------------- launcher ----------------
extern "C" void kernel_launch(void* const* d_in, const int* in_sizes, int n_in,
                              void* d_out, int out_size) {
    (void)in_sizes; (void)n_in; (void)out_size;
    const float* x    = (const float*)d_in[0];
    const int*   ei   = (const int*)d_in[1];     // int32 (JAX default, not x64)
    const int*   ea   = (const int*)d_in[2];
    const float* W    = (const float*)d_in[3];
    const float* b    = (const float*)d_in[4];
    const float* root = (const float*)d_in[5];
    const float* gam  = (const float*)d_in[6];
    const float* bet  = (const float*)d_in[7];
    const float* mean = (const float*)d_in[8];
    const float* var  = (const float*)d_in[9];
    float* out = (float*)d_out;

    const int gemm_blocks = (NN + 127) / 128;
    const int layer_blocks = (NN * 32 + 255) / 256;

    // launch order places the first k_gemm at position 6 -> ncu (-s 5 -c 1) profiles it
    k_zero<<<(NN + 255) / 256, 256>>>();                       // 1
    k_deg<<<(EE + 255) / 256, 256>>>(ei);                      // 2
    k_scanA<<<NB_SCAN, 1024>>>();                              // 3 (also dinv/rdeg)
    k_scanB<<<1, 128>>>();                                     // 4
    k_scanC<<<NB_SCAN, 1024>>>();                              // 5
    k_gemm<<<gemm_blocks, 256>>>(x, W, b, NN);                 // 6 (layer 0 GEMM)
    k_pack<<<(EE * 8 + 255) / 256, 256>>>(ea);                 // 7
    k_scatter<<<(EE + 255) / 256, 256>>>();                    // 8
    k_layer<<<layer_blocks, 256>>>(root, gam, bet, mean, var, out, 1);  // 9 (layer 0)

    for (int l = 1; l < 5; l++) {
        k_gemm<<<gemm_blocks, 256>>>(
            out, W + (size_t)l * 128 * 128, b + (size_t)l * 128, NN);
        k_layer<<<layer_blocks, 256>>>(root + (size_t)l * 128,
                                       gam + (size_t)l * 128, bet + (size_t)l * 128,
                                       mean + (size_t)l * 128, var + (size_t)l * 128,
                                       out, (l < 4) ? 1 : 0);
    }
}

// round 7
// speedup vs baseline: 2.4634x; 1.0077x over previous
#include <cuda_runtime.h>
#include <cstdint>

#define NN 100000
#define EE 600000
#define DD 128
#define BN_EPS 1e-5f
#define NB_SCAN 100          // scan blocks, 1000 elems each
#define GEMM_SMEM_BYTES (3 * 128 * 36 * 4)

// ---------------- scratch (static device globals; no runtime alloc) ----------------
__device__ __align__(16) float    g_hl  [(size_t)NN * DD];   // 51.2 MB
__device__ __align__(16) unsigned g_pk  [(size_t)EE * 8];    // edge-order packed attrs
__device__ __align__(16) unsigned g_pk_csr[(size_t)EE * 8];  // CSR-order packed attrs
__device__ __align__(16) int      g_row [EE];
__device__ __align__(16) int      g_col [EE];
__device__ __align__(16) float    g_deg [NN];
__device__ __align__(16) float    g_dinv[NN];
__device__ __align__(16) float    g_rdeg[NN];
// CSR by target (col)
__device__ __align__(16) int      g_cnt   [NN];
__device__ __align__(16) int      g_cursor[NN];
__device__ __align__(16) int      g_start [NN + 1];
__device__ __align__(16) int2     g_csr_rn[EE];              // {row, norm bits}
__device__ __align__(16) int      g_bsum[NB_SCAN];
__device__ __align__(16) int      g_boff[NB_SCAN];
// pre-split W (tf32 hi/lo), all 5 layers
__device__ __align__(16) unsigned g_Whi[5 * 128 * 128];
__device__ __align__(16) unsigned g_Wlo[5 * 128 * 128];

// ---------------- tf32 helpers ----------------
__device__ __forceinline__ unsigned f2tf32(float a) {
    unsigned r;
    asm("cvt.rna.tf32.f32 %0, %1;" : "=r"(r) : "f"(a));
    return r;
}
__device__ __forceinline__ void mma_tf32(float* c, const unsigned* a, const unsigned* b) {
    asm volatile(
        "mma.sync.aligned.m16n8k8.row.col.f32.tf32.tf32.f32 "
        "{%0,%1,%2,%3}, {%4,%5,%6,%7}, {%8,%9}, {%0,%1,%2,%3};"
        : "+f"(c[0]), "+f"(c[1]), "+f"(c[2]), "+f"(c[3])
        : "r"(a[0]), "r"(a[1]), "r"(a[2]), "r"(a[3]), "r"(b[0]), "r"(b[1]));
}

// ---------------- prep kernels ----------------
__global__ void k_zero() {
    int i = blockIdx.x * blockDim.x + threadIdx.x;
    if (i < NN) {
        g_deg[i] = 0.0f;
        g_cnt[i] = 0;
        g_cursor[i] = 0;
    }
}

// edge_index is int32 (JAX default config). Clamp defensively.
__global__ void k_deg(const int* __restrict__ ei) {
    int e = blockIdx.x * blockDim.x + threadIdx.x;
    if (e < EE) {
        int r = ei[e];
        int c = ei[EE + e];
        r = (r < 0) ? 0 : ((r >= NN) ? NN - 1 : r);
        c = (c < 0) ? 0 : ((c >= NN) ? NN - 1 : c);
        g_row[e] = r;
        g_col[e] = c;
        atomicAdd(&g_deg[r], 1.0f);        // out-degree (reference's deg)
        atomicAdd(&g_cnt[c], 1);           // in-degree for CSR
    }
}

// split all 5 layers' W into tf32 hi/lo once per launch
__global__ void k_splitW(const float* __restrict__ W) {
    int i = blockIdx.x * blockDim.x + threadIdx.x;
    if (i < 5 * 128 * 128) {
        float w = W[i];
        unsigned hi = f2tf32(w);
        g_Whi[i] = hi;
        g_Wlo[i] = f2tf32(w - __uint_as_float(hi));
    }
}

// scan pass A: per-chunk block sums of g_cnt; also finish deg -> dinv/rdeg
__global__ __launch_bounds__(1024) void k_scanA() {
    __shared__ int red[1024];
    const int b = blockIdx.x, t = threadIdx.x;
    const int i = b * 1000 + t;
    int v = 0;
    if (t < 1000 && i < NN) {
        v = g_cnt[i];
        float d = g_deg[i] + 1.0f;
        g_dinv[i] = rsqrtf(d);
        g_rdeg[i] = 1.0f / d;
    }
    red[t] = v;
    __syncthreads();
    for (int s = 512; s > 0; s >>= 1) {
        if (t < s) red[t] += red[t + s];
        __syncthreads();
    }
    if (t == 0) g_bsum[b] = red[0];
}

// scan pass B: exclusive scan of the 100 block sums
__global__ void k_scanB() {
    __shared__ int s[128];
    const int t = threadIdx.x;
    int v = (t < NB_SCAN) ? g_bsum[t] : 0;
    s[t] = v;
    __syncthreads();
    for (int d = 1; d < 128; d <<= 1) {
        int add = (t >= d) ? s[t - d] : 0;
        __syncthreads();
        s[t] += add;
        __syncthreads();
    }
    if (t < NB_SCAN) g_boff[t] = s[t] - v;
    if (t == 0) g_start[NN] = EE;
}

// scan pass C: per-chunk exclusive scan + block offset -> g_start
__global__ __launch_bounds__(1024) void k_scanC() {
    __shared__ int s[2][1024];
    const int b = blockIdx.x, t = threadIdx.x;
    const int i = b * 1000 + t;
    const int v = (t < 1000 && i < NN) ? g_cnt[i] : 0;
    int cur = 0;
    s[0][t] = v;
    __syncthreads();
    for (int d = 1; d < 1024; d <<= 1) {
        int nxt = cur ^ 1;
        s[nxt][t] = s[cur][t] + ((t >= d) ? s[cur][t - d] : 0);
        __syncthreads();
        cur = nxt;
    }
    if (t < 1000 && i < NN) g_start[i] = g_boff[b] + s[cur][t] - v;
}

// pack 16 consecutive int32 attr values (each 0..3) into one uint32
__global__ void k_pack(const int* __restrict__ ea) {
    int idx = blockIdx.x * blockDim.x + threadIdx.x;   // word index over EE*8
    if (idx < EE * 8) {
        const int4* p4 = reinterpret_cast<const int4*>(ea + (size_t)idx * 16);
        unsigned w = 0;
        int4 a = p4[0], b = p4[1], c = p4[2], d = p4[3];
        w |= ((unsigned)a.x & 3u) << 0;  w |= ((unsigned)a.y & 3u) << 2;
        w |= ((unsigned)a.z & 3u) << 4;  w |= ((unsigned)a.w & 3u) << 6;
        w |= ((unsigned)b.x & 3u) << 8;  w |= ((unsigned)b.y & 3u) << 10;
        w |= ((unsigned)b.z & 3u) << 12; w |= ((unsigned)b.w & 3u) << 14;
        w |= ((unsigned)c.x & 3u) << 16; w |= ((unsigned)c.y & 3u) << 18;
        w |= ((unsigned)c.z & 3u) << 20; w |= ((unsigned)c.w & 3u) << 22;
        w |= ((unsigned)d.x & 3u) << 24; w |= ((unsigned)d.y & 3u) << 26;
        w |= ((unsigned)d.z & 3u) << 28; w |= ((unsigned)d.w & 3u) << 30;
        g_pk[idx] = w;
    }
}

// scatter edges into CSR-by-col: packed (row, norm) + pk words in CSR order
__global__ void k_scatter() {
    int e = blockIdx.x * blockDim.x + threadIdx.x;
    if (e < EE) {
        int r = g_row[e];
        int c = g_col[e];
        int pos = atomicAdd(&g_cursor[c], 1);
        int idx = g_start[c] + pos;
        int2 rn;
        rn.x = r;
        rn.y = __float_as_int(g_dinv[r] * g_dinv[c]);
        g_csr_rn[idx] = rn;
        const uint4* src = reinterpret_cast<const uint4*>(&g_pk[(size_t)e * 8]);
        uint4* dst = reinterpret_cast<uint4*>(&g_pk_csr[(size_t)idx * 8]);
        dst[0] = src[0];
        dst[1] = src[1];
    }
}

// ---------------- GEMM (tf32 tc, 3-term split, pre-split W): g_hl = A@W^T + bias -------
// block 256 thr (8 warps), tile 128x128, K-chunk 32. warp tile 32x64.
// dyn smem: sA fp32 [128][36], sWhi/sWlo tf32 [128][36]. No B-side cvt in hot loop.
__global__ __launch_bounds__(256) void k_gemm(const float* __restrict__ A,
                                              const unsigned* __restrict__ Whi,
                                              const unsigned* __restrict__ Wlo,
                                              const float* __restrict__ bias,
                                              int n) {
    extern __shared__ __align__(16) float smem_dyn[];
    float*    sA   = smem_dyn;
    unsigned* sWhi = reinterpret_cast<unsigned*>(smem_dyn + 128 * 36);
    unsigned* sWlo = sWhi + 128 * 36;

    const int tid = threadIdx.x;
    const int lane = tid & 31;
    const int warp = tid >> 5;
    const int group = lane >> 2;     // 0..7
    const int tg = lane & 3;         // 0..3
    const int m0 = (warp & 3) * 32;  // warp row offset in tile
    const int n0 = (warp >> 2) * 64; // warp col offset in tile
    const int row0 = blockIdx.x * 128;

    float acc[2][8][4];
#pragma unroll
    for (int i = 0; i < 2; i++)
#pragma unroll
        for (int j = 0; j < 8; j++)
#pragma unroll
            for (int q = 0; q < 4; q++) acc[i][j][q] = 0.0f;

    for (int kb = 0; kb < 128; kb += 32) {
        // load A tile: 128 rows x 32 floats
#pragma unroll
        for (int r = 0; r < 4; r++) {
            int idx = r * 256 + tid;
            int arow = idx >> 3;
            int k4 = idx & 7;
            int grow = row0 + arow;
            float4 v = make_float4(0.f, 0.f, 0.f, 0.f);
            if (grow < n)
                v = *reinterpret_cast<const float4*>(&A[(size_t)grow * 128 + kb + k4 * 4]);
            *reinterpret_cast<float4*>(&sA[arow * 36 + k4 * 4]) = v;
        }
        // load pre-split W tiles: s[j][k] = W{hi,lo}[j][kb+k]
#pragma unroll
        for (int r = 0; r < 4; r++) {
            int idx = r * 256 + tid;
            int j = idx >> 3;
            int k4 = idx & 7;
            uint4 vh = *reinterpret_cast<const uint4*>(&Whi[(size_t)j * 128 + kb + k4 * 4]);
            uint4 vl = *reinterpret_cast<const uint4*>(&Wlo[(size_t)j * 128 + kb + k4 * 4]);
            *reinterpret_cast<uint4*>(&sWhi[j * 36 + k4 * 4]) = vh;
            *reinterpret_cast<uint4*>(&sWlo[j * 36 + k4 * 4]) = vl;
        }
        __syncthreads();

#pragma unroll
        for (int ks = 0; ks < 32; ks += 8) {
            // A fragments (2 m-tiles), hi+lo split in registers
            unsigned ah[2][4], al[2][4];
#pragma unroll
            for (int i = 0; i < 2; i++) {
                int rb = m0 + 16 * i;
                float a0 = sA[(rb + group) * 36 + ks + tg];
                float a1 = sA[(rb + group + 8) * 36 + ks + tg];
                float a2 = sA[(rb + group) * 36 + ks + tg + 4];
                float a3 = sA[(rb + group + 8) * 36 + ks + tg + 4];
                ah[i][0] = f2tf32(a0); al[i][0] = f2tf32(a0 - __uint_as_float(ah[i][0]));
                ah[i][1] = f2tf32(a1); al[i][1] = f2tf32(a1 - __uint_as_float(ah[i][1]));
                ah[i][2] = f2tf32(a2); al[i][2] = f2tf32(a2 - __uint_as_float(ah[i][2]));
                ah[i][3] = f2tf32(a3); al[i][3] = f2tf32(a3 - __uint_as_float(ah[i][3]));
            }
            // B fragments straight from pre-split smem (no cvt)
#pragma unroll
            for (int j = 0; j < 8; j++) {
                int base = (n0 + 8 * j + group) * 36 + ks + tg;
                unsigned bh[2], bl[2];
                bh[0] = sWhi[base];
                bh[1] = sWhi[base + 4];
                bl[0] = sWlo[base];
                bl[1] = sWlo[base + 4];
#pragma unroll
                for (int i = 0; i < 2; i++) {
                    mma_tf32(acc[i][j], ah[i], bh);   // hi*hi
                    mma_tf32(acc[i][j], ah[i], bl);   // hi*lo
                    mma_tf32(acc[i][j], al[i], bh);   // lo*hi
                }
            }
        }
        __syncthreads();
    }

    // epilogue: + bias, store (thread owns rows m0+16i+group{,+8}, cols n0+8j+2tg{,+1})
#pragma unroll
    for (int j = 0; j < 8; j++) {
        int col = n0 + 8 * j + 2 * tg;
        float b0 = bias[col];
        float b1 = bias[col + 1];
#pragma unroll
        for (int i = 0; i < 2; i++) {
            int r_lo = row0 + m0 + 16 * i + group;
            int r_hi = r_lo + 8;
            if (r_lo < n) {
                float2 v = make_float2(acc[i][j][0] + b0, acc[i][j][1] + b1);
                *reinterpret_cast<float2*>(&g_hl[(size_t)r_lo * 128 + col]) = v;
            }
            if (r_hi < n) {
                float2 v = make_float2(acc[i][j][2] + b0, acc[i][j][3] + b1);
                *reinterpret_cast<float2*>(&g_hl[(size_t)r_hi * 128 + col]) = v;
            }
        }
    }
}

// ---------------- fused per-node layer kernel ----------------
__global__ __launch_bounds__(256) void k_layer(const float* __restrict__ rootl,
                                               const float* __restrict__ gammal,
                                               const float* __restrict__ betal,
                                               const float* __restrict__ meanl,
                                               const float* __restrict__ varl,
                                               float* __restrict__ out, int do_relu) {
    const int warp = (blockIdx.x * blockDim.x + threadIdx.x) >> 5;
    const int lane = threadIdx.x & 31;
    if (warp >= NN) return;
    const int i = warp;
    const int c4 = lane * 4;

    float4 h4 = *reinterpret_cast<const float4*>(&g_hl[(size_t)i * 128 + c4]);
    float4 r4 = *reinterpret_cast<const float4*>(&rootl[c4]);
    const float rd = g_rdeg[i];
    float ax = fmaxf(h4.x + r4.x, 0.f) * rd;
    float ay = fmaxf(h4.y + r4.y, 0.f) * rd;
    float az = fmaxf(h4.z + r4.z, 0.f) * rd;
    float aw = fmaxf(h4.w + r4.w, 0.f) * rd;

    const int s = g_start[i];
    const int e_end = g_start[i + 1];
    const unsigned sh = (lane & 3) * 8;
    const int wsel = lane >> 2;

    if (s < e_end) {
        // 1-ahead prefetch of the uniform per-edge data
        int2 rn = g_csr_rn[s];
        unsigned w = g_pk_csr[(size_t)s * 8 + wsel];
        for (int p = s; p < e_end; p++) {
            int2 rn_cur = rn;
            unsigned w_cur = w;
            if (p + 1 < e_end) {
                rn = g_csr_rn[p + 1];
                w = g_pk_csr[(size_t)(p + 1) * 8 + wsel];
            }
            float nm = __int_as_float(rn_cur.y);
            unsigned byte = (w_cur >> sh) & 0xFFu;
            float4 hv = *reinterpret_cast<const float4*>(&g_hl[(size_t)rn_cur.x * 128 + c4]);
            ax += fmaxf(hv.x + (float)(byte & 3u), 0.f) * nm;
            ay += fmaxf(hv.y + (float)((byte >> 2) & 3u), 0.f) * nm;
            az += fmaxf(hv.z + (float)((byte >> 4) & 3u), 0.f) * nm;
            aw += fmaxf(hv.w + (float)((byte >> 6) & 3u), 0.f) * nm;
        }
    }

    float4 g4 = *reinterpret_cast<const float4*>(&gammal[c4]);
    float4 b4 = *reinterpret_cast<const float4*>(&betal[c4]);
    float4 m4 = *reinterpret_cast<const float4*>(&meanl[c4]);
    float4 v4 = *reinterpret_cast<const float4*>(&varl[c4]);
    float sx = g4.x * rsqrtf(v4.x + BN_EPS);
    float sy = g4.y * rsqrtf(v4.y + BN_EPS);
    float sz = g4.z * rsqrtf(v4.z + BN_EPS);
    float sw = g4.w * rsqrtf(v4.w + BN_EPS);
    float4 o;
    o.x = ax * sx + (b4.x - m4.x * sx);
    o.y = ay * sy + (b4.y - m4.y * sy);
    o.z = az * sz + (b4.z - m4.z * sz);
    o.w = aw * sw + (b4.w - m4.w * sw);
    if (do_relu) {
        o.x = fmaxf(o.x, 0.f);
        o.y = fmaxf(o.y, 0.f);
        o.z = fmaxf(o.z, 0.f);
        o.w = fmaxf(o.w, 0.f);
    }
    *reinterpret_cast<float4*>(&out[(size_t)i * 128 + c4]) = o;
}

// ---------------- launcher ----------------
extern "C" void kernel_launch(void* const* d_in, const int* in_sizes, int n_in,
                              void* d_out, int out_size) {
    (void)in_sizes; (void)n_in; (void)out_size;
    const float* x    = (const float*)d_in[0];
    const int*   ei   = (const int*)d_in[1];     // int32 (JAX default, not x64)
    const int*   ea   = (const int*)d_in[2];
    const float* W    = (const float*)d_in[3];
    const float* b    = (const float*)d_in[4];
    const float* root = (const float*)d_in[5];
    const float* gam  = (const float*)d_in[6];
    const float* bet  = (const float*)d_in[7];
    const float* mean = (const float*)d_in[8];
    const float* var  = (const float*)d_in[9];
    float* out = (float*)d_out;

    static bool attr_done = false;
    if (!attr_done) {
        cudaFuncSetAttribute(k_gemm, cudaFuncAttributeMaxDynamicSharedMemorySize,
                             GEMM_SMEM_BYTES);
        attr_done = true;
    }

    unsigned* whi_p = nullptr;
    unsigned* wlo_p = nullptr;
    cudaGetSymbolAddress((void**)&whi_p, g_Whi);
    cudaGetSymbolAddress((void**)&wlo_p, g_Wlo);

    const int gemm_blocks = (NN + 127) / 128;
    const int layer_blocks = (NN * 32 + 255) / 256;

    // ncu (-s 5 -c 1) has landed on launch index 3 each round -> put k_gemm there
    k_zero<<<(NN + 255) / 256, 256>>>();                                  // idx 0
    k_deg<<<(EE + 255) / 256, 256>>>(ei);                                 // idx 1
    k_splitW<<<(5 * 128 * 128 + 255) / 256, 256>>>(W);                    // idx 2
    k_gemm<<<gemm_blocks, 256, GEMM_SMEM_BYTES>>>(x, whi_p, wlo_p, b, NN); // idx 3 <- ncu
    k_scanA<<<NB_SCAN, 1024>>>();
    k_scanB<<<1, 128>>>();
    k_scanC<<<NB_SCAN, 1024>>>();
    k_pack<<<(EE * 8 + 255) / 256, 256>>>(ea);
    k_scatter<<<(EE + 255) / 256, 256>>>();
    k_layer<<<layer_blocks, 256>>>(root, gam, bet, mean, var, out, 1);

    for (int l = 1; l < 5; l++) {
        k_gemm<<<gemm_blocks, 256, GEMM_SMEM_BYTES>>>(
            out, whi_p + (size_t)l * 128 * 128, wlo_p + (size_t)l * 128 * 128,
            b + (size_t)l * 128, NN);
        k_layer<<<layer_blocks, 256>>>(root + (size_t)l * 128,
                                       gam + (size_t)l * 128, bet + (size_t)l * 128,
                                       mean + (size_t)l * 128, var + (size_t)l * 128,
                                       out, (l < 4) ? 1 : 0);
    }
}

// round 8
// speedup vs baseline: 2.7549x; 1.1183x over previous
#include <cuda_runtime.h>
#include <cstdint>

#define NN 100000
#define EE 600000
#define DD 128
#define BN_EPS 1e-5f
#define NB_SCAN 100          // scan blocks, 1000 elems each
#define GEMM_SMEM_BYTES (3 * 128 * 36 * 4)

// ---------------- scratch (static device globals; no runtime alloc) ----------------
__device__ __align__(16) float    g_hl  [(size_t)NN * DD];   // 51.2 MB
__device__ __align__(16) unsigned g_pk  [(size_t)EE * 8];    // edge-order packed attrs
__device__ __align__(16) unsigned g_pk_csr[(size_t)EE * 8];  // CSR-order packed attrs
__device__ __align__(16) int      g_row [EE];
__device__ __align__(16) int      g_col [EE];
__device__ __align__(16) float    g_deg [NN];
__device__ __align__(16) float    g_dinv[NN];
__device__ __align__(16) float    g_rdeg[NN];
// CSR by target (col)
__device__ __align__(16) int      g_cnt   [NN];
__device__ __align__(16) int      g_cursor[NN];
__device__ __align__(16) int      g_start [NN + 1];
__device__ __align__(16) int2     g_csr_rn[EE];              // {row, norm bits}
__device__ __align__(16) int      g_bsum[NB_SCAN];
__device__ __align__(16) int      g_boff[NB_SCAN];
// pre-split W (tf32 hi/lo), all 5 layers
__device__ __align__(16) unsigned g_Whi[5 * 128 * 128];
__device__ __align__(16) unsigned g_Wlo[5 * 128 * 128];

// ---------------- tf32 helpers ----------------
__device__ __forceinline__ unsigned f2tf32(float a) {
    unsigned r;
    asm("cvt.rna.tf32.f32 %0, %1;" : "=r"(r) : "f"(a));
    return r;
}
__device__ __forceinline__ void mma_tf32(float* c, const unsigned* a, const unsigned* b) {
    asm volatile(
        "mma.sync.aligned.m16n8k8.row.col.f32.tf32.tf32.f32 "
        "{%0,%1,%2,%3}, {%4,%5,%6,%7}, {%8,%9}, {%0,%1,%2,%3};"
        : "+f"(c[0]), "+f"(c[1]), "+f"(c[2]), "+f"(c[3])
        : "r"(a[0]), "r"(a[1]), "r"(a[2]), "r"(a[3]), "r"(b[0]), "r"(b[1]));
}

// ---------------- prep kernels ----------------
__global__ void k_zero() {
    int i = blockIdx.x * blockDim.x + threadIdx.x;
    if (i < NN) {
        g_deg[i] = 0.0f;
        g_cnt[i] = 0;
        g_cursor[i] = 0;
    }
}

// edge_index is int32 (JAX default config). Clamp defensively.
__global__ void k_deg(const int* __restrict__ ei) {
    int e = blockIdx.x * blockDim.x + threadIdx.x;
    if (e < EE) {
        int r = ei[e];
        int c = ei[EE + e];
        r = (r < 0) ? 0 : ((r >= NN) ? NN - 1 : r);
        c = (c < 0) ? 0 : ((c >= NN) ? NN - 1 : c);
        g_row[e] = r;
        g_col[e] = c;
        atomicAdd(&g_deg[r], 1.0f);        // out-degree (reference's deg)
        atomicAdd(&g_cnt[c], 1);           // in-degree for CSR
    }
}

// split all 5 layers' W into tf32 hi/lo once per launch
__global__ void k_splitW(const float* __restrict__ W) {
    int i = blockIdx.x * blockDim.x + threadIdx.x;
    if (i < 5 * 128 * 128) {
        float w = W[i];
        unsigned hi = f2tf32(w);
        g_Whi[i] = hi;
        g_Wlo[i] = f2tf32(w - __uint_as_float(hi));
    }
}

// scan pass A: per-chunk block sums of g_cnt; also finish deg -> dinv/rdeg
__global__ __launch_bounds__(1024) void k_scanA() {
    __shared__ int red[1024];
    const int b = blockIdx.x, t = threadIdx.x;
    const int i = b * 1000 + t;
    int v = 0;
    if (t < 1000 && i < NN) {
        v = g_cnt[i];
        float d = g_deg[i] + 1.0f;
        g_dinv[i] = rsqrtf(d);
        g_rdeg[i] = 1.0f / d;
    }
    red[t] = v;
    __syncthreads();
    for (int s = 512; s > 0; s >>= 1) {
        if (t < s) red[t] += red[t + s];
        __syncthreads();
    }
    if (t == 0) g_bsum[b] = red[0];
}

// scan pass B: exclusive scan of the 100 block sums
__global__ void k_scanB() {
    __shared__ int s[128];
    const int t = threadIdx.x;
    int v = (t < NB_SCAN) ? g_bsum[t] : 0;
    s[t] = v;
    __syncthreads();
    for (int d = 1; d < 128; d <<= 1) {
        int add = (t >= d) ? s[t - d] : 0;
        __syncthreads();
        s[t] += add;
        __syncthreads();
    }
    if (t < NB_SCAN) g_boff[t] = s[t] - v;
    if (t == 0) g_start[NN] = EE;
}

// scan pass C: per-chunk exclusive scan + block offset -> g_start
__global__ __launch_bounds__(1024) void k_scanC() {
    __shared__ int s[2][1024];
    const int b = blockIdx.x, t = threadIdx.x;
    const int i = b * 1000 + t;
    const int v = (t < 1000 && i < NN) ? g_cnt[i] : 0;
    int cur = 0;
    s[0][t] = v;
    __syncthreads();
    for (int d = 1; d < 1024; d <<= 1) {
        int nxt = cur ^ 1;
        s[nxt][t] = s[cur][t] + ((t >= d) ? s[cur][t - d] : 0);
        __syncthreads();
        cur = nxt;
    }
    if (t < 1000 && i < NN) g_start[i] = g_boff[b] + s[cur][t] - v;
}

// pack 16 consecutive int32 attr values (each 0..3) into one uint32
__global__ void k_pack(const int* __restrict__ ea) {
    int idx = blockIdx.x * blockDim.x + threadIdx.x;   // word index over EE*8
    if (idx < EE * 8) {
        const int4* p4 = reinterpret_cast<const int4*>(ea + (size_t)idx * 16);
        unsigned w = 0;
        int4 a = p4[0], b = p4[1], c = p4[2], d = p4[3];
        w |= ((unsigned)a.x & 3u) << 0;  w |= ((unsigned)a.y & 3u) << 2;
        w |= ((unsigned)a.z & 3u) << 4;  w |= ((unsigned)a.w & 3u) << 6;
        w |= ((unsigned)b.x & 3u) << 8;  w |= ((unsigned)b.y & 3u) << 10;
        w |= ((unsigned)b.z & 3u) << 12; w |= ((unsigned)b.w & 3u) << 14;
        w |= ((unsigned)c.x & 3u) << 16; w |= ((unsigned)c.y & 3u) << 18;
        w |= ((unsigned)c.z & 3u) << 20; w |= ((unsigned)c.w & 3u) << 22;
        w |= ((unsigned)d.x & 3u) << 24; w |= ((unsigned)d.y & 3u) << 26;
        w |= ((unsigned)d.z & 3u) << 28; w |= ((unsigned)d.w & 3u) << 30;
        g_pk[idx] = w;
    }
}

// scatter edges into CSR-by-col: packed (row, norm) + pk words in CSR order
__global__ void k_scatter() {
    int e = blockIdx.x * blockDim.x + threadIdx.x;
    if (e < EE) {
        int r = g_row[e];
        int c = g_col[e];
        int pos = atomicAdd(&g_cursor[c], 1);
        int idx = g_start[c] + pos;
        int2 rn;
        rn.x = r;
        rn.y = __float_as_int(g_dinv[r] * g_dinv[c]);
        g_csr_rn[idx] = rn;
        const uint4* src = reinterpret_cast<const uint4*>(&g_pk[(size_t)e * 8]);
        uint4* dst = reinterpret_cast<uint4*>(&g_pk_csr[(size_t)idx * 8]);
        dst[0] = src[0];
        dst[1] = src[1];
    }
}

// ---------------- GEMM (tf32 tc, 3-term split, pre-split W): g_hl = A@W^T + bias -------
// block 256 thr (8 warps), tile 128x128, K-chunk 32. warp tile 32x64.
// launch_bounds(256,2): cap at 128 regs -> 2 blocks/SM -> 16 warps/SM.
__global__ __launch_bounds__(256, 2) void k_gemm(const float* __restrict__ A,
                                                 const unsigned* __restrict__ Whi,
                                                 const unsigned* __restrict__ Wlo,
                                                 const float* __restrict__ bias,
                                                 int n) {
    extern __shared__ __align__(16) float smem_dyn[];
    float*    sA   = smem_dyn;
    unsigned* sWhi = reinterpret_cast<unsigned*>(smem_dyn + 128 * 36);
    unsigned* sWlo = sWhi + 128 * 36;

    const int tid = threadIdx.x;
    const int lane = tid & 31;
    const int warp = tid >> 5;
    const int group = lane >> 2;     // 0..7
    const int tg = lane & 3;         // 0..3
    const int m0 = (warp & 3) * 32;  // warp row offset in tile
    const int n0 = (warp >> 2) * 64; // warp col offset in tile
    const int row0 = blockIdx.x * 128;

    float acc[2][8][4];
#pragma unroll
    for (int i = 0; i < 2; i++)
#pragma unroll
        for (int j = 0; j < 8; j++)
#pragma unroll
            for (int q = 0; q < 4; q++) acc[i][j][q] = 0.0f;

    for (int kb = 0; kb < 128; kb += 32) {
        // load A tile: 128 rows x 32 floats
#pragma unroll
        for (int r = 0; r < 4; r++) {
            int idx = r * 256 + tid;
            int arow = idx >> 3;
            int k4 = idx & 7;
            int grow = row0 + arow;
            float4 v = make_float4(0.f, 0.f, 0.f, 0.f);
            if (grow < n)
                v = *reinterpret_cast<const float4*>(&A[(size_t)grow * 128 + kb + k4 * 4]);
            *reinterpret_cast<float4*>(&sA[arow * 36 + k4 * 4]) = v;
        }
        // load pre-split W tiles: s[j][k] = W{hi,lo}[j][kb+k]
#pragma unroll
        for (int r = 0; r < 4; r++) {
            int idx = r * 256 + tid;
            int j = idx >> 3;
            int k4 = idx & 7;
            uint4 vh = *reinterpret_cast<const uint4*>(&Whi[(size_t)j * 128 + kb + k4 * 4]);
            uint4 vl = *reinterpret_cast<const uint4*>(&Wlo[(size_t)j * 128 + kb + k4 * 4]);
            *reinterpret_cast<uint4*>(&sWhi[j * 36 + k4 * 4]) = vh;
            *reinterpret_cast<uint4*>(&sWlo[j * 36 + k4 * 4]) = vl;
        }
        __syncthreads();

#pragma unroll
        for (int ks = 0; ks < 32; ks += 8) {
            // A fragments (2 m-tiles), hi+lo split in registers
            unsigned ah[2][4], al[2][4];
#pragma unroll
            for (int i = 0; i < 2; i++) {
                int rb = m0 + 16 * i;
                float a0 = sA[(rb + group) * 36 + ks + tg];
                float a1 = sA[(rb + group + 8) * 36 + ks + tg];
                float a2 = sA[(rb + group) * 36 + ks + tg + 4];
                float a3 = sA[(rb + group + 8) * 36 + ks + tg + 4];
                ah[i][0] = f2tf32(a0); al[i][0] = f2tf32(a0 - __uint_as_float(ah[i][0]));
                ah[i][1] = f2tf32(a1); al[i][1] = f2tf32(a1 - __uint_as_float(ah[i][1]));
                ah[i][2] = f2tf32(a2); al[i][2] = f2tf32(a2 - __uint_as_float(ah[i][2]));
                ah[i][3] = f2tf32(a3); al[i][3] = f2tf32(a3 - __uint_as_float(ah[i][3]));
            }
            // B fragments straight from pre-split smem (no cvt)
#pragma unroll
            for (int j = 0; j < 8; j++) {
                int base = (n0 + 8 * j + group) * 36 + ks + tg;
                unsigned bh[2], bl[2];
                bh[0] = sWhi[base];
                bh[1] = sWhi[base + 4];
                bl[0] = sWlo[base];
                bl[1] = sWlo[base + 4];
#pragma unroll
                for (int i = 0; i < 2; i++) {
                    mma_tf32(acc[i][j], ah[i], bh);   // hi*hi
                    mma_tf32(acc[i][j], ah[i], bl);   // hi*lo
                    mma_tf32(acc[i][j], al[i], bh);   // lo*hi
                }
            }
        }
        __syncthreads();
    }

    // epilogue: + bias, store (thread owns rows m0+16i+group{,+8}, cols n0+8j+2tg{,+1})
#pragma unroll
    for (int j = 0; j < 8; j++) {
        int col = n0 + 8 * j + 2 * tg;
        float b0 = bias[col];
        float b1 = bias[col + 1];
#pragma unroll
        for (int i = 0; i < 2; i++) {
            int r_lo = row0 + m0 + 16 * i + group;
            int r_hi = r_lo + 8;
            if (r_lo < n) {
                float2 v = make_float2(acc[i][j][0] + b0, acc[i][j][1] + b1);
                *reinterpret_cast<float2*>(&g_hl[(size_t)r_lo * 128 + col]) = v;
            }
            if (r_hi < n) {
                float2 v = make_float2(acc[i][j][2] + b0, acc[i][j][3] + b1);
                *reinterpret_cast<float2*>(&g_hl[(size_t)r_hi * 128 + col]) = v;
            }
        }
    }
}

// ---------------- fused per-node layer kernel ----------------
__global__ __launch_bounds__(256) void k_layer(const float* __restrict__ rootl,
                                               const float* __restrict__ gammal,
                                               const float* __restrict__ betal,
                                               const float* __restrict__ meanl,
                                               const float* __restrict__ varl,
                                               float* __restrict__ out, int do_relu) {
    const int warp = (blockIdx.x * blockDim.x + threadIdx.x) >> 5;
    const int lane = threadIdx.x & 31;
    if (warp >= NN) return;
    const int i = warp;
    const int c4 = lane * 4;

    float4 h4 = *reinterpret_cast<const float4*>(&g_hl[(size_t)i * 128 + c4]);
    float4 r4 = *reinterpret_cast<const float4*>(&rootl[c4]);
    const float rd = g_rdeg[i];
    float ax = fmaxf(h4.x + r4.x, 0.f) * rd;
    float ay = fmaxf(h4.y + r4.y, 0.f) * rd;
    float az = fmaxf(h4.z + r4.z, 0.f) * rd;
    float aw = fmaxf(h4.w + r4.w, 0.f) * rd;

    const int s = g_start[i];
    const int e_end = g_start[i + 1];
    const unsigned sh = (lane & 3) * 8;
    const int wsel = lane >> 2;

    if (s < e_end) {
        // 1-ahead prefetch of the uniform per-edge data
        int2 rn = g_csr_rn[s];
        unsigned w = g_pk_csr[(size_t)s * 8 + wsel];
        for (int p = s; p < e_end; p++) {
            int2 rn_cur = rn;
            unsigned w_cur = w;
            if (p + 1 < e_end) {
                rn = g_csr_rn[p + 1];
                w = g_pk_csr[(size_t)(p + 1) * 8 + wsel];
            }
            float nm = __int_as_float(rn_cur.y);
            unsigned byte = (w_cur >> sh) & 0xFFu;
            float4 hv = *reinterpret_cast<const float4*>(&g_hl[(size_t)rn_cur.x * 128 + c4]);
            ax += fmaxf(hv.x + (float)(byte & 3u), 0.f) * nm;
            ay += fmaxf(hv.y + (float)((byte >> 2) & 3u), 0.f) * nm;
            az += fmaxf(hv.z + (float)((byte >> 4) & 3u), 0.f) * nm;
            aw += fmaxf(hv.w + (float)((byte >> 6) & 3u), 0.f) * nm;
        }
    }

    float4 g4 = *reinterpret_cast<const float4*>(&gammal[c4]);
    float4 b4 = *reinterpret_cast<const float4*>(&betal[c4]);
    float4 m4 = *reinterpret_cast<const float4*>(&meanl[c4]);
    float4 v4 = *reinterpret_cast<const float4*>(&varl[c4]);
    float sx = g4.x * rsqrtf(v4.x + BN_EPS);
    float sy = g4.y * rsqrtf(v4.y + BN_EPS);
    float sz = g4.z * rsqrtf(v4.z + BN_EPS);
    float sw = g4.w * rsqrtf(v4.w + BN_EPS);
    float4 o;
    o.x = ax * sx + (b4.x - m4.x * sx);
    o.y = ay * sy + (b4.y - m4.y * sy);
    o.z = az * sz + (b4.z - m4.z * sz);
    o.w = aw * sw + (b4.w - m4.w * sw);
    if (do_relu) {
        o.x = fmaxf(o.x, 0.f);
        o.y = fmaxf(o.y, 0.f);
        o.z = fmaxf(o.z, 0.f);
        o.w = fmaxf(o.w, 0.f);
    }
    *reinterpret_cast<float4*>(&out[(size_t)i * 128 + c4]) = o;
}

// ---------------- launcher ----------------
extern "C" void kernel_launch(void* const* d_in, const int* in_sizes, int n_in,
                              void* d_out, int out_size) {
    (void)in_sizes; (void)n_in; (void)out_size;
    const float* x    = (const float*)d_in[0];
    const int*   ei   = (const int*)d_in[1];     // int32 (JAX default, not x64)
    const int*   ea   = (const int*)d_in[2];
    const float* W    = (const float*)d_in[3];
    const float* b    = (const float*)d_in[4];
    const float* root = (const float*)d_in[5];
    const float* gam  = (const float*)d_in[6];
    const float* bet  = (const float*)d_in[7];
    const float* mean = (const float*)d_in[8];
    const float* var  = (const float*)d_in[9];
    float* out = (float*)d_out;

    static bool attr_done = false;
    if (!attr_done) {
        cudaFuncSetAttribute(k_gemm, cudaFuncAttributeMaxDynamicSharedMemorySize,
                             GEMM_SMEM_BYTES);
        attr_done = true;
    }

    unsigned* whi_p = nullptr;
    unsigned* wlo_p = nullptr;
    cudaGetSymbolAddress((void**)&whi_p, g_Whi);
    cudaGetSymbolAddress((void**)&wlo_p, g_Wlo);

    const int gemm_blocks = (NN + 127) / 128;
    const int layer_blocks = (NN * 32 + 255) / 256;

    // ncu (-s 5 -c 1) lands on launch index 3 -> keep k_gemm there
    k_zero<<<(NN + 255) / 256, 256>>>();                                  // idx 0
    k_deg<<<(EE + 255) / 256, 256>>>(ei);                                 // idx 1
    k_splitW<<<(5 * 128 * 128 + 255) / 256, 256>>>(W);                    // idx 2
    k_gemm<<<gemm_blocks, 256, GEMM_SMEM_BYTES>>>(x, whi_p, wlo_p, b, NN); // idx 3 <- ncu
    k_scanA<<<NB_SCAN, 1024>>>();
    k_scanB<<<1, 128>>>();
    k_scanC<<<NB_SCAN, 1024>>>();
    k_pack<<<(EE * 8 + 255) / 256, 256>>>(ea);
    k_scatter<<<(EE + 255) / 256, 256>>>();
    k_layer<<<layer_blocks, 256>>>(root, gam, bet, mean, var, out, 1);

    for (int l = 1; l < 5; l++) {
        k_gemm<<<gemm_blocks, 256, GEMM_SMEM_BYTES>>>(
            out, whi_p + (size_t)l * 128 * 128, wlo_p + (size_t)l * 128 * 128,
            b + (size_t)l * 128, NN);
        k_layer<<<layer_blocks, 256>>>(root + (size_t)l * 128,
                                       gam + (size_t)l * 128, bet + (size_t)l * 128,
                                       mean + (size_t)l * 128, var + (size_t)l * 128,
                                       out, (l < 4) ? 1 : 0);
    }
}

// round 9
// speedup vs baseline: 2.8104x; 1.0202x over previous
#include <cuda_runtime.h>
#include <cstdint>

#define NN 100000
#define EE 600000
#define DD 128
#define BN_EPS 1e-5f
#define NB_SCAN 100          // scan blocks, 1000 elems each
// sA 128x36 fp32 + sWhi/sWlo 64x36 u32 = (4608 + 4608) * 4 bytes
#define GEMM_SMEM_BYTES ((128 * 36 + 2 * 64 * 36) * 4)

// ---------------- scratch (static device globals; no runtime alloc) ----------------
__device__ __align__(16) float    g_hl  [(size_t)NN * DD];   // 51.2 MB
__device__ __align__(16) unsigned g_pk  [(size_t)EE * 8];    // edge-order packed attrs
__device__ __align__(16) unsigned g_pk_csr[(size_t)EE * 8];  // CSR-order packed attrs
__device__ __align__(16) int      g_row [EE];
__device__ __align__(16) int      g_col [EE];
__device__ __align__(16) float    g_deg [NN];
__device__ __align__(16) float    g_dinv[NN];
__device__ __align__(16) float    g_rdeg[NN];
// CSR by target (col)
__device__ __align__(16) int      g_cnt   [NN];
__device__ __align__(16) int      g_cursor[NN];
__device__ __align__(16) int      g_start [NN + 1];
__device__ __align__(16) int2     g_csr_rn[EE];              // {row, norm bits}
__device__ __align__(16) int      g_bsum[NB_SCAN];
__device__ __align__(16) int      g_boff[NB_SCAN];
// pre-split W (tf32 hi/lo), all 5 layers
__device__ __align__(16) unsigned g_Whi[5 * 128 * 128];
__device__ __align__(16) unsigned g_Wlo[5 * 128 * 128];

// ---------------- tf32 helpers ----------------
__device__ __forceinline__ unsigned f2tf32(float a) {
    unsigned r;
    asm("cvt.rna.tf32.f32 %0, %1;" : "=r"(r) : "f"(a));
    return r;
}
__device__ __forceinline__ void mma_tf32(float* c, const unsigned* a, const unsigned* b) {
    asm volatile(
        "mma.sync.aligned.m16n8k8.row.col.f32.tf32.tf32.f32 "
        "{%0,%1,%2,%3}, {%4,%5,%6,%7}, {%8,%9}, {%0,%1,%2,%3};"
        : "+f"(c[0]), "+f"(c[1]), "+f"(c[2]), "+f"(c[3])
        : "r"(a[0]), "r"(a[1]), "r"(a[2]), "r"(a[3]), "r"(b[0]), "r"(b[1]));
}

// ---------------- prep kernels ----------------
__global__ void k_zero() {
    int i = blockIdx.x * blockDim.x + threadIdx.x;
    if (i < NN) {
        g_deg[i] = 0.0f;
        g_cnt[i] = 0;
        g_cursor[i] = 0;
    }
}

// edge_index is int32 (JAX default config). Clamp defensively.
__global__ void k_deg(const int* __restrict__ ei) {
    int e = blockIdx.x * blockDim.x + threadIdx.x;
    if (e < EE) {
        int r = ei[e];
        int c = ei[EE + e];
        r = (r < 0) ? 0 : ((r >= NN) ? NN - 1 : r);
        c = (c < 0) ? 0 : ((c >= NN) ? NN - 1 : c);
        g_row[e] = r;
        g_col[e] = c;
        atomicAdd(&g_deg[r], 1.0f);        // out-degree (reference's deg)
        atomicAdd(&g_cnt[c], 1);           // in-degree for CSR
    }
}

// split all 5 layers' W into tf32 hi/lo once per launch
__global__ void k_splitW(const float* __restrict__ W) {
    int i = blockIdx.x * blockDim.x + threadIdx.x;
    if (i < 5 * 128 * 128) {
        float w = W[i];
        unsigned hi = f2tf32(w);
        g_Whi[i] = hi;
        g_Wlo[i] = f2tf32(w - __uint_as_float(hi));
    }
}

// scan pass A: per-chunk block sums of g_cnt; also finish deg -> dinv/rdeg
__global__ __launch_bounds__(1024) void k_scanA() {
    __shared__ int red[1024];
    const int b = blockIdx.x, t = threadIdx.x;
    const int i = b * 1000 + t;
    int v = 0;
    if (t < 1000 && i < NN) {
        v = g_cnt[i];
        float d = g_deg[i] + 1.0f;
        g_dinv[i] = rsqrtf(d);
        g_rdeg[i] = 1.0f / d;
    }
    red[t] = v;
    __syncthreads();
    for (int s = 512; s > 0; s >>= 1) {
        if (t < s) red[t] += red[t + s];
        __syncthreads();
    }
    if (t == 0) g_bsum[b] = red[0];
}

// scan pass B: exclusive scan of the 100 block sums
__global__ void k_scanB() {
    __shared__ int s[128];
    const int t = threadIdx.x;
    int v = (t < NB_SCAN) ? g_bsum[t] : 0;
    s[t] = v;
    __syncthreads();
    for (int d = 1; d < 128; d <<= 1) {
        int add = (t >= d) ? s[t - d] : 0;
        __syncthreads();
        s[t] += add;
        __syncthreads();
    }
    if (t < NB_SCAN) g_boff[t] = s[t] - v;
    if (t == 0) g_start[NN] = EE;
}

// scan pass C: per-chunk exclusive scan + block offset -> g_start
__global__ __launch_bounds__(1024) void k_scanC() {
    __shared__ int s[2][1024];
    const int b = blockIdx.x, t = threadIdx.x;
    const int i = b * 1000 + t;
    const int v = (t < 1000 && i < NN) ? g_cnt[i] : 0;
    int cur = 0;
    s[0][t] = v;
    __syncthreads();
    for (int d = 1; d < 1024; d <<= 1) {
        int nxt = cur ^ 1;
        s[nxt][t] = s[cur][t] + ((t >= d) ? s[cur][t - d] : 0);
        __syncthreads();
        cur = nxt;
    }
    if (t < 1000 && i < NN) g_start[i] = g_boff[b] + s[cur][t] - v;
}

// pack 16 consecutive int32 attr values (each 0..3) into one uint32
__global__ void k_pack(const int* __restrict__ ea) {
    int idx = blockIdx.x * blockDim.x + threadIdx.x;   // word index over EE*8
    if (idx < EE * 8) {
        const int4* p4 = reinterpret_cast<const int4*>(ea + (size_t)idx * 16);
        unsigned w = 0;
        int4 a = p4[0], b = p4[1], c = p4[2], d = p4[3];
        w |= ((unsigned)a.x & 3u) << 0;  w |= ((unsigned)a.y & 3u) << 2;
        w |= ((unsigned)a.z & 3u) << 4;  w |= ((unsigned)a.w & 3u) << 6;
        w |= ((unsigned)b.x & 3u) << 8;  w |= ((unsigned)b.y & 3u) << 10;
        w |= ((unsigned)b.z & 3u) << 12; w |= ((unsigned)b.w & 3u) << 14;
        w |= ((unsigned)c.x & 3u) << 16; w |= ((unsigned)c.y & 3u) << 18;
        w |= ((unsigned)c.z & 3u) << 20; w |= ((unsigned)c.w & 3u) << 22;
        w |= ((unsigned)d.x & 3u) << 24; w |= ((unsigned)d.y & 3u) << 26;
        w |= ((unsigned)d.z & 3u) << 28; w |= ((unsigned)d.w & 3u) << 30;
        g_pk[idx] = w;
    }
}

// scatter edges into CSR-by-col: packed (row, norm) + pk words in CSR order
__global__ void k_scatter() {
    int e = blockIdx.x * blockDim.x + threadIdx.x;
    if (e < EE) {
        int r = g_row[e];
        int c = g_col[e];
        int pos = atomicAdd(&g_cursor[c], 1);
        int idx = g_start[c] + pos;
        int2 rn;
        rn.x = r;
        rn.y = __float_as_int(g_dinv[r] * g_dinv[c]);
        g_csr_rn[idx] = rn;
        const uint4* src = reinterpret_cast<const uint4*>(&g_pk[(size_t)e * 8]);
        uint4* dst = reinterpret_cast<uint4*>(&g_pk_csr[(size_t)idx * 8]);
        dst[0] = src[0];
        dst[1] = src[1];
    }
}

// ---------------- GEMM (tf32 tc, 3-term split, pre-split W): g_hl = A@W^T + bias -------
// block 256 thr (8 warps), tile 128x64, K-chunk 32. warp tile 32x32 (4m x 2n warps).
// acc 32 regs/thread -> launch_bounds(256,3): 3 blocks/SM = 24 warps.
__global__ __launch_bounds__(256, 3) void k_gemm(const float* __restrict__ A,
                                                 const unsigned* __restrict__ Whi,
                                                 const unsigned* __restrict__ Wlo,
                                                 const float* __restrict__ bias,
                                                 int n) {
    extern __shared__ __align__(16) float smem_dyn[];
    float*    sA   = smem_dyn;                                   // [128][36]
    unsigned* sWhi = reinterpret_cast<unsigned*>(smem_dyn + 128 * 36); // [64][36]
    unsigned* sWlo = sWhi + 64 * 36;                             // [64][36]

    const int tid = threadIdx.x;
    const int lane = tid & 31;
    const int warp = tid >> 5;
    const int group = lane >> 2;     // 0..7
    const int tg = lane & 3;         // 0..3
    const int m0 = (warp & 3) * 32;  // warp row offset in tile
    const int n0 = (warp >> 2) * 32; // warp col offset in tile (2 col-warps)
    const int row0 = (blockIdx.x >> 1) * 128;
    const int col0 = (blockIdx.x & 1) * 64;

    float acc[2][4][4];
#pragma unroll
    for (int i = 0; i < 2; i++)
#pragma unroll
        for (int j = 0; j < 4; j++)
#pragma unroll
            for (int q = 0; q < 4; q++) acc[i][j][q] = 0.0f;

    for (int kb = 0; kb < 128; kb += 32) {
        // load A tile: 128 rows x 32 floats = 1024 float4, 256 thr x 4
#pragma unroll
        for (int r = 0; r < 4; r++) {
            int idx = r * 256 + tid;
            int arow = idx >> 3;
            int k4 = idx & 7;
            int grow = row0 + arow;
            float4 v = make_float4(0.f, 0.f, 0.f, 0.f);
            if (grow < n)
                v = *reinterpret_cast<const float4*>(&A[(size_t)grow * 128 + kb + k4 * 4]);
            *reinterpret_cast<float4*>(&sA[arow * 36 + k4 * 4]) = v;
        }
        // load pre-split W tiles: 64 cols x 32 k = 512 uint4 per buffer, 256 thr x 2
#pragma unroll
        for (int r = 0; r < 2; r++) {
            int idx = r * 256 + tid;
            int j = idx >> 3;               // 0..63
            int k4 = idx & 7;               // 0..7
            uint4 vh = *reinterpret_cast<const uint4*>(&Whi[(size_t)(col0 + j) * 128 + kb + k4 * 4]);
            uint4 vl = *reinterpret_cast<const uint4*>(&Wlo[(size_t)(col0 + j) * 128 + kb + k4 * 4]);
            *reinterpret_cast<uint4*>(&sWhi[j * 36 + k4 * 4]) = vh;
            *reinterpret_cast<uint4*>(&sWlo[j * 36 + k4 * 4]) = vl;
        }
        __syncthreads();

#pragma unroll
        for (int ks = 0; ks < 32; ks += 8) {
            // A fragments (2 m-tiles), hi+lo split in registers
            unsigned ah[2][4], al[2][4];
#pragma unroll
            for (int i = 0; i < 2; i++) {
                int rb = m0 + 16 * i;
                float a0 = sA[(rb + group) * 36 + ks + tg];
                float a1 = sA[(rb + group + 8) * 36 + ks + tg];
                float a2 = sA[(rb + group) * 36 + ks + tg + 4];
                float a3 = sA[(rb + group + 8) * 36 + ks + tg + 4];
                ah[i][0] = f2tf32(a0); al[i][0] = f2tf32(a0 - __uint_as_float(ah[i][0]));
                ah[i][1] = f2tf32(a1); al[i][1] = f2tf32(a1 - __uint_as_float(ah[i][1]));
                ah[i][2] = f2tf32(a2); al[i][2] = f2tf32(a2 - __uint_as_float(ah[i][2]));
                ah[i][3] = f2tf32(a3); al[i][3] = f2tf32(a3 - __uint_as_float(ah[i][3]));
            }
            // B fragments straight from pre-split smem (no cvt)
#pragma unroll
            for (int j = 0; j < 4; j++) {
                int base = (n0 + 8 * j + group) * 36 + ks + tg;
                unsigned bh[2], bl[2];
                bh[0] = sWhi[base];
                bh[1] = sWhi[base + 4];
                bl[0] = sWlo[base];
                bl[1] = sWlo[base + 4];
#pragma unroll
                for (int i = 0; i < 2; i++) {
                    mma_tf32(acc[i][j], ah[i], bh);   // hi*hi
                    mma_tf32(acc[i][j], ah[i], bl);   // hi*lo
                    mma_tf32(acc[i][j], al[i], bh);   // lo*hi
                }
            }
        }
        __syncthreads();
    }

    // epilogue: + bias, store
#pragma unroll
    for (int j = 0; j < 4; j++) {
        int col = col0 + n0 + 8 * j + 2 * tg;
        float b0 = bias[col];
        float b1 = bias[col + 1];
#pragma unroll
        for (int i = 0; i < 2; i++) {
            int r_lo = row0 + m0 + 16 * i + group;
            int r_hi = r_lo + 8;
            if (r_lo < n) {
                float2 v = make_float2(acc[i][j][0] + b0, acc[i][j][1] + b1);
                *reinterpret_cast<float2*>(&g_hl[(size_t)r_lo * 128 + col]) = v;
            }
            if (r_hi < n) {
                float2 v = make_float2(acc[i][j][2] + b0, acc[i][j][3] + b1);
                *reinterpret_cast<float2*>(&g_hl[(size_t)r_hi * 128 + col]) = v;
            }
        }
    }
}

// ---------------- fused per-node layer kernel ----------------
__global__ __launch_bounds__(256) void k_layer(const float* __restrict__ rootl,
                                               const float* __restrict__ gammal,
                                               const float* __restrict__ betal,
                                               const float* __restrict__ meanl,
                                               const float* __restrict__ varl,
                                               float* __restrict__ out, int do_relu) {
    const int warp = (blockIdx.x * blockDim.x + threadIdx.x) >> 5;
    const int lane = threadIdx.x & 31;
    if (warp >= NN) return;
    const int i = warp;
    const int c4 = lane * 4;

    float4 h4 = *reinterpret_cast<const float4*>(&g_hl[(size_t)i * 128 + c4]);
    float4 r4 = *reinterpret_cast<const float4*>(&rootl[c4]);
    const float rd = g_rdeg[i];
    float ax = fmaxf(h4.x + r4.x, 0.f) * rd;
    float ay = fmaxf(h4.y + r4.y, 0.f) * rd;
    float az = fmaxf(h4.z + r4.z, 0.f) * rd;
    float aw = fmaxf(h4.w + r4.w, 0.f) * rd;

    const int s = g_start[i];
    const int e_end = g_start[i + 1];
    const unsigned sh = (lane & 3) * 8;
    const int wsel = lane >> 2;

    if (s < e_end) {
        // 1-ahead prefetch of the uniform per-edge data
        int2 rn = g_csr_rn[s];
        unsigned w = g_pk_csr[(size_t)s * 8 + wsel];
        for (int p = s; p < e_end; p++) {
            int2 rn_cur = rn;
            unsigned w_cur = w;
            if (p + 1 < e_end) {
                rn = g_csr_rn[p + 1];
                w = g_pk_csr[(size_t)(p + 1) * 8 + wsel];
            }
            float nm = __int_as_float(rn_cur.y);
            unsigned byte = (w_cur >> sh) & 0xFFu;
            float4 hv = *reinterpret_cast<const float4*>(&g_hl[(size_t)rn_cur.x * 128 + c4]);
            ax += fmaxf(hv.x + (float)(byte & 3u), 0.f) * nm;
            ay += fmaxf(hv.y + (float)((byte >> 2) & 3u), 0.f) * nm;
            az += fmaxf(hv.z + (float)((byte >> 4) & 3u), 0.f) * nm;
            aw += fmaxf(hv.w + (float)((byte >> 6) & 3u), 0.f) * nm;
        }
    }

    float4 g4 = *reinterpret_cast<const float4*>(&gammal[c4]);
    float4 b4 = *reinterpret_cast<const float4*>(&betal[c4]);
    float4 m4 = *reinterpret_cast<const float4*>(&meanl[c4]);
    float4 v4 = *reinterpret_cast<const float4*>(&varl[c4]);
    float sx = g4.x * rsqrtf(v4.x + BN_EPS);
    float sy = g4.y * rsqrtf(v4.y + BN_EPS);
    float sz = g4.z * rsqrtf(v4.z + BN_EPS);
    float sw = g4.w * rsqrtf(v4.w + BN_EPS);
    float4 o;
    o.x = ax * sx + (b4.x - m4.x * sx);
    o.y = ay * sy + (b4.y - m4.y * sy);
    o.z = az * sz + (b4.z - m4.z * sz);
    o.w = aw * sw + (b4.w - m4.w * sw);
    if (do_relu) {
        o.x = fmaxf(o.x, 0.f);
        o.y = fmaxf(o.y, 0.f);
        o.z = fmaxf(o.z, 0.f);
        o.w = fmaxf(o.w, 0.f);
    }
    *reinterpret_cast<float4*>(&out[(size_t)i * 128 + c4]) = o;
}

// ---------------- launcher ----------------
extern "C" void kernel_launch(void* const* d_in, const int* in_sizes, int n_in,
                              void* d_out, int out_size) {
    (void)in_sizes; (void)n_in; (void)out_size;
    const float* x    = (const float*)d_in[0];
    const int*   ei   = (const int*)d_in[1];     // int32 (JAX default, not x64)
    const int*   ea   = (const int*)d_in[2];
    const float* W    = (const float*)d_in[3];
    const float* b    = (const float*)d_in[4];
    const float* root = (const float*)d_in[5];
    const float* gam  = (const float*)d_in[6];
    const float* bet  = (const float*)d_in[7];
    const float* mean = (const float*)d_in[8];
    const float* var  = (const float*)d_in[9];
    float* out = (float*)d_out;

    // one-time setup (outside capture on the first/correctness call)
    static cudaStream_t s2 = nullptr;
    static cudaEvent_t ev_fork = nullptr, ev_join = nullptr;
    static bool init_done = false;
    if (!init_done) {
        cudaFuncSetAttribute(k_gemm, cudaFuncAttributeMaxDynamicSharedMemorySize,
                             GEMM_SMEM_BYTES);
        cudaStreamCreateWithFlags(&s2, cudaStreamNonBlocking);
        cudaEventCreateWithFlags(&ev_fork, cudaEventDisableTiming);
        cudaEventCreateWithFlags(&ev_join, cudaEventDisableTiming);
        init_done = true;
    }

    unsigned* whi_p = nullptr;
    unsigned* wlo_p = nullptr;
    cudaGetSymbolAddress((void**)&whi_p, g_Whi);
    cudaGetSymbolAddress((void**)&wlo_p, g_Wlo);

    const int gemm_blocks = 2 * ((NN + 127) / 128);   // 128x64 tiles
    const int layer_blocks = (NN * 32 + 255) / 256;

    // fork: gemm0 + pack (depend only on x/W/ea) run on s2 concurrent with prep chain
    k_splitW<<<(5 * 128 * 128 + 255) / 256, 256>>>(W);                    // idx 0
    cudaEventRecord(ev_fork, 0);
    cudaStreamWaitEvent(s2, ev_fork, 0);
    k_zero<<<(NN + 255) / 256, 256>>>();                                  // idx 1 (s0)
    k_deg<<<(EE + 255) / 256, 256>>>(ei);                                 // idx 2 (s0)
    k_gemm<<<gemm_blocks, 256, GEMM_SMEM_BYTES, s2>>>(x, whi_p, wlo_p, b, NN); // idx 3 <- ncu
    k_pack<<<(EE * 8 + 255) / 256, 256, 0, s2>>>(ea);                     // (s2)
    cudaEventRecord(ev_join, s2);
    k_scanA<<<NB_SCAN, 1024>>>();                                         // (s0)
    k_scanB<<<1, 128>>>();                                                // (s0)
    k_scanC<<<NB_SCAN, 1024>>>();                                         // (s0)
    cudaStreamWaitEvent(0, ev_join, 0);
    k_scatter<<<(EE + 255) / 256, 256>>>();                               // (s0)
    k_layer<<<layer_blocks, 256>>>(root, gam, bet, mean, var, out, 1);    // layer 0

    for (int l = 1; l < 5; l++) {
        k_gemm<<<gemm_blocks, 256, GEMM_SMEM_BYTES>>>(
            out, whi_p + (size_t)l * 128 * 128, wlo_p + (size_t)l * 128 * 128,
            b + (size_t)l * 128, NN);
        k_layer<<<layer_blocks, 256>>>(root + (size_t)l * 128,
                                       gam + (size_t)l * 128, bet + (size_t)l * 128,
                                       mean + (size_t)l * 128, var + (size_t)l * 128,
                                       out, (l < 4) ? 1 : 0);
    }
}

// round 10
// speedup vs baseline: 3.3862x; 1.2049x over previous
#include <cuda_runtime.h>
#include <cstdint>

#define NN 100000
#define EE 600000
#define DD 128
#define BN_EPS 1e-5f
#define NB_SCAN 100          // scan blocks, 1000 elems each
// sAhi/sAlo u32 [128][36] + sWhi/sWlo u32 [64][36]
#define GEMM_SMEM_BYTES ((2 * 128 * 36 + 2 * 64 * 36) * 4)

// ---------------- scratch (static device globals; no runtime alloc) ----------------
__device__ __align__(16) float    g_hl  [(size_t)NN * DD];   // 51.2 MB
__device__ __align__(16) unsigned g_pk  [(size_t)EE * 8];    // edge-order packed attrs
__device__ __align__(16) unsigned g_pk_csr[(size_t)EE * 8];  // CSR-order packed attrs
__device__ __align__(16) int      g_row [EE];
__device__ __align__(16) int      g_col [EE];
__device__ __align__(16) float    g_deg [NN];
__device__ __align__(16) float    g_dinv[NN];
__device__ __align__(16) float    g_rdeg[NN];
// CSR by target (col)
__device__ __align__(16) int      g_cnt   [NN];
__device__ __align__(16) int      g_cursor[NN];
__device__ __align__(16) int      g_start [NN + 1];
__device__ __align__(16) int2     g_csr_rn[EE];              // {row, norm bits}
__device__ __align__(16) int      g_bsum[NB_SCAN];
__device__ __align__(16) int      g_boff[NB_SCAN];
// pre-split W as packed bf16x2 pairs (hi/lo), all 5 layers: [5*128][64] u32
__device__ __align__(16) unsigned g_Whi[5 * 128 * 64];
__device__ __align__(16) unsigned g_Wlo[5 * 128 * 64];

// ---------------- bf16 helpers ----------------
// pack two f32 into bf16x2: result = {hi: a_odd, lo: a_even}
__device__ __forceinline__ unsigned pack_bf16x2(float odd, float even) {
    unsigned r;
    asm("cvt.rn.bf16x2.f32 %0, %1, %2;" : "=r"(r) : "f"(odd), "f"(even));
    return r;
}
__device__ __forceinline__ float bf16lo_f32(unsigned u) {
    return __uint_as_float(u << 16);
}
__device__ __forceinline__ float bf16hi_f32(unsigned u) {
    return __uint_as_float(u & 0xFFFF0000u);
}
__device__ __forceinline__ void mma_bf16(float* c, const unsigned* a, const unsigned* b) {
    asm volatile(
        "mma.sync.aligned.m16n8k16.row.col.f32.bf16.bf16.f32 "
        "{%0,%1,%2,%3}, {%4,%5,%6,%7}, {%8,%9}, {%0,%1,%2,%3};"
        : "+f"(c[0]), "+f"(c[1]), "+f"(c[2]), "+f"(c[3])
        : "r"(a[0]), "r"(a[1]), "r"(a[2]), "r"(a[3]), "r"(b[0]), "r"(b[1]));
}

// ---------------- prep kernels ----------------
__global__ void k_zero() {
    int i = blockIdx.x * blockDim.x + threadIdx.x;
    if (i < NN) {
        g_deg[i] = 0.0f;
        g_cnt[i] = 0;
        g_cursor[i] = 0;
    }
}

// edge_index is int32 (JAX default config). Clamp defensively.
__global__ void k_deg(const int* __restrict__ ei) {
    int e = blockIdx.x * blockDim.x + threadIdx.x;
    if (e < EE) {
        int r = ei[e];
        int c = ei[EE + e];
        r = (r < 0) ? 0 : ((r >= NN) ? NN - 1 : r);
        c = (c < 0) ? 0 : ((c >= NN) ? NN - 1 : c);
        g_row[e] = r;
        g_col[e] = c;
        atomicAdd(&g_deg[r], 1.0f);        // out-degree (reference's deg)
        atomicAdd(&g_cnt[c], 1);           // in-degree for CSR
    }
}

// split all 5 layers' W into packed bf16x2 hi/lo pairs once per launch
__global__ void k_splitW(const float* __restrict__ W) {
    int idx = blockIdx.x * blockDim.x + threadIdx.x;   // over 5*128*64 pairs
    if (idx < 5 * 128 * 64) {
        int j = idx >> 6;        // global row (layer*128 + out-col)
        int kp = idx & 63;       // k-pair index
        float w0 = W[(size_t)j * 128 + 2 * kp];
        float w1 = W[(size_t)j * 128 + 2 * kp + 1];
        unsigned hi = pack_bf16x2(w1, w0);
        float r0 = w0 - bf16lo_f32(hi);
        float r1 = w1 - bf16hi_f32(hi);
        g_Whi[idx] = hi;
        g_Wlo[idx] = pack_bf16x2(r1, r0);
    }
}

// scan pass A: per-chunk block sums of g_cnt; also finish deg -> dinv/rdeg
__global__ __launch_bounds__(1024) void k_scanA() {
    __shared__ int red[1024];
    const int b = blockIdx.x, t = threadIdx.x;
    const int i = b * 1000 + t;
    int v = 0;
    if (t < 1000 && i < NN) {
        v = g_cnt[i];
        float d = g_deg[i] + 1.0f;
        g_dinv[i] = rsqrtf(d);
        g_rdeg[i] = 1.0f / d;
    }
    red[t] = v;
    __syncthreads();
    for (int s = 512; s > 0; s >>= 1) {
        if (t < s) red[t] += red[t + s];
        __syncthreads();
    }
    if (t == 0) g_bsum[b] = red[0];
}

// scan pass B: exclusive scan of the 100 block sums
__global__ void k_scanB() {
    __shared__ int s[128];
    const int t = threadIdx.x;
    int v = (t < NB_SCAN) ? g_bsum[t] : 0;
    s[t] = v;
    __syncthreads();
    for (int d = 1; d < 128; d <<= 1) {
        int add = (t >= d) ? s[t - d] : 0;
        __syncthreads();
        s[t] += add;
        __syncthreads();
    }
    if (t < NB_SCAN) g_boff[t] = s[t] - v;
    if (t == 0) g_start[NN] = EE;
}

// scan pass C: per-chunk exclusive scan + block offset -> g_start
__global__ __launch_bounds__(1024) void k_scanC() {
    __shared__ int s[2][1024];
    const int b = blockIdx.x, t = threadIdx.x;
    const int i = b * 1000 + t;
    const int v = (t < 1000 && i < NN) ? g_cnt[i] : 0;
    int cur = 0;
    s[0][t] = v;
    __syncthreads();
    for (int d = 1; d < 1024; d <<= 1) {
        int nxt = cur ^ 1;
        s[nxt][t] = s[cur][t] + ((t >= d) ? s[cur][t - d] : 0);
        __syncthreads();
        cur = nxt;
    }
    if (t < 1000 && i < NN) g_start[i] = g_boff[b] + s[cur][t] - v;
}

// pack 16 consecutive int32 attr values (each 0..3) into one uint32
__global__ void k_pack(const int* __restrict__ ea) {
    int idx = blockIdx.x * blockDim.x + threadIdx.x;   // word index over EE*8
    if (idx < EE * 8) {
        const int4* p4 = reinterpret_cast<const int4*>(ea + (size_t)idx * 16);
        unsigned w = 0;
        int4 a = p4[0], b = p4[1], c = p4[2], d = p4[3];
        w |= ((unsigned)a.x & 3u) << 0;  w |= ((unsigned)a.y & 3u) << 2;
        w |= ((unsigned)a.z & 3u) << 4;  w |= ((unsigned)a.w & 3u) << 6;
        w |= ((unsigned)b.x & 3u) << 8;  w |= ((unsigned)b.y & 3u) << 10;
        w |= ((unsigned)b.z & 3u) << 12; w |= ((unsigned)b.w & 3u) << 14;
        w |= ((unsigned)c.x & 3u) << 16; w |= ((unsigned)c.y & 3u) << 18;
        w |= ((unsigned)c.z & 3u) << 20; w |= ((unsigned)c.w & 3u) << 22;
        w |= ((unsigned)d.x & 3u) << 24; w |= ((unsigned)d.y & 3u) << 26;
        w |= ((unsigned)d.z & 3u) << 28; w |= ((unsigned)d.w & 3u) << 30;
        g_pk[idx] = w;
    }
}

// scatter edges into CSR-by-col: packed (row, norm) + pk words in CSR order
__global__ void k_scatter() {
    int e = blockIdx.x * blockDim.x + threadIdx.x;
    if (e < EE) {
        int r = g_row[e];
        int c = g_col[e];
        int pos = atomicAdd(&g_cursor[c], 1);
        int idx = g_start[c] + pos;
        int2 rn;
        rn.x = r;
        rn.y = __float_as_int(g_dinv[r] * g_dinv[c]);
        g_csr_rn[idx] = rn;
        const uint4* src = reinterpret_cast<const uint4*>(&g_pk[(size_t)e * 8]);
        uint4* dst = reinterpret_cast<uint4*>(&g_pk_csr[(size_t)idx * 8]);
        dst[0] = src[0];
        dst[1] = src[1];
    }
}

// ---------------- GEMM (bf16 m16n8k16 tc, 3-term split): g_hl = A@W^T + bias ----------
// block 256 thr (8 warps), tile 128x64, K-chunk 64. warp tile 32x32 (4m x 2n warps).
// A split to bf16x2 hi/lo during smem load; W pre-split in global. Zero cvt in hot loop.
// smem pitch 36 u32 -> conflict-free fragment LDS (group*36+tg covers 32 banks).
__global__ __launch_bounds__(256, 3) void k_gemm(const float* __restrict__ A,
                                                 const unsigned* __restrict__ Whi,
                                                 const unsigned* __restrict__ Wlo,
                                                 const float* __restrict__ bias,
                                                 int n) {
    extern __shared__ __align__(16) unsigned smem_dyn[];
    unsigned* sAhi = smem_dyn;                 // [128][36] (32 kp used)
    unsigned* sAlo = sAhi + 128 * 36;
    unsigned* sWhi = sAlo + 128 * 36;          // [64][36]
    unsigned* sWlo = sWhi + 64 * 36;

    const int tid = threadIdx.x;
    const int lane = tid & 31;
    const int warp = tid >> 5;
    const int group = lane >> 2;     // 0..7
    const int tg = lane & 3;         // 0..3
    const int m0 = (warp & 3) * 32;  // warp row offset in tile
    const int n0 = (warp >> 2) * 32; // warp col offset in tile
    const int row0 = (blockIdx.x >> 1) * 128;
    const int col0 = (blockIdx.x & 1) * 64;

    float acc[2][4][4];
#pragma unroll
    for (int i = 0; i < 2; i++)
#pragma unroll
        for (int j = 0; j < 4; j++)
#pragma unroll
            for (int q = 0; q < 4; q++) acc[i][j][q] = 0.0f;

    for (int kb = 0; kb < 128; kb += 64) {
        const int kpb = kb >> 1;     // k-pair base
        // load A tile (128 rows x 64 k = 2048 float4), split to bf16x2 hi/lo
#pragma unroll
        for (int r = 0; r < 8; r++) {
            int idx = r * 256 + tid;
            int arow = idx >> 4;            // 0..127
            int k4 = idx & 15;              // float4 index: k = kb + 4*k4
            int grow = row0 + arow;
            float4 v = make_float4(0.f, 0.f, 0.f, 0.f);
            if (grow < n)
                v = *reinterpret_cast<const float4*>(&A[(size_t)grow * 128 + kb + k4 * 4]);
            unsigned h01 = pack_bf16x2(v.y, v.x);
            unsigned h23 = pack_bf16x2(v.w, v.z);
            float f0 = bf16lo_f32(h01), f1 = bf16hi_f32(h01);
            float f2 = bf16lo_f32(h23), f3 = bf16hi_f32(h23);
            unsigned l01 = pack_bf16x2(v.y - f1, v.x - f0);
            unsigned l23 = pack_bf16x2(v.w - f3, v.z - f2);
            uint2 hv = make_uint2(h01, h23);
            uint2 lv = make_uint2(l01, l23);
            *reinterpret_cast<uint2*>(&sAhi[arow * 36 + 2 * k4]) = hv;
            *reinterpret_cast<uint2*>(&sAlo[arow * 36 + 2 * k4]) = lv;
        }
        // load pre-split W tiles: 64 rows x 32 kp = 512 uint4 per buffer
#pragma unroll
        for (int r = 0; r < 2; r++) {
            int idx = r * 256 + tid;
            int j = idx >> 3;               // 0..63
            int q = idx & 7;                // kp = 4q (0..28)
            uint4 vh = *reinterpret_cast<const uint4*>(&Whi[(size_t)(col0 + j) * 64 + kpb + 4 * q]);
            uint4 vl = *reinterpret_cast<const uint4*>(&Wlo[(size_t)(col0 + j) * 64 + kpb + 4 * q]);
            *reinterpret_cast<uint4*>(&sWhi[j * 36 + 4 * q]) = vh;
            *reinterpret_cast<uint4*>(&sWlo[j * 36 + 4 * q]) = vl;
        }
        __syncthreads();

#pragma unroll
        for (int ks = 0; ks < 64; ks += 16) {
            const int kp0 = ks >> 1;        // 0,8,16,24
            unsigned ah[2][4], al[2][4];
#pragma unroll
            for (int i = 0; i < 2; i++) {
                int rb = m0 + 16 * i;
                int ra = (rb + group) * 36 + kp0 + tg;
                int rc = (rb + group + 8) * 36 + kp0 + tg;
                ah[i][0] = sAhi[ra];
                ah[i][1] = sAhi[rc];
                ah[i][2] = sAhi[ra + 4];
                ah[i][3] = sAhi[rc + 4];
                al[i][0] = sAlo[ra];
                al[i][1] = sAlo[rc];
                al[i][2] = sAlo[ra + 4];
                al[i][3] = sAlo[rc + 4];
            }
#pragma unroll
            for (int j = 0; j < 4; j++) {
                int base = (n0 + 8 * j + group) * 36 + kp0 + tg;
                unsigned bh[2], bl[2];
                bh[0] = sWhi[base];
                bh[1] = sWhi[base + 4];
                bl[0] = sWlo[base];
                bl[1] = sWlo[base + 4];
#pragma unroll
                for (int i = 0; i < 2; i++) {
                    mma_bf16(acc[i][j], ah[i], bh);   // hi*hi
                    mma_bf16(acc[i][j], ah[i], bl);   // hi*lo
                    mma_bf16(acc[i][j], al[i], bh);   // lo*hi
                }
            }
        }
        __syncthreads();
    }

    // epilogue: + bias, store (c layout same as m16n8k8: rows group/group+8, cols 2tg,2tg+1)
#pragma unroll
    for (int j = 0; j < 4; j++) {
        int col = col0 + n0 + 8 * j + 2 * tg;
        float b0 = bias[col];
        float b1 = bias[col + 1];
#pragma unroll
        for (int i = 0; i < 2; i++) {
            int r_lo = row0 + m0 + 16 * i + group;
            int r_hi = r_lo + 8;
            if (r_lo < n) {
                float2 v = make_float2(acc[i][j][0] + b0, acc[i][j][1] + b1);
                *reinterpret_cast<float2*>(&g_hl[(size_t)r_lo * 128 + col]) = v;
            }
            if (r_hi < n) {
                float2 v = make_float2(acc[i][j][2] + b0, acc[i][j][3] + b1);
                *reinterpret_cast<float2*>(&g_hl[(size_t)r_hi * 128 + col]) = v;
            }
        }
    }
}

// ---------------- fused per-node layer kernel ----------------
__global__ __launch_bounds__(256) void k_layer(const float* __restrict__ rootl,
                                               const float* __restrict__ gammal,
                                               const float* __restrict__ betal,
                                               const float* __restrict__ meanl,
                                               const float* __restrict__ varl,
                                               float* __restrict__ out, int do_relu) {
    const int warp = (blockIdx.x * blockDim.x + threadIdx.x) >> 5;
    const int lane = threadIdx.x & 31;
    if (warp >= NN) return;
    const int i = warp;
    const int c4 = lane * 4;

    float4 h4 = *reinterpret_cast<const float4*>(&g_hl[(size_t)i * 128 + c4]);
    float4 r4 = *reinterpret_cast<const float4*>(&rootl[c4]);
    const float rd = g_rdeg[i];
    float ax = fmaxf(h4.x + r4.x, 0.f) * rd;
    float ay = fmaxf(h4.y + r4.y, 0.f) * rd;
    float az = fmaxf(h4.z + r4.z, 0.f) * rd;
    float aw = fmaxf(h4.w + r4.w, 0.f) * rd;

    const int s = g_start[i];
    const int e_end = g_start[i + 1];
    const unsigned sh = (lane & 3) * 8;
    const int wsel = lane >> 2;

    if (s < e_end) {
        // 1-ahead prefetch of the uniform per-edge data
        int2 rn = g_csr_rn[s];
        unsigned w = g_pk_csr[(size_t)s * 8 + wsel];
        for (int p = s; p < e_end; p++) {
            int2 rn_cur = rn;
            unsigned w_cur = w;
            if (p + 1 < e_end) {
                rn = g_csr_rn[p + 1];
                w = g_pk_csr[(size_t)(p + 1) * 8 + wsel];
            }
            float nm = __int_as_float(rn_cur.y);
            unsigned byte = (w_cur >> sh) & 0xFFu;
            float4 hv = *reinterpret_cast<const float4*>(&g_hl[(size_t)rn_cur.x * 128 + c4]);
            ax += fmaxf(hv.x + (float)(byte & 3u), 0.f) * nm;
            ay += fmaxf(hv.y + (float)((byte >> 2) & 3u), 0.f) * nm;
            az += fmaxf(hv.z + (float)((byte >> 4) & 3u), 0.f) * nm;
            aw += fmaxf(hv.w + (float)((byte >> 6) & 3u), 0.f) * nm;
        }
    }

    float4 g4 = *reinterpret_cast<const float4*>(&gammal[c4]);
    float4 b4 = *reinterpret_cast<const float4*>(&betal[c4]);
    float4 m4 = *reinterpret_cast<const float4*>(&meanl[c4]);
    float4 v4 = *reinterpret_cast<const float4*>(&varl[c4]);
    float sx = g4.x * rsqrtf(v4.x + BN_EPS);
    float sy = g4.y * rsqrtf(v4.y + BN_EPS);
    float sz = g4.z * rsqrtf(v4.z + BN_EPS);
    float sw = g4.w * rsqrtf(v4.w + BN_EPS);
    float4 o;
    o.x = ax * sx + (b4.x - m4.x * sx);
    o.y = ay * sy + (b4.y - m4.y * sy);
    o.z = az * sz + (b4.z - m4.z * sz);
    o.w = aw * sw + (b4.w - m4.w * sw);
    if (do_relu) {
        o.x = fmaxf(o.x, 0.f);
        o.y = fmaxf(o.y, 0.f);
        o.z = fmaxf(o.z, 0.f);
        o.w = fmaxf(o.w, 0.f);
    }
    *reinterpret_cast<float4*>(&out[(size_t)i * 128 + c4]) = o;
}

// ---------------- launcher ----------------
extern "C" void kernel_launch(void* const* d_in, const int* in_sizes, int n_in,
                              void* d_out, int out_size) {
    (void)in_sizes; (void)n_in; (void)out_size;
    const float* x    = (const float*)d_in[0];
    const int*   ei   = (const int*)d_in[1];     // int32 (JAX default, not x64)
    const int*   ea   = (const int*)d_in[2];
    const float* W    = (const float*)d_in[3];
    const float* b    = (const float*)d_in[4];
    const float* root = (const float*)d_in[5];
    const float* gam  = (const float*)d_in[6];
    const float* bet  = (const float*)d_in[7];
    const float* mean = (const float*)d_in[8];
    const float* var  = (const float*)d_in[9];
    float* out = (float*)d_out;

    // one-time setup (outside capture on the first/correctness call)
    static cudaStream_t s2 = nullptr;
    static cudaEvent_t ev_fork = nullptr, ev_join = nullptr;
    static bool init_done = false;
    if (!init_done) {
        cudaFuncSetAttribute(k_gemm, cudaFuncAttributeMaxDynamicSharedMemorySize,
                             GEMM_SMEM_BYTES);
        cudaStreamCreateWithFlags(&s2, cudaStreamNonBlocking);
        cudaEventCreateWithFlags(&ev_fork, cudaEventDisableTiming);
        cudaEventCreateWithFlags(&ev_join, cudaEventDisableTiming);
        init_done = true;
    }

    unsigned* whi_p = nullptr;
    unsigned* wlo_p = nullptr;
    cudaGetSymbolAddress((void**)&whi_p, g_Whi);
    cudaGetSymbolAddress((void**)&wlo_p, g_Wlo);

    const int gemm_blocks = 2 * ((NN + 127) / 128);   // 128x64 tiles
    const int layer_blocks = (NN * 32 + 255) / 256;

    // fork: gemm0 + pack (depend only on x/W/ea) run on s2 concurrent with prep chain
    k_splitW<<<(5 * 128 * 64 + 255) / 256, 256>>>(W);                     // idx 0
    cudaEventRecord(ev_fork, 0);
    cudaStreamWaitEvent(s2, ev_fork, 0);
    k_zero<<<(NN + 255) / 256, 256>>>();                                  // idx 1 (s0)
    k_deg<<<(EE + 255) / 256, 256>>>(ei);                                 // idx 2 (s0)
    k_gemm<<<gemm_blocks, 256, GEMM_SMEM_BYTES, s2>>>(x, whi_p, wlo_p, b, NN); // idx 3 <- ncu
    k_pack<<<(EE * 8 + 255) / 256, 256, 0, s2>>>(ea);                     // (s2)
    cudaEventRecord(ev_join, s2);
    k_scanA<<<NB_SCAN, 1024>>>();                                         // (s0)
    k_scanB<<<1, 128>>>();                                                // (s0)
    k_scanC<<<NB_SCAN, 1024>>>();                                         // (s0)
    cudaStreamWaitEvent(0, ev_join, 0);
    k_scatter<<<(EE + 255) / 256, 256>>>();                               // (s0)
    k_layer<<<layer_blocks, 256>>>(root, gam, bet, mean, var, out, 1);    // layer 0

    for (int l = 1; l < 5; l++) {
        k_gemm<<<gemm_blocks, 256, GEMM_SMEM_BYTES>>>(
            out, whi_p + (size_t)l * 128 * 64, wlo_p + (size_t)l * 128 * 64,
            b + (size_t)l * 128, NN);
        k_layer<<<layer_blocks, 256>>>(root + (size_t)l * 128,
                                       gam + (size_t)l * 128, bet + (size_t)l * 128,
                                       mean + (size_t)l * 128, var + (size_t)l * 128,
                                       out, (l < 4) ? 1 : 0);
    }
}

// round 12
// speedup vs baseline: 3.4557x; 1.0205x over previous
#include <cuda_runtime.h>
#include <cstdint>

#define NN 100000
#define EE 600000
#define DD 128
#define BN_EPS 1e-5f
#define NB_SCAN 100          // scan blocks, 1000 elems each
// sAhi/sAlo u32 [128][36] + sWhi/sWlo u32 [64][36]
#define GEMM_SMEM_BYTES ((2 * 128 * 36 + 2 * 64 * 36) * 4)

// ---------------- scratch (static device globals; no runtime alloc) ----------------
__device__ __align__(16) float    g_hl  [(size_t)NN * DD];   // 51.2 MB
__device__ __align__(16) unsigned g_pk  [(size_t)EE * 8];    // edge-order packed attrs
__device__ __align__(16) unsigned g_pk_csr[(size_t)EE * 8];  // CSR-order packed attrs
__device__ __align__(16) int      g_row [EE];
__device__ __align__(16) int      g_col [EE];
__device__ __align__(16) float    g_deg [NN];
__device__ __align__(16) float    g_dinv[NN];
__device__ __align__(16) float    g_rdeg[NN];
// CSR by target (col)
__device__ __align__(16) int      g_cnt   [NN];
__device__ __align__(16) int      g_cursor[NN];
__device__ __align__(16) int      g_start [NN + 1];
__device__ __align__(16) int2     g_csr_rn[EE];              // {row, norm bits}
__device__ __align__(16) int      g_bsum[NB_SCAN];
__device__ __align__(16) int      g_boff[NB_SCAN];
// pre-split W as packed bf16x2 pairs (hi/lo), all 5 layers: [5*128][64] u32
__device__ __align__(16) unsigned g_Whi[5 * 128 * 64];
__device__ __align__(16) unsigned g_Wlo[5 * 128 * 64];

// ---------------- bf16 helpers ----------------
__device__ __forceinline__ unsigned pack_bf16x2(float odd, float even) {
    unsigned r;
    asm("cvt.rn.bf16x2.f32 %0, %1, %2;" : "=r"(r) : "f"(odd), "f"(even));
    return r;
}
__device__ __forceinline__ float bf16lo_f32(unsigned u) {
    return __uint_as_float(u << 16);
}
__device__ __forceinline__ float bf16hi_f32(unsigned u) {
    return __uint_as_float(u & 0xFFFF0000u);
}
__device__ __forceinline__ void mma_bf16(float* c, const unsigned* a, const unsigned* b) {
    asm volatile(
        "mma.sync.aligned.m16n8k16.row.col.f32.bf16.bf16.f32 "
        "{%0,%1,%2,%3}, {%4,%5,%6,%7}, {%8,%9}, {%0,%1,%2,%3};"
        : "+f"(c[0]), "+f"(c[1]), "+f"(c[2]), "+f"(c[3])
        : "r"(a[0]), "r"(a[1]), "r"(a[2]), "r"(a[3]), "r"(b[0]), "r"(b[1]));
}
__device__ __forceinline__ void ldsm_x4(unsigned* r, unsigned addr) {
    asm volatile("ldmatrix.sync.aligned.m8n8.x4.shared.b16 {%0,%1,%2,%3}, [%4];"
                 : "=r"(r[0]), "=r"(r[1]), "=r"(r[2]), "=r"(r[3]) : "r"(addr));
}
__device__ __forceinline__ void ldsm_x2(unsigned* r, unsigned addr) {
    asm volatile("ldmatrix.sync.aligned.m8n8.x2.shared.b16 {%0,%1}, [%2];"
                 : "=r"(r[0]), "=r"(r[1]) : "r"(addr));
}

// ---------------- prep kernels ----------------
__global__ void k_zero() {
    int i = blockIdx.x * blockDim.x + threadIdx.x;
    if (i < NN) {
        g_deg[i] = 0.0f;
        g_cnt[i] = 0;
        g_cursor[i] = 0;
    }
}

// edge_index is int32 (JAX default config). Clamp defensively.
__global__ void k_deg(const int* __restrict__ ei) {
    int e = blockIdx.x * blockDim.x + threadIdx.x;
    if (e < EE) {
        int r = ei[e];
        int c = ei[EE + e];
        r = (r < 0) ? 0 : ((r >= NN) ? NN - 1 : r);
        c = (c < 0) ? 0 : ((c >= NN) ? NN - 1 : c);
        g_row[e] = r;
        g_col[e] = c;
        atomicAdd(&g_deg[r], 1.0f);        // out-degree (reference's deg)
        atomicAdd(&g_cnt[c], 1);           // in-degree for CSR
    }
}

// split all 5 layers' W into packed bf16x2 hi/lo pairs once per launch
__global__ void k_splitW(const float* __restrict__ W) {
    int idx = blockIdx.x * blockDim.x + threadIdx.x;   // over 5*128*64 pairs
    if (idx < 5 * 128 * 64) {
        int j = idx >> 6;        // global row (layer*128 + out-col)
        int kp = idx & 63;       // k-pair index
        float w0 = W[(size_t)j * 128 + 2 * kp];
        float w1 = W[(size_t)j * 128 + 2 * kp + 1];
        unsigned hi = pack_bf16x2(w1, w0);
        float r0 = w0 - bf16lo_f32(hi);
        float r1 = w1 - bf16hi_f32(hi);
        g_Whi[idx] = hi;
        g_Wlo[idx] = pack_bf16x2(r1, r0);
    }
}

// scan pass A: per-chunk block sums of g_cnt; also finish deg -> dinv/rdeg
__global__ __launch_bounds__(1024) void k_scanA() {
    __shared__ int red[1024];
    const int b = blockIdx.x, t = threadIdx.x;
    const int i = b * 1000 + t;
    int v = 0;
    if (t < 1000 && i < NN) {
        v = g_cnt[i];
        float d = g_deg[i] + 1.0f;
        g_dinv[i] = rsqrtf(d);
        g_rdeg[i] = 1.0f / d;
    }
    red[t] = v;
    __syncthreads();
    for (int s = 512; s > 0; s >>= 1) {
        if (t < s) red[t] += red[t + s];
        __syncthreads();
    }
    if (t == 0) g_bsum[b] = red[0];
}

// scan pass B: exclusive scan of the 100 block sums
__global__ void k_scanB() {
    __shared__ int s[128];
    const int t = threadIdx.x;
    int v = (t < NB_SCAN) ? g_bsum[t] : 0;
    s[t] = v;
    __syncthreads();
    for (int d = 1; d < 128; d <<= 1) {
        int add = (t >= d) ? s[t - d] : 0;
        __syncthreads();
        s[t] += add;
        __syncthreads();
    }
    if (t < NB_SCAN) g_boff[t] = s[t] - v;
    if (t == 0) g_start[NN] = EE;
}

// scan pass C: per-chunk exclusive scan + block offset -> g_start
__global__ __launch_bounds__(1024) void k_scanC() {
    __shared__ int s[2][1024];
    const int b = blockIdx.x, t = threadIdx.x;
    const int i = b * 1000 + t;
    const int v = (t < 1000 && i < NN) ? g_cnt[i] : 0;
    int cur = 0;
    s[0][t] = v;
    __syncthreads();
    for (int d = 1; d < 1024; d <<= 1) {
        int nxt = cur ^ 1;
        s[nxt][t] = s[cur][t] + ((t >= d) ? s[cur][t - d] : 0);
        __syncthreads();
        cur = nxt;
    }
    if (t < 1000 && i < NN) g_start[i] = g_boff[b] + s[cur][t] - v;
}

// pack 16 consecutive int32 attr values (each 0..3) into one uint32
__global__ void k_pack(const int* __restrict__ ea) {
    int idx = blockIdx.x * blockDim.x + threadIdx.x;   // word index over EE*8
    if (idx < EE * 8) {
        const int4* p4 = reinterpret_cast<const int4*>(ea + (size_t)idx * 16);
        unsigned w = 0;
        int4 a = p4[0], b = p4[1], c = p4[2], d = p4[3];
        w |= ((unsigned)a.x & 3u) << 0;  w |= ((unsigned)a.y & 3u) << 2;
        w |= ((unsigned)a.z & 3u) << 4;  w |= ((unsigned)a.w & 3u) << 6;
        w |= ((unsigned)b.x & 3u) << 8;  w |= ((unsigned)b.y & 3u) << 10;
        w |= ((unsigned)b.z & 3u) << 12; w |= ((unsigned)b.w & 3u) << 14;
        w |= ((unsigned)c.x & 3u) << 16; w |= ((unsigned)c.y & 3u) << 18;
        w |= ((unsigned)c.z & 3u) << 20; w |= ((unsigned)c.w & 3u) << 22;
        w |= ((unsigned)d.x & 3u) << 24; w |= ((unsigned)d.y & 3u) << 26;
        w |= ((unsigned)d.z & 3u) << 28; w |= ((unsigned)d.w & 3u) << 30;
        g_pk[idx] = w;
    }
}

// scatter edges into CSR-by-col: packed (row, norm) + pk words in CSR order
__global__ void k_scatter() {
    int e = blockIdx.x * blockDim.x + threadIdx.x;
    if (e < EE) {
        int r = g_row[e];
        int c = g_col[e];
        int pos = atomicAdd(&g_cursor[c], 1);
        int idx = g_start[c] + pos;
        int2 rn;
        rn.x = r;
        rn.y = __float_as_int(g_dinv[r] * g_dinv[c]);
        g_csr_rn[idx] = rn;
        const uint4* src = reinterpret_cast<const uint4*>(&g_pk[(size_t)e * 8]);
        uint4* dst = reinterpret_cast<uint4*>(&g_pk_csr[(size_t)idx * 8]);
        dst[0] = src[0];
        dst[1] = src[1];
    }
}

// ---------------- GEMM (bf16 m16n8k16 tc, 3-term split, ldmatrix): g_hl = A@W^T + bias -
// block 256 thr (8 warps), tile 128x64, K-chunk 64. warp tile 32x32 (4m x 2n warps).
// A split to bf16x2 hi/lo during smem load; W pre-split in global.
// Fragments loaded via ldmatrix (x4 for A, x2 for B): 12 instr/ks vs 32 LDS.32.
__global__ __launch_bounds__(256, 3) void k_gemm(const float* __restrict__ A,
                                                 const unsigned* __restrict__ Whi,
                                                 const unsigned* __restrict__ Wlo,
                                                 const float* __restrict__ bias,
                                                 int n) {
    extern __shared__ __align__(16) unsigned smem_dyn[];
    unsigned* sAhi = smem_dyn;                 // [128][36] (32 kp used)
    unsigned* sAlo = sAhi + 128 * 36;
    unsigned* sWhi = sAlo + 128 * 36;          // [64][36]
    unsigned* sWlo = sWhi + 64 * 36;

    const int tid = threadIdx.x;
    const int lane = tid & 31;
    const int warp = tid >> 5;
    const int group = lane >> 2;     // 0..7
    const int tg = lane & 3;         // 0..3
    const int m0 = (warp & 3) * 32;  // warp row offset in tile
    const int n0 = (warp >> 2) * 32; // warp col offset in tile
    const int row0 = (blockIdx.x >> 1) * 128;
    const int col0 = (blockIdx.x & 1) * 64;

    // ldmatrix per-lane base addresses (bytes); pitch = 36 u32 = 144 B
    const unsigned aHiB = (unsigned)__cvta_generic_to_shared(sAhi)
                        + (((m0 + (lane & 15)) * 36 + (lane >> 4) * 4) << 2);
    const unsigned aLoB = aHiB + 128 * 36 * 4;
    const unsigned bHiB = (unsigned)__cvta_generic_to_shared(sWhi)
                        + (((n0 + (lane & 7)) * 36 + ((lane >> 3) & 1) * 4) << 2);
    const unsigned bLoB = bHiB + 64 * 36 * 4;

    float acc[2][4][4];
#pragma unroll
    for (int i = 0; i < 2; i++)
#pragma unroll
        for (int j = 0; j < 4; j++)
#pragma unroll
            for (int q = 0; q < 4; q++) acc[i][j][q] = 0.0f;

    for (int kb = 0; kb < 128; kb += 64) {
        const int kpb = kb >> 1;     // k-pair base
        // load A tile (128 rows x 64 k = 2048 float4), split to bf16x2 hi/lo
#pragma unroll
        for (int r = 0; r < 8; r++) {
            int idx = r * 256 + tid;
            int arow = idx >> 4;            // 0..127
            int k4 = idx & 15;              // float4 index: k = kb + 4*k4
            int grow = row0 + arow;
            float4 v = make_float4(0.f, 0.f, 0.f, 0.f);
            if (grow < n)
                v = *reinterpret_cast<const float4*>(&A[(size_t)grow * 128 + kb + k4 * 4]);
            unsigned h01 = pack_bf16x2(v.y, v.x);
            unsigned h23 = pack_bf16x2(v.w, v.z);
            float f0 = bf16lo_f32(h01), f1 = bf16hi_f32(h01);
            float f2 = bf16lo_f32(h23), f3 = bf16hi_f32(h23);
            unsigned l01 = pack_bf16x2(v.y - f1, v.x - f0);
            unsigned l23 = pack_bf16x2(v.w - f3, v.z - f2);
            uint2 hv = make_uint2(h01, h23);
            uint2 lv = make_uint2(l01, l23);
            *reinterpret_cast<uint2*>(&sAhi[arow * 36 + 2 * k4]) = hv;
            *reinterpret_cast<uint2*>(&sAlo[arow * 36 + 2 * k4]) = lv;
        }
        // load pre-split W tiles: 64 rows x 32 kp = 512 uint4 per buffer
#pragma unroll
        for (int r = 0; r < 2; r++) {
            int idx = r * 256 + tid;
            int j = idx >> 3;               // 0..63
            int q = idx & 7;                // kp = 4q (0..28)
            uint4 vh = *reinterpret_cast<const uint4*>(&Whi[(size_t)(col0 + j) * 64 + kpb + 4 * q]);
            uint4 vl = *reinterpret_cast<const uint4*>(&Wlo[(size_t)(col0 + j) * 64 + kpb + 4 * q]);
            *reinterpret_cast<uint4*>(&sWhi[j * 36 + 4 * q]) = vh;
            *reinterpret_cast<uint4*>(&sWlo[j * 36 + 4 * q]) = vl;
        }
        __syncthreads();

#pragma unroll
        for (int ks16 = 0; ks16 < 4; ks16++) {
            const unsigned ko = ks16 * 32;   // kp0*4 bytes = ks16*8*4
            unsigned ah[2][4], al[2][4];
            ldsm_x4(ah[0], aHiB + ko);
            ldsm_x4(ah[1], aHiB + 16 * 144 + ko);
            ldsm_x4(al[0], aLoB + ko);
            ldsm_x4(al[1], aLoB + 16 * 144 + ko);
#pragma unroll
            for (int j = 0; j < 4; j++) {
                unsigned bh[2], bl[2];
                ldsm_x2(bh, bHiB + j * 8 * 144 + ko);
                ldsm_x2(bl, bLoB + j * 8 * 144 + ko);
#pragma unroll
                for (int i = 0; i < 2; i++) {
                    mma_bf16(acc[i][j], ah[i], bh);   // hi*hi
                    mma_bf16(acc[i][j], ah[i], bl);   // hi*lo
                    mma_bf16(acc[i][j], al[i], bh);   // lo*hi
                }
            }
        }
        __syncthreads();
    }

    // epilogue: + bias, store (c layout: rows group/group+8, cols 2tg,2tg+1)
#pragma unroll
    for (int j = 0; j < 4; j++) {
        int col = col0 + n0 + 8 * j + 2 * tg;
        float b0 = bias[col];
        float b1 = bias[col + 1];
#pragma unroll
        for (int i = 0; i < 2; i++) {
            int r_lo = row0 + m0 + 16 * i + group;
            int r_hi = r_lo + 8;
            if (r_lo < n) {
                float2 v = make_float2(acc[i][j][0] + b0, acc[i][j][1] + b1);
                *reinterpret_cast<float2*>(&g_hl[(size_t)r_lo * 128 + col]) = v;
            }
            if (r_hi < n) {
                float2 v = make_float2(acc[i][j][2] + b0, acc[i][j][3] + b1);
                *reinterpret_cast<float2*>(&g_hl[(size_t)r_hi * 128 + col]) = v;
            }
        }
    }
}

// ---------------- fused per-node layer kernel ----------------
__global__ __launch_bounds__(256) void k_layer(const float* __restrict__ rootl,
                                               const float* __restrict__ gammal,
                                               const float* __restrict__ betal,
                                               const float* __restrict__ meanl,
                                               const float* __restrict__ varl,
                                               float* __restrict__ out, int do_relu) {
    const int warp = (blockIdx.x * blockDim.x + threadIdx.x) >> 5;
    const int lane = threadIdx.x & 31;
    if (warp >= NN) return;
    const int i = warp;
    const int c4 = lane * 4;

    float4 h4 = *reinterpret_cast<const float4*>(&g_hl[(size_t)i * 128 + c4]);
    float4 r4 = *reinterpret_cast<const float4*>(&rootl[c4]);
    const float rd = g_rdeg[i];
    float ax = fmaxf(h4.x + r4.x, 0.f) * rd;
    float ay = fmaxf(h4.y + r4.y, 0.f) * rd;
    float az = fmaxf(h4.z + r4.z, 0.f) * rd;
    float aw = fmaxf(h4.w + r4.w, 0.f) * rd;

    const int s = g_start[i];
    const int e_end = g_start[i + 1];
    const unsigned sh = (lane & 3) * 8;
    const int wsel = lane >> 2;

    if (s < e_end) {
        // 1-ahead prefetch of the uniform per-edge data
        int2 rn = g_csr_rn[s];
        unsigned w = g_pk_csr[(size_t)s * 8 + wsel];
        for (int p = s; p < e_end; p++) {
            int2 rn_cur = rn;
            unsigned w_cur = w;
            if (p + 1 < e_end) {
                rn = g_csr_rn[p + 1];
                w = g_pk_csr[(size_t)(p + 1) * 8 + wsel];
            }
            float nm = __int_as_float(rn_cur.y);
            unsigned byte = (w_cur >> sh) & 0xFFu;
            float4 hv = *reinterpret_cast<const float4*>(&g_hl[(size_t)rn_cur.x * 128 + c4]);
            ax += fmaxf(hv.x + (float)(byte & 3u), 0.f) * nm;
            ay += fmaxf(hv.y + (float)((byte >> 2) & 3u), 0.f) * nm;
            az += fmaxf(hv.z + (float)((byte >> 4) & 3u), 0.f) * nm;
            aw += fmaxf(hv.w + (float)((byte >> 6) & 3u), 0.f) * nm;
        }
    }

    float4 g4 = *reinterpret_cast<const float4*>(&gammal[c4]);
    float4 b4 = *reinterpret_cast<const float4*>(&betal[c4]);
    float4 m4 = *reinterpret_cast<const float4*>(&meanl[c4]);
    float4 v4 = *reinterpret_cast<const float4*>(&varl[c4]);
    float sx = g4.x * rsqrtf(v4.x + BN_EPS);
    float sy = g4.y * rsqrtf(v4.y + BN_EPS);
    float sz = g4.z * rsqrtf(v4.z + BN_EPS);
    float sw = g4.w * rsqrtf(v4.w + BN_EPS);
    float4 o;
    o.x = ax * sx + (b4.x - m4.x * sx);
    o.y = ay * sy + (b4.y - m4.y * sy);
    o.z = az * sz + (b4.z - m4.z * sz);
    o.w = aw * sw + (b4.w - m4.w * sw);
    if (do_relu) {
        o.x = fmaxf(o.x, 0.f);
        o.y = fmaxf(o.y, 0.f);
        o.z = fmaxf(o.z, 0.f);
        o.w = fmaxf(o.w, 0.f);
    }
    *reinterpret_cast<float4*>(&out[(size_t)i * 128 + c4]) = o;
}

// ---------------- launcher ----------------
extern "C" void kernel_launch(void* const* d_in, const int* in_sizes, int n_in,
                              void* d_out, int out_size) {
    (void)in_sizes; (void)n_in; (void)out_size;
    const float* x    = (const float*)d_in[0];
    const int*   ei   = (const int*)d_in[1];     // int32 (JAX default, not x64)
    const int*   ea   = (const int*)d_in[2];
    const float* W    = (const float*)d_in[3];
    const float* b    = (const float*)d_in[4];
    const float* root = (const float*)d_in[5];
    const float* gam  = (const float*)d_in[6];
    const float* bet  = (const float*)d_in[7];
    const float* mean = (const float*)d_in[8];
    const float* var  = (const float*)d_in[9];
    float* out = (float*)d_out;

    // one-time setup (outside capture on the first/correctness call)
    static cudaStream_t s2 = nullptr, s3 = nullptr;
    static cudaEvent_t ev_fork = nullptr, ev_gemm = nullptr, ev_pack = nullptr;
    static bool init_done = false;
    if (!init_done) {
        cudaFuncSetAttribute(k_gemm, cudaFuncAttributeMaxDynamicSharedMemorySize,
                             GEMM_SMEM_BYTES);
        cudaStreamCreateWithFlags(&s2, cudaStreamNonBlocking);
        cudaStreamCreateWithFlags(&s3, cudaStreamNonBlocking);
        cudaEventCreateWithFlags(&ev_fork, cudaEventDisableTiming);
        cudaEventCreateWithFlags(&ev_gemm, cudaEventDisableTiming);
        cudaEventCreateWithFlags(&ev_pack, cudaEventDisableTiming);
        init_done = true;
    }

    unsigned* whi_p = nullptr;
    unsigned* wlo_p = nullptr;
    cudaGetSymbolAddress((void**)&whi_p, g_Whi);
    cudaGetSymbolAddress((void**)&wlo_p, g_Wlo);

    const int gemm_blocks = 2 * ((NN + 127) / 128);   // 128x64 tiles
    const int layer_blocks = (NN * 32 + 255) / 256;

    // fork: gemm0 (s2) and pack (s3) run concurrently with the prep chain (s0)
    k_splitW<<<(5 * 128 * 64 + 255) / 256, 256>>>(W);                     // kernel 0
    cudaEventRecord(ev_fork, 0);
    cudaStreamWaitEvent(s2, ev_fork, 0);
    cudaStreamWaitEvent(s3, ev_fork, 0);
    k_zero<<<(NN + 255) / 256, 256>>>();                                  // kernel 1 (s0)
    k_deg<<<(EE + 255) / 256, 256>>>(ei);                                 // kernel 2 (s0)
    k_gemm<<<gemm_blocks, 256, GEMM_SMEM_BYTES, s2>>>(x, whi_p, wlo_p, b, NN); // kernel 3 <- ncu
    k_pack<<<(EE * 8 + 255) / 256, 256, 0, s3>>>(ea);                     // (s3)
    cudaEventRecord(ev_gemm, s2);
    cudaEventRecord(ev_pack, s3);
    k_scanA<<<NB_SCAN, 1024>>>();                                         // (s0)
    k_scanB<<<1, 128>>>();                                                // (s0)
    k_scanC<<<NB_SCAN, 1024>>>();                                         // (s0)
    cudaStreamWaitEvent(0, ev_pack, 0);
    k_scatter<<<(EE + 255) / 256, 256>>>();                               // (s0)
    cudaStreamWaitEvent(0, ev_gemm, 0);
    k_layer<<<layer_blocks, 256>>>(root, gam, bet, mean, var, out, 1);    // layer 0

    for (int l = 1; l < 5; l++) {
        k_gemm<<<gemm_blocks, 256, GEMM_SMEM_BYTES>>>(
            out, whi_p + (size_t)l * 128 * 64, wlo_p + (size_t)l * 128 * 64,
            b + (size_t)l * 128, NN);
        k_layer<<<layer_blocks, 256>>>(root + (size_t)l * 128,
                                       gam + (size_t)l * 128, bet + (size_t)l * 128,
                                       mean + (size_t)l * 128, var + (size_t)l * 128,
                                       out, (l < 4) ? 1 : 0);
    }
}

// round 13
// speedup vs baseline: 3.4803x; 1.0071x over previous
#include <cuda_runtime.h>
#include <cstdint>

#define NN 100000
#define EE 600000
#define DD 128
#define BN_EPS 1e-5f
#define NB_SCAN 100          // scan blocks, 1000 elems each
// sAhi/sAlo u32 [128][36] + sWhi/sWlo u32 [64][36]
#define GEMM_SMEM_BYTES ((2 * 128 * 36 + 2 * 64 * 36) * 4)

// ---------------- scratch (static device globals; no runtime alloc) ----------------
__device__ __align__(16) float    g_hl  [(size_t)NN * DD];   // 51.2 MB
__device__ __align__(16) unsigned g_pk  [(size_t)EE * 8];    // edge-order packed attrs
__device__ __align__(16) unsigned g_pk_csr[(size_t)EE * 8];  // CSR-order packed attrs
__device__ __align__(16) int      g_row [EE];
__device__ __align__(16) int      g_col [EE];
__device__ __align__(16) float    g_deg [NN];
__device__ __align__(16) float    g_dinv[NN];
__device__ __align__(16) float    g_rdeg[NN];
// CSR by target (col)
__device__ __align__(16) int      g_cnt   [NN];
__device__ __align__(16) int      g_cursor[NN];
__device__ __align__(16) int      g_start [NN + 1];
__device__ __align__(16) int2     g_csr_rn[EE];              // {row, norm bits}
__device__ __align__(16) int      g_bsum[NB_SCAN];
__device__ __align__(16) int      g_boff[NB_SCAN];
// pre-split W as packed bf16x2 pairs (hi/lo), all 5 layers: [5*128][64] u32
__device__ __align__(16) unsigned g_Whi[5 * 128 * 64];
__device__ __align__(16) unsigned g_Wlo[5 * 128 * 64];
// pre-split activations (layer outputs) as packed bf16x2 hi/lo: [NN][64] u32
__device__ __align__(16) unsigned g_Ahi[(size_t)NN * 64];
__device__ __align__(16) unsigned g_Alo[(size_t)NN * 64];

// ---------------- bf16 helpers ----------------
__device__ __forceinline__ unsigned pack_bf16x2(float odd, float even) {
    unsigned r;
    asm("cvt.rn.bf16x2.f32 %0, %1, %2;" : "=r"(r) : "f"(odd), "f"(even));
    return r;
}
__device__ __forceinline__ float bf16lo_f32(unsigned u) {
    return __uint_as_float(u << 16);
}
__device__ __forceinline__ float bf16hi_f32(unsigned u) {
    return __uint_as_float(u & 0xFFFF0000u);
}
__device__ __forceinline__ void mma_bf16(float* c, const unsigned* a, const unsigned* b) {
    asm volatile(
        "mma.sync.aligned.m16n8k16.row.col.f32.bf16.bf16.f32 "
        "{%0,%1,%2,%3}, {%4,%5,%6,%7}, {%8,%9}, {%0,%1,%2,%3};"
        : "+f"(c[0]), "+f"(c[1]), "+f"(c[2]), "+f"(c[3])
        : "r"(a[0]), "r"(a[1]), "r"(a[2]), "r"(a[3]), "r"(b[0]), "r"(b[1]));
}
__device__ __forceinline__ void ldsm_x4(unsigned* r, unsigned addr) {
    asm volatile("ldmatrix.sync.aligned.m8n8.x4.shared.b16 {%0,%1,%2,%3}, [%4];"
                 : "=r"(r[0]), "=r"(r[1]), "=r"(r[2]), "=r"(r[3]) : "r"(addr));
}
__device__ __forceinline__ void ldsm_x2(unsigned* r, unsigned addr) {
    asm volatile("ldmatrix.sync.aligned.m8n8.x2.shared.b16 {%0,%1}, [%2];"
                 : "=r"(r[0]), "=r"(r[1]) : "r"(addr));
}

// ---------------- prep kernels ----------------
__global__ void k_zero() {
    int i = blockIdx.x * blockDim.x + threadIdx.x;
    if (i < NN) {
        g_deg[i] = 0.0f;
        g_cnt[i] = 0;
        g_cursor[i] = 0;
    }
}

// edge_index is int32 (JAX default config). Clamp defensively.
__global__ void k_deg(const int* __restrict__ ei) {
    int e = blockIdx.x * blockDim.x + threadIdx.x;
    if (e < EE) {
        int r = ei[e];
        int c = ei[EE + e];
        r = (r < 0) ? 0 : ((r >= NN) ? NN - 1 : r);
        c = (c < 0) ? 0 : ((c >= NN) ? NN - 1 : c);
        g_row[e] = r;
        g_col[e] = c;
        atomicAdd(&g_deg[r], 1.0f);        // out-degree (reference's deg)
        atomicAdd(&g_cnt[c], 1);           // in-degree for CSR
    }
}

// split all 5 layers' W into packed bf16x2 hi/lo pairs once per launch
__global__ void k_splitW(const float* __restrict__ W) {
    int idx = blockIdx.x * blockDim.x + threadIdx.x;   // over 5*128*64 pairs
    if (idx < 5 * 128 * 64) {
        int j = idx >> 6;        // global row (layer*128 + out-col)
        int kp = idx & 63;       // k-pair index
        float w0 = W[(size_t)j * 128 + 2 * kp];
        float w1 = W[(size_t)j * 128 + 2 * kp + 1];
        unsigned hi = pack_bf16x2(w1, w0);
        float r0 = w0 - bf16lo_f32(hi);
        float r1 = w1 - bf16hi_f32(hi);
        g_Whi[idx] = hi;
        g_Wlo[idx] = pack_bf16x2(r1, r0);
    }
}

// scan pass A: per-chunk block sums of g_cnt; also finish deg -> dinv/rdeg
__global__ __launch_bounds__(1024) void k_scanA() {
    __shared__ int red[1024];
    const int b = blockIdx.x, t = threadIdx.x;
    const int i = b * 1000 + t;
    int v = 0;
    if (t < 1000 && i < NN) {
        v = g_cnt[i];
        float d = g_deg[i] + 1.0f;
        g_dinv[i] = rsqrtf(d);
        g_rdeg[i] = 1.0f / d;
    }
    red[t] = v;
    __syncthreads();
    for (int s = 512; s > 0; s >>= 1) {
        if (t < s) red[t] += red[t + s];
        __syncthreads();
    }
    if (t == 0) g_bsum[b] = red[0];
}

// scan pass B: exclusive scan of the 100 block sums
__global__ void k_scanB() {
    __shared__ int s[128];
    const int t = threadIdx.x;
    int v = (t < NB_SCAN) ? g_bsum[t] : 0;
    s[t] = v;
    __syncthreads();
    for (int d = 1; d < 128; d <<= 1) {
        int add = (t >= d) ? s[t - d] : 0;
        __syncthreads();
        s[t] += add;
        __syncthreads();
    }
    if (t < NB_SCAN) g_boff[t] = s[t] - v;
    if (t == 0) g_start[NN] = EE;
}

// scan pass C: per-chunk exclusive scan + block offset -> g_start
__global__ __launch_bounds__(1024) void k_scanC() {
    __shared__ int s[2][1024];
    const int b = blockIdx.x, t = threadIdx.x;
    const int i = b * 1000 + t;
    const int v = (t < 1000 && i < NN) ? g_cnt[i] : 0;
    int cur = 0;
    s[0][t] = v;
    __syncthreads();
    for (int d = 1; d < 1024; d <<= 1) {
        int nxt = cur ^ 1;
        s[nxt][t] = s[cur][t] + ((t >= d) ? s[cur][t - d] : 0);
        __syncthreads();
        cur = nxt;
    }
    if (t < 1000 && i < NN) g_start[i] = g_boff[b] + s[cur][t] - v;
}

// pack 16 consecutive int32 attr values (each 0..3) into one uint32
__global__ void k_pack(const int* __restrict__ ea) {
    int idx = blockIdx.x * blockDim.x + threadIdx.x;   // word index over EE*8
    if (idx < EE * 8) {
        const int4* p4 = reinterpret_cast<const int4*>(ea + (size_t)idx * 16);
        unsigned w = 0;
        int4 a = p4[0], b = p4[1], c = p4[2], d = p4[3];
        w |= ((unsigned)a.x & 3u) << 0;  w |= ((unsigned)a.y & 3u) << 2;
        w |= ((unsigned)a.z & 3u) << 4;  w |= ((unsigned)a.w & 3u) << 6;
        w |= ((unsigned)b.x & 3u) << 8;  w |= ((unsigned)b.y & 3u) << 10;
        w |= ((unsigned)b.z & 3u) << 12; w |= ((unsigned)b.w & 3u) << 14;
        w |= ((unsigned)c.x & 3u) << 16; w |= ((unsigned)c.y & 3u) << 18;
        w |= ((unsigned)c.z & 3u) << 20; w |= ((unsigned)c.w & 3u) << 22;
        w |= ((unsigned)d.x & 3u) << 24; w |= ((unsigned)d.y & 3u) << 26;
        w |= ((unsigned)d.z & 3u) << 28; w |= ((unsigned)d.w & 3u) << 30;
        g_pk[idx] = w;
    }
}

// scatter edges into CSR-by-col: packed (row, norm) + pk words in CSR order
__global__ void k_scatter() {
    int e = blockIdx.x * blockDim.x + threadIdx.x;
    if (e < EE) {
        int r = g_row[e];
        int c = g_col[e];
        int pos = atomicAdd(&g_cursor[c], 1);
        int idx = g_start[c] + pos;
        int2 rn;
        rn.x = r;
        rn.y = __float_as_int(g_dinv[r] * g_dinv[c]);
        g_csr_rn[idx] = rn;
        const uint4* src = reinterpret_cast<const uint4*>(&g_pk[(size_t)e * 8]);
        uint4* dst = reinterpret_cast<uint4*>(&g_pk_csr[(size_t)idx * 8]);
        dst[0] = src[0];
        dst[1] = src[1];
    }
}

// ---------------- GEMM layer 0 (fp32 A, split in-kernel): g_hl = A@W^T + bias ----------
__global__ __launch_bounds__(256, 3) void k_gemm(const float* __restrict__ A,
                                                 const unsigned* __restrict__ Whi,
                                                 const unsigned* __restrict__ Wlo,
                                                 const float* __restrict__ bias,
                                                 int n) {
    extern __shared__ __align__(16) unsigned smem_dyn[];
    unsigned* sAhi = smem_dyn;                 // [128][36] (32 kp used)
    unsigned* sAlo = sAhi + 128 * 36;
    unsigned* sWhi = sAlo + 128 * 36;          // [64][36]
    unsigned* sWlo = sWhi + 64 * 36;

    const int tid = threadIdx.x;
    const int lane = tid & 31;
    const int warp = tid >> 5;
    const int group = lane >> 2;
    const int tg = lane & 3;
    const int m0 = (warp & 3) * 32;
    const int n0 = (warp >> 2) * 32;
    const int row0 = (blockIdx.x >> 1) * 128;
    const int col0 = (blockIdx.x & 1) * 64;

    const unsigned aHiB = (unsigned)__cvta_generic_to_shared(sAhi)
                        + (((m0 + (lane & 15)) * 36 + (lane >> 4) * 4) << 2);
    const unsigned aLoB = aHiB + 128 * 36 * 4;
    const unsigned bHiB = (unsigned)__cvta_generic_to_shared(sWhi)
                        + (((n0 + (lane & 7)) * 36 + ((lane >> 3) & 1) * 4) << 2);
    const unsigned bLoB = bHiB + 64 * 36 * 4;

    float acc[2][4][4];
#pragma unroll
    for (int i = 0; i < 2; i++)
#pragma unroll
        for (int j = 0; j < 4; j++)
#pragma unroll
            for (int q = 0; q < 4; q++) acc[i][j][q] = 0.0f;

    for (int kb = 0; kb < 128; kb += 64) {
        const int kpb = kb >> 1;
#pragma unroll
        for (int r = 0; r < 8; r++) {
            int idx = r * 256 + tid;
            int arow = idx >> 4;
            int k4 = idx & 15;
            int grow = row0 + arow;
            float4 v = make_float4(0.f, 0.f, 0.f, 0.f);
            if (grow < n)
                v = *reinterpret_cast<const float4*>(&A[(size_t)grow * 128 + kb + k4 * 4]);
            unsigned h01 = pack_bf16x2(v.y, v.x);
            unsigned h23 = pack_bf16x2(v.w, v.z);
            float f0 = bf16lo_f32(h01), f1 = bf16hi_f32(h01);
            float f2 = bf16lo_f32(h23), f3 = bf16hi_f32(h23);
            unsigned l01 = pack_bf16x2(v.y - f1, v.x - f0);
            unsigned l23 = pack_bf16x2(v.w - f3, v.z - f2);
            *reinterpret_cast<uint2*>(&sAhi[arow * 36 + 2 * k4]) = make_uint2(h01, h23);
            *reinterpret_cast<uint2*>(&sAlo[arow * 36 + 2 * k4]) = make_uint2(l01, l23);
        }
#pragma unroll
        for (int r = 0; r < 2; r++) {
            int idx = r * 256 + tid;
            int j = idx >> 3;
            int q = idx & 7;
            uint4 vh = *reinterpret_cast<const uint4*>(&Whi[(size_t)(col0 + j) * 64 + kpb + 4 * q]);
            uint4 vl = *reinterpret_cast<const uint4*>(&Wlo[(size_t)(col0 + j) * 64 + kpb + 4 * q]);
            *reinterpret_cast<uint4*>(&sWhi[j * 36 + 4 * q]) = vh;
            *reinterpret_cast<uint4*>(&sWlo[j * 36 + 4 * q]) = vl;
        }
        __syncthreads();

#pragma unroll
        for (int ks16 = 0; ks16 < 4; ks16++) {
            const unsigned ko = ks16 * 32;
            unsigned ah[2][4], al[2][4];
            ldsm_x4(ah[0], aHiB + ko);
            ldsm_x4(ah[1], aHiB + 16 * 144 + ko);
            ldsm_x4(al[0], aLoB + ko);
            ldsm_x4(al[1], aLoB + 16 * 144 + ko);
#pragma unroll
            for (int j = 0; j < 4; j++) {
                unsigned bh[2], bl[2];
                ldsm_x2(bh, bHiB + j * 8 * 144 + ko);
                ldsm_x2(bl, bLoB + j * 8 * 144 + ko);
#pragma unroll
                for (int i = 0; i < 2; i++) {
                    mma_bf16(acc[i][j], ah[i], bh);
                    mma_bf16(acc[i][j], ah[i], bl);
                    mma_bf16(acc[i][j], al[i], bh);
                }
            }
        }
        __syncthreads();
    }

#pragma unroll
    for (int j = 0; j < 4; j++) {
        int col = col0 + n0 + 8 * j + 2 * tg;
        float b0 = bias[col];
        float b1 = bias[col + 1];
#pragma unroll
        for (int i = 0; i < 2; i++) {
            int r_lo = row0 + m0 + 16 * i + group;
            int r_hi = r_lo + 8;
            if (r_lo < n) {
                float2 v = make_float2(acc[i][j][0] + b0, acc[i][j][1] + b1);
                *reinterpret_cast<float2*>(&g_hl[(size_t)r_lo * 128 + col]) = v;
            }
            if (r_hi < n) {
                float2 v = make_float2(acc[i][j][2] + b0, acc[i][j][3] + b1);
                *reinterpret_cast<float2*>(&g_hl[(size_t)r_hi * 128 + col]) = v;
            }
        }
    }
}

// ---------------- GEMM layers 1-4 (pre-split A from g_Ahi/g_Alo) ----------------------
// Load phase is pure uint4 copies: no cvt, no split arithmetic.
__global__ __launch_bounds__(256, 3) void k_gemm_pre(const unsigned* __restrict__ Ahi,
                                                     const unsigned* __restrict__ Alo,
                                                     const unsigned* __restrict__ Whi,
                                                     const unsigned* __restrict__ Wlo,
                                                     const float* __restrict__ bias,
                                                     int n) {
    extern __shared__ __align__(16) unsigned smem_dyn[];
    unsigned* sAhi = smem_dyn;                 // [128][36] (32 kp used)
    unsigned* sAlo = sAhi + 128 * 36;
    unsigned* sWhi = sAlo + 128 * 36;          // [64][36]
    unsigned* sWlo = sWhi + 64 * 36;

    const int tid = threadIdx.x;
    const int lane = tid & 31;
    const int warp = tid >> 5;
    const int group = lane >> 2;
    const int tg = lane & 3;
    const int m0 = (warp & 3) * 32;
    const int n0 = (warp >> 2) * 32;
    const int row0 = (blockIdx.x >> 1) * 128;
    const int col0 = (blockIdx.x & 1) * 64;

    const unsigned aHiB = (unsigned)__cvta_generic_to_shared(sAhi)
                        + (((m0 + (lane & 15)) * 36 + (lane >> 4) * 4) << 2);
    const unsigned aLoB = aHiB + 128 * 36 * 4;
    const unsigned bHiB = (unsigned)__cvta_generic_to_shared(sWhi)
                        + (((n0 + (lane & 7)) * 36 + ((lane >> 3) & 1) * 4) << 2);
    const unsigned bLoB = bHiB + 64 * 36 * 4;

    float acc[2][4][4];
#pragma unroll
    for (int i = 0; i < 2; i++)
#pragma unroll
        for (int j = 0; j < 4; j++)
#pragma unroll
            for (int q = 0; q < 4; q++) acc[i][j][q] = 0.0f;

    for (int kb = 0; kb < 128; kb += 64) {
        const int kpb = kb >> 1;
        // A tiles: 128 rows x 32 kp per buffer = 1024 uint4 for both; 256 thr x 4
#pragma unroll
        for (int r = 0; r < 4; r++) {
            int idx = r * 256 + tid;
            int sel = idx & 1;              // 0: hi, 1: lo
            int arow = (idx >> 1) & 127;    // 0..127
            int q = idx >> 8;               // 0..3 -> kp = 4q... need 8 q values
            // 128 rows * 8 q * 2 sel = 2048; idx in [0,1024) covers 4 q values per r
            (void)sel; (void)arow; (void)q;
        }
        // simpler exact mapping: 2048 uint4 total, 256 thr x 8
#pragma unroll
        for (int r = 0; r < 8; r++) {
            int idx = r * 256 + tid;        // 0..2047
            int sel = idx >> 10;            // 0: hi (first 1024), 1: lo
            int rem = idx & 1023;
            int arow = rem >> 3;            // 0..127
            int q = rem & 7;                // kp = 4q
            int grow = row0 + arow;
            uint4 v = make_uint4(0u, 0u, 0u, 0u);
            const unsigned* src = sel ? Alo : Ahi;
            if (grow < n)
                v = *reinterpret_cast<const uint4*>(&src[(size_t)grow * 64 + kpb + 4 * q]);
            unsigned* dst = sel ? sAlo : sAhi;
            *reinterpret_cast<uint4*>(&dst[arow * 36 + 4 * q]) = v;
        }
#pragma unroll
        for (int r = 0; r < 2; r++) {
            int idx = r * 256 + tid;
            int j = idx >> 3;
            int q = idx & 7;
            uint4 vh = *reinterpret_cast<const uint4*>(&Whi[(size_t)(col0 + j) * 64 + kpb + 4 * q]);
            uint4 vl = *reinterpret_cast<const uint4*>(&Wlo[(size_t)(col0 + j) * 64 + kpb + 4 * q]);
            *reinterpret_cast<uint4*>(&sWhi[j * 36 + 4 * q]) = vh;
            *reinterpret_cast<uint4*>(&sWlo[j * 36 + 4 * q]) = vl;
        }
        __syncthreads();

#pragma unroll
        for (int ks16 = 0; ks16 < 4; ks16++) {
            const unsigned ko = ks16 * 32;
            unsigned ah[2][4], al[2][4];
            ldsm_x4(ah[0], aHiB + ko);
            ldsm_x4(ah[1], aHiB + 16 * 144 + ko);
            ldsm_x4(al[0], aLoB + ko);
            ldsm_x4(al[1], aLoB + 16 * 144 + ko);
#pragma unroll
            for (int j = 0; j < 4; j++) {
                unsigned bh[2], bl[2];
                ldsm_x2(bh, bHiB + j * 8 * 144 + ko);
                ldsm_x2(bl, bLoB + j * 8 * 144 + ko);
#pragma unroll
                for (int i = 0; i < 2; i++) {
                    mma_bf16(acc[i][j], ah[i], bh);
                    mma_bf16(acc[i][j], ah[i], bl);
                    mma_bf16(acc[i][j], al[i], bh);
                }
            }
        }
        __syncthreads();
    }

#pragma unroll
    for (int j = 0; j < 4; j++) {
        int col = col0 + n0 + 8 * j + 2 * tg;
        float b0 = bias[col];
        float b1 = bias[col + 1];
#pragma unroll
        for (int i = 0; i < 2; i++) {
            int r_lo = row0 + m0 + 16 * i + group;
            int r_hi = r_lo + 8;
            if (r_lo < n) {
                float2 v = make_float2(acc[i][j][0] + b0, acc[i][j][1] + b1);
                *reinterpret_cast<float2*>(&g_hl[(size_t)r_lo * 128 + col]) = v;
            }
            if (r_hi < n) {
                float2 v = make_float2(acc[i][j][2] + b0, acc[i][j][3] + b1);
                *reinterpret_cast<float2*>(&g_hl[(size_t)r_hi * 128 + col]) = v;
            }
        }
    }
}

// ---------------- fused per-node layer kernel ----------------
// final=0 (layers 0-3): relu + write pre-split bf16x2 hi/lo (feeds next GEMM).
// final=1 (layer 4): no relu, write fp32 out.
__global__ __launch_bounds__(256) void k_layer(const float* __restrict__ rootl,
                                               const float* __restrict__ gammal,
                                               const float* __restrict__ betal,
                                               const float* __restrict__ meanl,
                                               const float* __restrict__ varl,
                                               float* __restrict__ out, int final_layer) {
    const int warp = (blockIdx.x * blockDim.x + threadIdx.x) >> 5;
    const int lane = threadIdx.x & 31;
    if (warp >= NN) return;
    const int i = warp;
    const int c4 = lane * 4;

    float4 h4 = *reinterpret_cast<const float4*>(&g_hl[(size_t)i * 128 + c4]);
    float4 r4 = *reinterpret_cast<const float4*>(&rootl[c4]);
    const float rd = g_rdeg[i];
    float ax = fmaxf(h4.x + r4.x, 0.f) * rd;
    float ay = fmaxf(h4.y + r4.y, 0.f) * rd;
    float az = fmaxf(h4.z + r4.z, 0.f) * rd;
    float aw = fmaxf(h4.w + r4.w, 0.f) * rd;

    const int s = g_start[i];
    const int e_end = g_start[i + 1];
    const unsigned sh = (lane & 3) * 8;
    const int wsel = lane >> 2;

    if (s < e_end) {
        int2 rn = g_csr_rn[s];
        unsigned w = g_pk_csr[(size_t)s * 8 + wsel];
        for (int p = s; p < e_end; p++) {
            int2 rn_cur = rn;
            unsigned w_cur = w;
            if (p + 1 < e_end) {
                rn = g_csr_rn[p + 1];
                w = g_pk_csr[(size_t)(p + 1) * 8 + wsel];
            }
            float nm = __int_as_float(rn_cur.y);
            unsigned byte = (w_cur >> sh) & 0xFFu;
            float4 hv = *reinterpret_cast<const float4*>(&g_hl[(size_t)rn_cur.x * 128 + c4]);
            ax += fmaxf(hv.x + (float)(byte & 3u), 0.f) * nm;
            ay += fmaxf(hv.y + (float)((byte >> 2) & 3u), 0.f) * nm;
            az += fmaxf(hv.z + (float)((byte >> 4) & 3u), 0.f) * nm;
            aw += fmaxf(hv.w + (float)((byte >> 6) & 3u), 0.f) * nm;
        }
    }

    float4 g4 = *reinterpret_cast<const float4*>(&gammal[c4]);
    float4 b4 = *reinterpret_cast<const float4*>(&betal[c4]);
    float4 m4 = *reinterpret_cast<const float4*>(&meanl[c4]);
    float4 v4 = *reinterpret_cast<const float4*>(&varl[c4]);
    float sx = g4.x * rsqrtf(v4.x + BN_EPS);
    float sy = g4.y * rsqrtf(v4.y + BN_EPS);
    float sz = g4.z * rsqrtf(v4.z + BN_EPS);
    float sw = g4.w * rsqrtf(v4.w + BN_EPS);
    float4 o;
    o.x = ax * sx + (b4.x - m4.x * sx);
    o.y = ay * sy + (b4.y - m4.y * sy);
    o.z = az * sz + (b4.z - m4.z * sz);
    o.w = aw * sw + (b4.w - m4.w * sw);

    if (final_layer) {
        *reinterpret_cast<float4*>(&out[(size_t)i * 128 + c4]) = o;
    } else {
        // relu, then pre-split bf16x2 hi/lo for the next GEMM (kp = lane*2, lane*2+1)
        o.x = fmaxf(o.x, 0.f);
        o.y = fmaxf(o.y, 0.f);
        o.z = fmaxf(o.z, 0.f);
        o.w = fmaxf(o.w, 0.f);
        unsigned hi0 = pack_bf16x2(o.y, o.x);
        unsigned hi1 = pack_bf16x2(o.w, o.z);
        unsigned lo0 = pack_bf16x2(o.y - bf16hi_f32(hi0), o.x - bf16lo_f32(hi0));
        unsigned lo1 = pack_bf16x2(o.w - bf16hi_f32(hi1), o.z - bf16lo_f32(hi1));
        *reinterpret_cast<uint2*>(&g_Ahi[(size_t)i * 64 + lane * 2]) = make_uint2(hi0, hi1);
        *reinterpret_cast<uint2*>(&g_Alo[(size_t)i * 64 + lane * 2]) = make_uint2(lo0, lo1);
    }
}

// ---------------- launcher ----------------
extern "C" void kernel_launch(void* const* d_in, const int* in_sizes, int n_in,
                              void* d_out, int out_size) {
    (void)in_sizes; (void)n_in; (void)out_size;
    const float* x    = (const float*)d_in[0];
    const int*   ei   = (const int*)d_in[1];     // int32 (JAX default, not x64)
    const int*   ea   = (const int*)d_in[2];
    const float* W    = (const float*)d_in[3];
    const float* b    = (const float*)d_in[4];
    const float* root = (const float*)d_in[5];
    const float* gam  = (const float*)d_in[6];
    const float* bet  = (const float*)d_in[7];
    const float* mean = (const float*)d_in[8];
    const float* var  = (const float*)d_in[9];
    float* out = (float*)d_out;

    // one-time setup (outside capture on the first/correctness call)
    static cudaStream_t s2 = nullptr, s3 = nullptr;
    static cudaEvent_t ev_fork = nullptr, ev_gemm = nullptr, ev_pack = nullptr;
    static bool init_done = false;
    if (!init_done) {
        cudaFuncSetAttribute(k_gemm, cudaFuncAttributeMaxDynamicSharedMemorySize,
                             GEMM_SMEM_BYTES);
        cudaFuncSetAttribute(k_gemm_pre, cudaFuncAttributeMaxDynamicSharedMemorySize,
                             GEMM_SMEM_BYTES);
        cudaStreamCreateWithFlags(&s2, cudaStreamNonBlocking);
        cudaStreamCreateWithFlags(&s3, cudaStreamNonBlocking);
        cudaEventCreateWithFlags(&ev_fork, cudaEventDisableTiming);
        cudaEventCreateWithFlags(&ev_gemm, cudaEventDisableTiming);
        cudaEventCreateWithFlags(&ev_pack, cudaEventDisableTiming);
        init_done = true;
    }

    unsigned *whi_p = nullptr, *wlo_p = nullptr, *ahi_p = nullptr, *alo_p = nullptr;
    cudaGetSymbolAddress((void**)&whi_p, g_Whi);
    cudaGetSymbolAddress((void**)&wlo_p, g_Wlo);
    cudaGetSymbolAddress((void**)&ahi_p, g_Ahi);
    cudaGetSymbolAddress((void**)&alo_p, g_Alo);

    const int gemm_blocks = 2 * ((NN + 127) / 128);   // 128x64 tiles
    const int layer_blocks = (NN * 32 + 255) / 256;

    // fork: gemm0 (s2) and pack (s3) run concurrently with the prep chain (s0)
    k_splitW<<<(5 * 128 * 64 + 255) / 256, 256>>>(W);                     // kernel 0
    cudaEventRecord(ev_fork, 0);
    cudaStreamWaitEvent(s2, ev_fork, 0);
    cudaStreamWaitEvent(s3, ev_fork, 0);
    k_zero<<<(NN + 255) / 256, 256>>>();                                  // kernel 1 (s0)
    k_deg<<<(EE + 255) / 256, 256>>>(ei);                                 // kernel 2 (s0)
    k_gemm<<<gemm_blocks, 256, GEMM_SMEM_BYTES, s2>>>(x, whi_p, wlo_p, b, NN); // kernel 3 <- ncu
    k_pack<<<(EE * 8 + 255) / 256, 256, 0, s3>>>(ea);                     // (s3)
    cudaEventRecord(ev_gemm, s2);
    cudaEventRecord(ev_pack, s3);
    k_scanA<<<NB_SCAN, 1024>>>();                                         // (s0)
    k_scanB<<<1, 128>>>();                                                // (s0)
    k_scanC<<<NB_SCAN, 1024>>>();                                         // (s0)
    cudaStreamWaitEvent(0, ev_pack, 0);
    k_scatter<<<(EE + 255) / 256, 256>>>();                               // (s0)
    cudaStreamWaitEvent(0, ev_gemm, 0);
    k_layer<<<layer_blocks, 256>>>(root, gam, bet, mean, var, out, 0);    // layer 0 -> split

    for (int l = 1; l < 5; l++) {
        k_gemm_pre<<<gemm_blocks, 256, GEMM_SMEM_BYTES>>>(
            ahi_p, alo_p,
            whi_p + (size_t)l * 128 * 64, wlo_p + (size_t)l * 128 * 64,
            b + (size_t)l * 128, NN);
        k_layer<<<layer_blocks, 256>>>(root + (size_t)l * 128,
                                       gam + (size_t)l * 128, bet + (size_t)l * 128,
                                       mean + (size_t)l * 128, var + (size_t)l * 128,
                                       out, (l < 4) ? 0 : 1);
    }
}

// round 14
// speedup vs baseline: 3.6079x; 1.0367x over previous
#include <cuda_runtime.h>
#include <cstdint>

#define NN 100000
#define EE 600000
#define DD 128
#define BN_EPS 1e-5f
#define NB_SCAN 100          // scan blocks, 1000 elems each
// single-buffer chunk: sAhi/sAlo u32 [128][36] + sWhi/sWlo u32 [64][36]
#define CHUNK_U32 (2 * 128 * 36 + 2 * 64 * 36)          // 13824 u32 = 55296 B
#define GEMM_SMEM_BYTES (CHUNK_U32 * 4)                  // k_gemm (single buffer)
#define GEMM_PRE_SMEM_BYTES (2 * CHUNK_U32 * 4)          // k_gemm_pre (double buffer)

// ---------------- scratch (static device globals; no runtime alloc) ----------------
__device__ __align__(16) float    g_hl  [(size_t)NN * DD];   // 51.2 MB
__device__ __align__(16) unsigned g_pk  [(size_t)EE * 8];    // edge-order packed attrs
__device__ __align__(16) unsigned g_pk_csr[(size_t)EE * 8];  // CSR-order packed attrs
__device__ __align__(16) int      g_row [EE];
__device__ __align__(16) int      g_col [EE];
__device__ __align__(16) float    g_deg [NN];
__device__ __align__(16) float    g_dinv[NN];
__device__ __align__(16) float    g_rdeg[NN];
// CSR by target (col)
__device__ __align__(16) int      g_cnt   [NN];
__device__ __align__(16) int      g_cursor[NN];
__device__ __align__(16) int      g_start [NN + 1];
__device__ __align__(16) int2     g_csr_rn[EE];              // {row, norm bits}
__device__ __align__(16) int      g_bsum[NB_SCAN];
__device__ __align__(16) int      g_boff[NB_SCAN];
// pre-split W as packed bf16x2 pairs (hi/lo), all 5 layers: [5*128][64] u32
__device__ __align__(16) unsigned g_Whi[5 * 128 * 64];
__device__ __align__(16) unsigned g_Wlo[5 * 128 * 64];
// pre-split activations (layer outputs) as packed bf16x2 hi/lo: [NN][64] u32
__device__ __align__(16) unsigned g_Ahi[(size_t)NN * 64];
__device__ __align__(16) unsigned g_Alo[(size_t)NN * 64];

// ---------------- bf16 helpers ----------------
__device__ __forceinline__ unsigned pack_bf16x2(float odd, float even) {
    unsigned r;
    asm("cvt.rn.bf16x2.f32 %0, %1, %2;" : "=r"(r) : "f"(odd), "f"(even));
    return r;
}
__device__ __forceinline__ float bf16lo_f32(unsigned u) {
    return __uint_as_float(u << 16);
}
__device__ __forceinline__ float bf16hi_f32(unsigned u) {
    return __uint_as_float(u & 0xFFFF0000u);
}
__device__ __forceinline__ void mma_bf16(float* c, const unsigned* a, const unsigned* b) {
    asm volatile(
        "mma.sync.aligned.m16n8k16.row.col.f32.bf16.bf16.f32 "
        "{%0,%1,%2,%3}, {%4,%5,%6,%7}, {%8,%9}, {%0,%1,%2,%3};"
        : "+f"(c[0]), "+f"(c[1]), "+f"(c[2]), "+f"(c[3])
        : "r"(a[0]), "r"(a[1]), "r"(a[2]), "r"(a[3]), "r"(b[0]), "r"(b[1]));
}
__device__ __forceinline__ void ldsm_x4(unsigned* r, unsigned addr) {
    asm volatile("ldmatrix.sync.aligned.m8n8.x4.shared.b16 {%0,%1,%2,%3}, [%4];"
                 : "=r"(r[0]), "=r"(r[1]), "=r"(r[2]), "=r"(r[3]) : "r"(addr));
}
__device__ __forceinline__ void ldsm_x2(unsigned* r, unsigned addr) {
    asm volatile("ldmatrix.sync.aligned.m8n8.x2.shared.b16 {%0,%1}, [%2];"
                 : "=r"(r[0]), "=r"(r[1]) : "r"(addr));
}
// 16-byte async copy; src_bytes = 16 (copy) or 0 (zero-fill)
__device__ __forceinline__ void cp_async16(unsigned smem_addr, const void* gptr, int src_bytes) {
    asm volatile("cp.async.cg.shared.global [%0], [%1], 16, %2;"
                 :: "r"(smem_addr), "l"(gptr), "r"(src_bytes));
}
__device__ __forceinline__ void cp_commit() {
    asm volatile("cp.async.commit_group;");
}
template <int N>
__device__ __forceinline__ void cp_wait() {
    asm volatile("cp.async.wait_group %0;" :: "n"(N));
}

// ---------------- prep kernels ----------------
__global__ void k_zero() {
    int i = blockIdx.x * blockDim.x + threadIdx.x;
    if (i < NN) {
        g_deg[i] = 0.0f;
        g_cnt[i] = 0;
        g_cursor[i] = 0;
    }
}

// edge_index is int32 (JAX default config). Clamp defensively.
__global__ void k_deg(const int* __restrict__ ei) {
    int e = blockIdx.x * blockDim.x + threadIdx.x;
    if (e < EE) {
        int r = ei[e];
        int c = ei[EE + e];
        r = (r < 0) ? 0 : ((r >= NN) ? NN - 1 : r);
        c = (c < 0) ? 0 : ((c >= NN) ? NN - 1 : c);
        g_row[e] = r;
        g_col[e] = c;
        atomicAdd(&g_deg[r], 1.0f);        // out-degree (reference's deg)
        atomicAdd(&g_cnt[c], 1);           // in-degree for CSR
    }
}

// split all 5 layers' W into packed bf16x2 hi/lo pairs once per launch
__global__ void k_splitW(const float* __restrict__ W) {
    int idx = blockIdx.x * blockDim.x + threadIdx.x;   // over 5*128*64 pairs
    if (idx < 5 * 128 * 64) {
        int j = idx >> 6;        // global row (layer*128 + out-col)
        int kp = idx & 63;       // k-pair index
        float w0 = W[(size_t)j * 128 + 2 * kp];
        float w1 = W[(size_t)j * 128 + 2 * kp + 1];
        unsigned hi = pack_bf16x2(w1, w0);
        float r0 = w0 - bf16lo_f32(hi);
        float r1 = w1 - bf16hi_f32(hi);
        g_Whi[idx] = hi;
        g_Wlo[idx] = pack_bf16x2(r1, r0);
    }
}

// scan pass A: per-chunk block sums of g_cnt; also finish deg -> dinv/rdeg
__global__ __launch_bounds__(1024) void k_scanA() {
    __shared__ int red[1024];
    const int b = blockIdx.x, t = threadIdx.x;
    const int i = b * 1000 + t;
    int v = 0;
    if (t < 1000 && i < NN) {
        v = g_cnt[i];
        float d = g_deg[i] + 1.0f;
        g_dinv[i] = rsqrtf(d);
        g_rdeg[i] = 1.0f / d;
    }
    red[t] = v;
    __syncthreads();
    for (int s = 512; s > 0; s >>= 1) {
        if (t < s) red[t] += red[t + s];
        __syncthreads();
    }
    if (t == 0) g_bsum[b] = red[0];
}

// scan pass B: exclusive scan of the 100 block sums
__global__ void k_scanB() {
    __shared__ int s[128];
    const int t = threadIdx.x;
    int v = (t < NB_SCAN) ? g_bsum[t] : 0;
    s[t] = v;
    __syncthreads();
    for (int d = 1; d < 128; d <<= 1) {
        int add = (t >= d) ? s[t - d] : 0;
        __syncthreads();
        s[t] += add;
        __syncthreads();
    }
    if (t < NB_SCAN) g_boff[t] = s[t] - v;
    if (t == 0) g_start[NN] = EE;
}

// scan pass C: per-chunk exclusive scan + block offset -> g_start
__global__ __launch_bounds__(1024) void k_scanC() {
    __shared__ int s[2][1024];
    const int b = blockIdx.x, t = threadIdx.x;
    const int i = b * 1000 + t;
    const int v = (t < 1000 && i < NN) ? g_cnt[i] : 0;
    int cur = 0;
    s[0][t] = v;
    __syncthreads();
    for (int d = 1; d < 1024; d <<= 1) {
        int nxt = cur ^ 1;
        s[nxt][t] = s[cur][t] + ((t >= d) ? s[cur][t - d] : 0);
        __syncthreads();
        cur = nxt;
    }
    if (t < 1000 && i < NN) g_start[i] = g_boff[b] + s[cur][t] - v;
}

// pack 16 consecutive int32 attr values (each 0..3) into one uint32
__global__ void k_pack(const int* __restrict__ ea) {
    int idx = blockIdx.x * blockDim.x + threadIdx.x;   // word index over EE*8
    if (idx < EE * 8) {
        const int4* p4 = reinterpret_cast<const int4*>(ea + (size_t)idx * 16);
        unsigned w = 0;
        int4 a = p4[0], b = p4[1], c = p4[2], d = p4[3];
        w |= ((unsigned)a.x & 3u) << 0;  w |= ((unsigned)a.y & 3u) << 2;
        w |= ((unsigned)a.z & 3u) << 4;  w |= ((unsigned)a.w & 3u) << 6;
        w |= ((unsigned)b.x & 3u) << 8;  w |= ((unsigned)b.y & 3u) << 10;
        w |= ((unsigned)b.z & 3u) << 12; w |= ((unsigned)b.w & 3u) << 14;
        w |= ((unsigned)c.x & 3u) << 16; w |= ((unsigned)c.y & 3u) << 18;
        w |= ((unsigned)c.z & 3u) << 20; w |= ((unsigned)c.w & 3u) << 22;
        w |= ((unsigned)d.x & 3u) << 24; w |= ((unsigned)d.y & 3u) << 26;
        w |= ((unsigned)d.z & 3u) << 28; w |= ((unsigned)d.w & 3u) << 30;
        g_pk[idx] = w;
    }
}

// scatter edges into CSR-by-col: packed (row, norm) + pk words in CSR order
__global__ void k_scatter() {
    int e = blockIdx.x * blockDim.x + threadIdx.x;
    if (e < EE) {
        int r = g_row[e];
        int c = g_col[e];
        int pos = atomicAdd(&g_cursor[c], 1);
        int idx = g_start[c] + pos;
        int2 rn;
        rn.x = r;
        rn.y = __float_as_int(g_dinv[r] * g_dinv[c]);
        g_csr_rn[idx] = rn;
        const uint4* src = reinterpret_cast<const uint4*>(&g_pk[(size_t)e * 8]);
        uint4* dst = reinterpret_cast<uint4*>(&g_pk_csr[(size_t)idx * 8]);
        dst[0] = src[0];
        dst[1] = src[1];
    }
}

// ---------------- GEMM layer 0 (fp32 A, split in-kernel): g_hl = A@W^T + bias ----------
// single-buffered (overlapped with prep chain on another stream; not critical).
__global__ __launch_bounds__(256, 3) void k_gemm(const float* __restrict__ A,
                                                 const unsigned* __restrict__ Whi,
                                                 const unsigned* __restrict__ Wlo,
                                                 const float* __restrict__ bias,
                                                 int n) {
    extern __shared__ __align__(16) unsigned smem_dyn[];
    unsigned* sAhi = smem_dyn;                 // [128][36] (32 kp used)
    unsigned* sAlo = sAhi + 128 * 36;
    unsigned* sWhi = sAlo + 128 * 36;          // [64][36]
    unsigned* sWlo = sWhi + 64 * 36;

    const int tid = threadIdx.x;
    const int lane = tid & 31;
    const int warp = tid >> 5;
    const int group = lane >> 2;
    const int tg = lane & 3;
    const int m0 = (warp & 3) * 32;
    const int n0 = (warp >> 2) * 32;
    const int row0 = (blockIdx.x >> 1) * 128;
    const int col0 = (blockIdx.x & 1) * 64;

    const unsigned aHiB = (unsigned)__cvta_generic_to_shared(sAhi)
                        + (((m0 + (lane & 15)) * 36 + (lane >> 4) * 4) << 2);
    const unsigned aLoB = aHiB + 128 * 36 * 4;
    const unsigned bHiB = (unsigned)__cvta_generic_to_shared(sWhi)
                        + (((n0 + (lane & 7)) * 36 + ((lane >> 3) & 1) * 4) << 2);
    const unsigned bLoB = bHiB + 64 * 36 * 4;

    float acc[2][4][4];
#pragma unroll
    for (int i = 0; i < 2; i++)
#pragma unroll
        for (int j = 0; j < 4; j++)
#pragma unroll
            for (int q = 0; q < 4; q++) acc[i][j][q] = 0.0f;

    for (int kb = 0; kb < 128; kb += 64) {
        const int kpb = kb >> 1;
#pragma unroll
        for (int r = 0; r < 8; r++) {
            int idx = r * 256 + tid;
            int arow = idx >> 4;
            int k4 = idx & 15;
            int grow = row0 + arow;
            float4 v = make_float4(0.f, 0.f, 0.f, 0.f);
            if (grow < n)
                v = *reinterpret_cast<const float4*>(&A[(size_t)grow * 128 + kb + k4 * 4]);
            unsigned h01 = pack_bf16x2(v.y, v.x);
            unsigned h23 = pack_bf16x2(v.w, v.z);
            float f0 = bf16lo_f32(h01), f1 = bf16hi_f32(h01);
            float f2 = bf16lo_f32(h23), f3 = bf16hi_f32(h23);
            unsigned l01 = pack_bf16x2(v.y - f1, v.x - f0);
            unsigned l23 = pack_bf16x2(v.w - f3, v.z - f2);
            *reinterpret_cast<uint2*>(&sAhi[arow * 36 + 2 * k4]) = make_uint2(h01, h23);
            *reinterpret_cast<uint2*>(&sAlo[arow * 36 + 2 * k4]) = make_uint2(l01, l23);
        }
#pragma unroll
        for (int r = 0; r < 2; r++) {
            int idx = r * 256 + tid;
            int j = idx >> 3;
            int q = idx & 7;
            uint4 vh = *reinterpret_cast<const uint4*>(&Whi[(size_t)(col0 + j) * 64 + kpb + 4 * q]);
            uint4 vl = *reinterpret_cast<const uint4*>(&Wlo[(size_t)(col0 + j) * 64 + kpb + 4 * q]);
            *reinterpret_cast<uint4*>(&sWhi[j * 36 + 4 * q]) = vh;
            *reinterpret_cast<uint4*>(&sWlo[j * 36 + 4 * q]) = vl;
        }
        __syncthreads();

#pragma unroll
        for (int ks16 = 0; ks16 < 4; ks16++) {
            const unsigned ko = ks16 * 32;
            unsigned ah[2][4], al[2][4];
            ldsm_x4(ah[0], aHiB + ko);
            ldsm_x4(ah[1], aHiB + 16 * 144 + ko);
            ldsm_x4(al[0], aLoB + ko);
            ldsm_x4(al[1], aLoB + 16 * 144 + ko);
#pragma unroll
            for (int j = 0; j < 4; j++) {
                unsigned bh[2], bl[2];
                ldsm_x2(bh, bHiB + j * 8 * 144 + ko);
                ldsm_x2(bl, bLoB + j * 8 * 144 + ko);
#pragma unroll
                for (int i = 0; i < 2; i++) {
                    mma_bf16(acc[i][j], ah[i], bh);
                    mma_bf16(acc[i][j], ah[i], bl);
                    mma_bf16(acc[i][j], al[i], bh);
                }
            }
        }
        __syncthreads();
    }

#pragma unroll
    for (int j = 0; j < 4; j++) {
        int col = col0 + n0 + 8 * j + 2 * tg;
        float b0 = bias[col];
        float b1 = bias[col + 1];
#pragma unroll
        for (int i = 0; i < 2; i++) {
            int r_lo = row0 + m0 + 16 * i + group;
            int r_hi = r_lo + 8;
            if (r_lo < n) {
                float2 v = make_float2(acc[i][j][0] + b0, acc[i][j][1] + b1);
                *reinterpret_cast<float2*>(&g_hl[(size_t)r_lo * 128 + col]) = v;
            }
            if (r_hi < n) {
                float2 v = make_float2(acc[i][j][2] + b0, acc[i][j][3] + b1);
                *reinterpret_cast<float2*>(&g_hl[(size_t)r_hi * 128 + col]) = v;
            }
        }
    }
}

// ---------------- GEMM layers 1-4: pre-split A, cp.async double-buffered ---------------
// Both K-chunks issued up front via cp.async; chunk-1 fill overlaps chunk-0 mma.
__global__ __launch_bounds__(256, 2) void k_gemm_pre(const unsigned* __restrict__ Ahi,
                                                     const unsigned* __restrict__ Alo,
                                                     const unsigned* __restrict__ Whi,
                                                     const unsigned* __restrict__ Wlo,
                                                     const float* __restrict__ bias,
                                                     int n) {
    extern __shared__ __align__(16) unsigned smem_dyn[];

    const int tid = threadIdx.x;
    const int lane = tid & 31;
    const int warp = tid >> 5;
    const int group = lane >> 2;
    const int tg = lane & 3;
    const int m0 = (warp & 3) * 32;
    const int n0 = (warp >> 2) * 32;
    const int row0 = (blockIdx.x >> 1) * 128;
    const int col0 = (blockIdx.x & 1) * 64;

    const unsigned smem_u = (unsigned)__cvta_generic_to_shared(smem_dyn);
    const unsigned CHUNK_B = CHUNK_U32 * 4;

    // ldmatrix per-lane base addresses (buffer 0); buffer 1 = +CHUNK_B
    const unsigned aHiB = smem_u + (((m0 + (lane & 15)) * 36 + (lane >> 4) * 4) << 2);
    const unsigned aLoB = aHiB + 128 * 36 * 4;
    const unsigned bHiB = smem_u + ((2 * 128 * 36) << 2)
                        + (((n0 + (lane & 7)) * 36 + ((lane >> 3) & 1) * 4) << 2);
    const unsigned bLoB = bHiB + 64 * 36 * 4;

    // issue cp.async for one K-chunk into buffer `b`
    auto load_chunk = [&](int kpb, int b) {
        const unsigned base = smem_u + b * CHUNK_B;
#pragma unroll
        for (int r = 0; r < 8; r++) {
            int idx = r * 256 + tid;        // 0..2047
            int sel = idx >> 10;            // 0: hi, 1: lo
            int rem = idx & 1023;
            int arow = rem >> 3;            // 0..127
            int q = rem & 7;                // kp = 4q
            int grow = row0 + arow;
            const unsigned* src = sel ? Alo : Ahi;
            unsigned dst = base + ((sel * 128 * 36 + arow * 36 + 4 * q) << 2);
            cp_async16(dst, &src[(size_t)grow * 64 + kpb + 4 * q], (grow < n) ? 16 : 0);
        }
#pragma unroll
        for (int r = 0; r < 2; r++) {
            int idx = r * 256 + tid;
            int j = idx >> 3;               // 0..63
            int q = idx & 7;
            unsigned dh = base + ((2 * 128 * 36 + j * 36 + 4 * q) << 2);
            unsigned dl = dh + ((64 * 36) << 2);
            cp_async16(dh, &Whi[(size_t)(col0 + j) * 64 + kpb + 4 * q], 16);
            cp_async16(dl, &Wlo[(size_t)(col0 + j) * 64 + kpb + 4 * q], 16);
        }
        cp_commit();
    };

    float acc[2][4][4];
#pragma unroll
    for (int i = 0; i < 2; i++)
#pragma unroll
        for (int j = 0; j < 4; j++)
#pragma unroll
            for (int q = 0; q < 4; q++) acc[i][j][q] = 0.0f;

    load_chunk(0, 0);    // chunk 0 -> buf 0
    load_chunk(32, 1);   // chunk 1 -> buf 1 (kpb = 64>>1)

    // compute on each buffer as it lands
#pragma unroll
    for (int b = 0; b < 2; b++) {
        if (b == 0) cp_wait<1>(); else cp_wait<0>();
        __syncthreads();
        const unsigned off = b * CHUNK_B;
#pragma unroll
        for (int ks16 = 0; ks16 < 4; ks16++) {
            const unsigned ko = off + ks16 * 32;
            unsigned ah[2][4], al[2][4];
            ldsm_x4(ah[0], aHiB + ko);
            ldsm_x4(ah[1], aHiB + 16 * 144 + ko);
            ldsm_x4(al[0], aLoB + ko);
            ldsm_x4(al[1], aLoB + 16 * 144 + ko);
#pragma unroll
            for (int j = 0; j < 4; j++) {
                unsigned bh[2], bl[2];
                ldsm_x2(bh, bHiB + j * 8 * 144 + ko);
                ldsm_x2(bl, bLoB + j * 8 * 144 + ko);
#pragma unroll
                for (int i = 0; i < 2; i++) {
                    mma_bf16(acc[i][j], ah[i], bh);
                    mma_bf16(acc[i][j], ah[i], bl);
                    mma_bf16(acc[i][j], al[i], bh);
                }
            }
        }
    }

#pragma unroll
    for (int j = 0; j < 4; j++) {
        int col = col0 + n0 + 8 * j + 2 * tg;
        float b0 = bias[col];
        float b1 = bias[col + 1];
#pragma unroll
        for (int i = 0; i < 2; i++) {
            int r_lo = row0 + m0 + 16 * i + group;
            int r_hi = r_lo + 8;
            if (r_lo < n) {
                float2 v = make_float2(acc[i][j][0] + b0, acc[i][j][1] + b1);
                *reinterpret_cast<float2*>(&g_hl[(size_t)r_lo * 128 + col]) = v;
            }
            if (r_hi < n) {
                float2 v = make_float2(acc[i][j][2] + b0, acc[i][j][3] + b1);
                *reinterpret_cast<float2*>(&g_hl[(size_t)r_hi * 128 + col]) = v;
            }
        }
    }
}

// ---------------- fused per-node layer kernel ----------------
// final=0 (layers 0-3): relu + write pre-split bf16x2 hi/lo (feeds next GEMM).
// final=1 (layer 4): no relu, write fp32 out.
__global__ __launch_bounds__(256) void k_layer(const float* __restrict__ rootl,
                                               const float* __restrict__ gammal,
                                               const float* __restrict__ betal,
                                               const float* __restrict__ meanl,
                                               const float* __restrict__ varl,
                                               float* __restrict__ out, int final_layer) {
    const int warp = (blockIdx.x * blockDim.x + threadIdx.x) >> 5;
    const int lane = threadIdx.x & 31;
    if (warp >= NN) return;
    const int i = warp;
    const int c4 = lane * 4;

    float4 h4 = *reinterpret_cast<const float4*>(&g_hl[(size_t)i * 128 + c4]);
    float4 r4 = *reinterpret_cast<const float4*>(&rootl[c4]);
    const float rd = g_rdeg[i];
    float ax = fmaxf(h4.x + r4.x, 0.f) * rd;
    float ay = fmaxf(h4.y + r4.y, 0.f) * rd;
    float az = fmaxf(h4.z + r4.z, 0.f) * rd;
    float aw = fmaxf(h4.w + r4.w, 0.f) * rd;

    const int s = g_start[i];
    const int e_end = g_start[i + 1];
    const unsigned sh = (lane & 3) * 8;
    const int wsel = lane >> 2;

    if (s < e_end) {
        int2 rn = g_csr_rn[s];
        unsigned w = g_pk_csr[(size_t)s * 8 + wsel];
        for (int p = s; p < e_end; p++) {
            int2 rn_cur = rn;
            unsigned w_cur = w;
            if (p + 1 < e_end) {
                rn = g_csr_rn[p + 1];
                w = g_pk_csr[(size_t)(p + 1) * 8 + wsel];
            }
            float nm = __int_as_float(rn_cur.y);
            unsigned byte = (w_cur >> sh) & 0xFFu;
            float4 hv = *reinterpret_cast<const float4*>(&g_hl[(size_t)rn_cur.x * 128 + c4]);
            ax += fmaxf(hv.x + (float)(byte & 3u), 0.f) * nm;
            ay += fmaxf(hv.y + (float)((byte >> 2) & 3u), 0.f) * nm;
            az += fmaxf(hv.z + (float)((byte >> 4) & 3u), 0.f) * nm;
            aw += fmaxf(hv.w + (float)((byte >> 6) & 3u), 0.f) * nm;
        }
    }

    float4 g4 = *reinterpret_cast<const float4*>(&gammal[c4]);
    float4 b4 = *reinterpret_cast<const float4*>(&betal[c4]);
    float4 m4 = *reinterpret_cast<const float4*>(&meanl[c4]);
    float4 v4 = *reinterpret_cast<const float4*>(&varl[c4]);
    float sx = g4.x * rsqrtf(v4.x + BN_EPS);
    float sy = g4.y * rsqrtf(v4.y + BN_EPS);
    float sz = g4.z * rsqrtf(v4.z + BN_EPS);
    float sw = g4.w * rsqrtf(v4.w + BN_EPS);
    float4 o;
    o.x = ax * sx + (b4.x - m4.x * sx);
    o.y = ay * sy + (b4.y - m4.y * sy);
    o.z = az * sz + (b4.z - m4.z * sz);
    o.w = aw * sw + (b4.w - m4.w * sw);

    if (final_layer) {
        *reinterpret_cast<float4*>(&out[(size_t)i * 128 + c4]) = o;
    } else {
        o.x = fmaxf(o.x, 0.f);
        o.y = fmaxf(o.y, 0.f);
        o.z = fmaxf(o.z, 0.f);
        o.w = fmaxf(o.w, 0.f);
        unsigned hi0 = pack_bf16x2(o.y, o.x);
        unsigned hi1 = pack_bf16x2(o.w, o.z);
        unsigned lo0 = pack_bf16x2(o.y - bf16hi_f32(hi0), o.x - bf16lo_f32(hi0));
        unsigned lo1 = pack_bf16x2(o.w - bf16hi_f32(hi1), o.z - bf16lo_f32(hi1));
        *reinterpret_cast<uint2*>(&g_Ahi[(size_t)i * 64 + lane * 2]) = make_uint2(hi0, hi1);
        *reinterpret_cast<uint2*>(&g_Alo[(size_t)i * 64 + lane * 2]) = make_uint2(lo0, lo1);
    }
}

// ---------------- launcher ----------------
extern "C" void kernel_launch(void* const* d_in, const int* in_sizes, int n_in,
                              void* d_out, int out_size) {
    (void)in_sizes; (void)n_in; (void)out_size;
    const float* x    = (const float*)d_in[0];
    const int*   ei   = (const int*)d_in[1];     // int32 (JAX default, not x64)
    const int*   ea   = (const int*)d_in[2];
    const float* W    = (const float*)d_in[3];
    const float* b    = (const float*)d_in[4];
    const float* root = (const float*)d_in[5];
    const float* gam  = (const float*)d_in[6];
    const float* bet  = (const float*)d_in[7];
    const float* mean = (const float*)d_in[8];
    const float* var  = (const float*)d_in[9];
    float* out = (float*)d_out;

    // one-time setup (outside capture on the first/correctness call)
    static cudaStream_t s2 = nullptr, s3 = nullptr;
    static cudaEvent_t ev_fork = nullptr, ev_gemm = nullptr, ev_pack = nullptr;
    static bool init_done = false;
    if (!init_done) {
        cudaFuncSetAttribute(k_gemm, cudaFuncAttributeMaxDynamicSharedMemorySize,
                             GEMM_SMEM_BYTES);
        cudaFuncSetAttribute(k_gemm_pre, cudaFuncAttributeMaxDynamicSharedMemorySize,
                             GEMM_PRE_SMEM_BYTES);
        cudaStreamCreateWithFlags(&s2, cudaStreamNonBlocking);
        cudaStreamCreateWithFlags(&s3, cudaStreamNonBlocking);
        cudaEventCreateWithFlags(&ev_fork, cudaEventDisableTiming);
        cudaEventCreateWithFlags(&ev_gemm, cudaEventDisableTiming);
        cudaEventCreateWithFlags(&ev_pack, cudaEventDisableTiming);
        init_done = true;
    }

    unsigned *whi_p = nullptr, *wlo_p = nullptr, *ahi_p = nullptr, *alo_p = nullptr;
    cudaGetSymbolAddress((void**)&whi_p, g_Whi);
    cudaGetSymbolAddress((void**)&wlo_p, g_Wlo);
    cudaGetSymbolAddress((void**)&ahi_p, g_Ahi);
    cudaGetSymbolAddress((void**)&alo_p, g_Alo);

    const int gemm_blocks = 2 * ((NN + 127) / 128);   // 128x64 tiles
    const int layer_blocks = (NN * 32 + 255) / 256;

    // fork: gemm0 (s2) and pack (s3) run concurrently with the prep chain (s0)
    k_splitW<<<(5 * 128 * 64 + 255) / 256, 256>>>(W);                     // kernel 0
    cudaEventRecord(ev_fork, 0);
    cudaStreamWaitEvent(s2, ev_fork, 0);
    cudaStreamWaitEvent(s3, ev_fork, 0);
    k_zero<<<(NN + 255) / 256, 256>>>();                                  // kernel 1 (s0)
    k_deg<<<(EE + 255) / 256, 256>>>(ei);                                 // kernel 2 (s0)
    k_gemm<<<gemm_blocks, 256, GEMM_SMEM_BYTES, s2>>>(x, whi_p, wlo_p, b, NN); // kernel 3 <- ncu
    k_pack<<<(EE * 8 + 255) / 256, 256, 0, s3>>>(ea);                     // (s3)
    cudaEventRecord(ev_gemm, s2);
    cudaEventRecord(ev_pack, s3);
    k_scanA<<<NB_SCAN, 1024>>>();                                         // (s0)
    k_scanB<<<1, 128>>>();                                                // (s0)
    k_scanC<<<NB_SCAN, 1024>>>();                                         // (s0)
    cudaStreamWaitEvent(0, ev_pack, 0);
    k_scatter<<<(EE + 255) / 256, 256>>>();                               // (s0)
    cudaStreamWaitEvent(0, ev_gemm, 0);
    k_layer<<<layer_blocks, 256>>>(root, gam, bet, mean, var, out, 0);    // layer 0 -> split

    for (int l = 1; l < 5; l++) {
        k_gemm_pre<<<gemm_blocks, 256, GEMM_PRE_SMEM_BYTES>>>(
            ahi_p, alo_p,
            whi_p + (size_t)l * 128 * 64, wlo_p + (size_t)l * 128 * 64,
            b + (size_t)l * 128, NN);
        k_layer<<<layer_blocks, 256>>>(root + (size_t)l * 128,
                                       gam + (size_t)l * 128, bet + (size_t)l * 128,
                                       mean + (size_t)l * 128, var + (size_t)l * 128,
                                       out, (l < 4) ? 0 : 1);
    }
}